// round 4
// baseline (speedup 1.0000x reference)
#include <cuda_runtime.h>
#include <cuda_bf16.h>
#include <math.h>
#include <stdint.h>

#define B_    4
#define N_    8192
#define C_    512
#define K3    1536
#define H_    8
#define D_    64
#define M_    64           // window
#define NW    (N_ / M_)    // 128
#define ROWS  (B_ * N_)    // 32768
#define NEG_INF_F (-1000000000.0f)

// ---------------- scratch (static device globals: allocation-free) ------------
__device__ __align__(16) __nv_bfloat16 g_x3[(size_t)ROWS * K3];     // 96 MB [hi|lo|hi]
__device__ __align__(16) __nv_bfloat16 g_attn3[(size_t)ROWS * K3];  // 96 MB [hi|lo|hi]
__device__ __align__(16) __nv_bfloat16 g_Wq3[C_ * K3];              // [hi|hi|lo]
__device__ __align__(16) __nv_bfloat16 g_Wkv3[C_ * K3];
__device__ __align__(16) __nv_bfloat16 g_Wp3[C_ * K3];
__device__ float g_Q[(size_t)ROWS * C_];
__device__ float g_KV[(size_t)ROWS * C_];
__device__ float g_ctx[16 * 64 * 64];
__device__ float g_csum[16 * 64];

// ---------------- helpers -----------------------------------------------------
__device__ __forceinline__ uint32_t smem_u32(const void* p) {
    uint32_t a;
    asm("{ .reg .u64 t; cvta.to.shared.u64 t, %1; cvt.u32.u64 %0, t; }"
        : "=r"(a) : "l"(p));
    return a;
}
#define CP_ASYNC16(dst, src) \
    asm volatile("cp.async.cg.shared.global [%0], [%1], 16;" \
                 :: "r"(dst), "l"(src))
#define CP_COMMIT() asm volatile("cp.async.commit_group;" ::: "memory")
#define CP_WAIT2()  asm volatile("cp.async.wait_group 2;" ::: "memory")

__device__ __forceinline__ void ldsm_x4(uint32_t& r0, uint32_t& r1,
                                        uint32_t& r2, uint32_t& r3, uint32_t addr) {
    asm volatile("ldmatrix.sync.aligned.m8n8.x4.shared.b16 {%0,%1,%2,%3}, [%4];"
                 : "=r"(r0), "=r"(r1), "=r"(r2), "=r"(r3) : "r"(addr));
}
__device__ __forceinline__ void mma_bf16(float* c, uint32_t a0, uint32_t a1,
                                         uint32_t a2, uint32_t a3,
                                         uint32_t b0, uint32_t b1) {
    asm volatile(
        "mma.sync.aligned.m16n8k16.row.col.f32.bf16.bf16.f32 "
        "{%0,%1,%2,%3}, {%4,%5,%6,%7}, {%8,%9}, {%0,%1,%2,%3};"
        : "+f"(c[0]), "+f"(c[1]), "+f"(c[2]), "+f"(c[3])
        : "r"(a0), "r"(a1), "r"(a2), "r"(a3), "r"(b0), "r"(b1));
}

// ---------------- hi/lo split conversion --------------------------------------
// mode 0 (A side): [hi | lo | hi]   mode 1 (B side): [hi | hi | lo]
__global__ __launch_bounds__(256) void split_kernel(
    const float* __restrict__ src, __nv_bfloat16* __restrict__ dst,
    int nrows, int mode)
{
    int total = nrows * (C_ / 4);
    for (int i = blockIdx.x * blockDim.x + threadIdx.x; i < total;
         i += gridDim.x * blockDim.x) {
        int r = i >> 7;             // C_/4 = 128
        int c = (i & 127) * 4;
        float4 v = *(const float4*)(src + (size_t)r * C_ + c);
        __nv_bfloat16 h0 = __float2bfloat16(v.x), h1 = __float2bfloat16(v.y);
        __nv_bfloat16 h2 = __float2bfloat16(v.z), h3 = __float2bfloat16(v.w);
        __nv_bfloat162 lo01 = __floats2bfloat162_rn(v.x - __bfloat162float(h0),
                                                    v.y - __bfloat162float(h1));
        __nv_bfloat162 lo23 = __floats2bfloat162_rn(v.z - __bfloat162float(h2),
                                                    v.w - __bfloat162float(h3));
        __nv_bfloat162 hi01; hi01.x = h0; hi01.y = h1;
        __nv_bfloat162 hi23; hi23.x = h2; hi23.y = h3;
        __nv_bfloat16* base = dst + (size_t)r * K3 + c;
        *(__nv_bfloat162*)(base + 0) = hi01;
        *(__nv_bfloat162*)(base + 2) = hi23;
        if (mode == 0) {
            *(__nv_bfloat162*)(base + 512) = lo01;
            *(__nv_bfloat162*)(base + 514) = lo23;
            *(__nv_bfloat162*)(base + 1024) = hi01;
            *(__nv_bfloat162*)(base + 1026) = hi23;
        } else {
            *(__nv_bfloat162*)(base + 512) = hi01;
            *(__nv_bfloat162*)(base + 514) = hi23;
            *(__nv_bfloat162*)(base + 1024) = lo01;
            *(__nv_bfloat162*)(base + 1026) = lo23;
        }
    }
}

// ---------------- bf16 mma.sync GEMM: C[m,n] = sum_k A3[m,k] B3[n,k] ----------
// 128x256 tile, BK=32, 512 threads (16 warps, 4m x 4n, warp tile 32x64).
// 4-stage cp.async ring, one __syncthreads per k-iteration.
#define GST     4
#define GA_ST   (128 * 40)            // halfs per A stage
#define GB_ST   (256 * 40)            // halfs per B stage
#define GB_BASE (GST * GA_ST)
#define GEMM_SMEM ((GB_BASE + GST * GB_ST) * 2)   // 122880 bytes
#define KITERS  (K3 / 32)             // 48

__global__ __launch_bounds__(512, 1) void gemm_mma(
    const __nv_bfloat16* __restrict__ A3, const __nv_bfloat16* __restrict__ B3,
    float* __restrict__ Cout, const float* __restrict__ bias)
{
    extern __shared__ __nv_bfloat16 smg[];
    const int tid = threadIdx.x;
    const int warp = tid >> 5, lane = tid & 31;
    const int wm = warp & 3, wn = warp >> 2;
    const int m0 = blockIdx.y * 128;
    const int n0 = blockIdx.x * 256;

    float acc[2][8][4];
#pragma unroll
    for (int i = 0; i < 2; i++)
#pragma unroll
        for (int j = 0; j < 8; j++)
#pragma unroll
            for (int e = 0; e < 4; e++) acc[i][j][e] = 0.f;

    const __nv_bfloat16* Ab = A3 + (size_t)m0 * K3;
    const __nv_bfloat16* Bb = B3 + (size_t)n0 * K3;

    // loaders: A = 512 16B-chunks (1/thread), B = 1024 chunks (2/thread)
    const int lrow = tid >> 2;          // 0..127
    const int lchk = (tid & 3) * 8;     // half offset within row

#define LOADT(s, j) do { \
    const int ko = (j) * 32; \
    CP_ASYNC16(smem_u32(smg + (s) * GA_ST + lrow * 40 + lchk), \
               Ab + (size_t)lrow * K3 + ko + lchk); \
    CP_ASYNC16(smem_u32(smg + GB_BASE + (size_t)(s) * GB_ST + lrow * 40 + lchk), \
               Bb + (size_t)lrow * K3 + ko + lchk); \
    CP_ASYNC16(smem_u32(smg + GB_BASE + (size_t)(s) * GB_ST + (lrow + 128) * 40 + lchk), \
               Bb + (size_t)(lrow + 128) * K3 + ko + lchk); \
} while (0)

    LOADT(0, 0); CP_COMMIT();
    LOADT(1, 1); CP_COMMIT();
    LOADT(2, 2); CP_COMMIT();

    // ldmatrix lane addressing
    const int a_row = wm * 32 + (lane & 15);
    const int a_col = (lane >> 4) << 3;
    const int b_row = wn * 64 + ((lane >> 4) << 3) + (lane & 7);
    const int b_col = ((lane >> 3) & 1) << 3;

    for (int j = 0; j < KITERS; ++j) {
        const int s = j & 3;
        CP_WAIT2();
        __syncthreads();
        if (j + 3 < KITERS) LOADT((j + 3) & 3, j + 3);
        CP_COMMIT();

        const __nv_bfloat16* As = smg + s * GA_ST;
        const __nv_bfloat16* Bs = smg + GB_BASE + (size_t)s * GB_ST;
#pragma unroll
        for (int kk = 0; kk < 2; kk++) {
            const int k16 = kk * 16;
            uint32_t a[2][4];
#pragma unroll
            for (int i = 0; i < 2; i++)
                ldsm_x4(a[i][0], a[i][1], a[i][2], a[i][3],
                        smem_u32(As + (a_row + i * 16) * 40 + k16 + a_col));
            uint32_t b[4][4];
#pragma unroll
            for (int jb = 0; jb < 4; jb++)
                ldsm_x4(b[jb][0], b[jb][1], b[jb][2], b[jb][3],
                        smem_u32(Bs + (b_row + jb * 16) * 40 + k16 + b_col));
#pragma unroll
            for (int i = 0; i < 2; i++)
#pragma unroll
                for (int jn = 0; jn < 8; jn++) {
                    const int jb = jn >> 1, hf = (jn & 1) * 2;
                    mma_bf16(acc[i][jn], a[i][0], a[i][1], a[i][2], a[i][3],
                             b[jb][hf], b[jb][hf + 1]);
                }
        }
    }

    // epilogue
#pragma unroll
    for (int i = 0; i < 2; i++) {
        const int r0 = m0 + wm * 32 + i * 16 + (lane >> 2);
#pragma unroll
        for (int jn = 0; jn < 8; jn++) {
            const int c0 = n0 + wn * 64 + jn * 8 + (lane & 3) * 2;
            float b0 = bias ? bias[c0] : 0.f;
            float b1 = bias ? bias[c0 + 1] : 0.f;
            float2 v0 = make_float2(acc[i][jn][0] + b0, acc[i][jn][1] + b1);
            float2 v1 = make_float2(acc[i][jn][2] + b0, acc[i][jn][3] + b1);
            *(float2*)(Cout + (size_t)r0 * C_ + c0) = v0;
            *(float2*)(Cout + (size_t)(r0 + 8) * C_ + c0) = v1;
        }
    }
}

// ---------------- local window attention (heads 0..3) -------------------------
#define QS 68
#define KS 68
#define SS 196
#define LA_SMEM ((64 * QS + 192 * KS + 64 * SS) * 4)

__global__ __launch_bounds__(256) void local_attn_kernel(float* __restrict__ attn_out)
{
    extern __shared__ float sm[];
    float* qs = sm;
    float* ks = qs + 64 * QS;
    float* sc = ks + 192 * KS;

    const int w = blockIdx.x;
    const int bh = blockIdx.y;
    const int b = bh >> 2, hh = bh & 3;
    const int t = threadIdx.x;
    const size_t rowbase = (size_t)b * N_ + (size_t)w * M_;
    const int col0 = hh * D_;

    for (int idx = t; idx < 64 * 16; idx += 256) {
        int r = idx >> 4, c4 = (idx & 15) * 4;
        float4 v = *(const float4*)(g_Q + (rowbase + r) * C_ + col0 + c4);
        float* dst = qs + r * QS + c4;
        dst[0] = v.x * 0.125f; dst[1] = v.y * 0.125f;
        dst[2] = v.z * 0.125f; dst[3] = v.w * 0.125f;
    }
    const int nbase = (w - 1) * M_;
    for (int idx = t; idx < 192 * 16; idx += 256) {
        int r = idx >> 4, c4 = (idx & 15) * 4;
        int n = nbase + r;
        float4 v = make_float4(0.f, 0.f, 0.f, 0.f);
        if (n >= 0 && n < N_)
            v = *(const float4*)(g_KV + ((size_t)b * N_ + n) * C_ + col0 + c4);
        float* dst = ks + r * KS + c4;
        dst[0] = v.x; dst[1] = v.y; dst[2] = v.z; dst[3] = v.w;
    }
    __syncthreads();

    {
        const int ti = (t & 15) * 4;
        const int tj = (t >> 4) * 12;
        float a[4][12];
#pragma unroll
        for (int i = 0; i < 4; i++)
#pragma unroll
            for (int j = 0; j < 12; j++) a[i][j] = 0.f;

        for (int k4 = 0; k4 < 64; k4 += 4) {
            float4 qv[4];
#pragma unroll
            for (int i = 0; i < 4; i++)
                qv[i] = *(const float4*)&qs[(ti + i) * QS + k4];
#pragma unroll
            for (int j = 0; j < 12; j++) {
                float4 kv = *(const float4*)&ks[(tj + j) * KS + k4];
#pragma unroll
                for (int i = 0; i < 4; i++) {
                    a[i][j] = fmaf(qv[i].x, kv.x, a[i][j]);
                    a[i][j] = fmaf(qv[i].y, kv.y, a[i][j]);
                    a[i][j] = fmaf(qv[i].z, kv.z, a[i][j]);
                    a[i][j] = fmaf(qv[i].w, kv.w, a[i][j]);
                }
            }
        }
        const bool leftInv = (w == 0), rightInv = (w == NW - 1);
#pragma unroll
        for (int i = 0; i < 4; i++)
#pragma unroll
            for (int j = 0; j < 12; j++) {
                int jj = tj + j;
                float s = a[i][j];
                if ((jj < 64 && leftInv) || (jj >= 128 && rightInv)) s = NEG_INF_F;
                sc[(ti + i) * SS + jj] = s;
            }
    }
    __syncthreads();

    {
        const int warp = t >> 5, lane = t & 31;
        for (int r = warp; r < 64; r += 8) {
            float m = -1e30f;
            for (int j = lane; j < 192; j += 32) m = fmaxf(m, sc[r * SS + j]);
#pragma unroll
            for (int o = 16; o; o >>= 1) m = fmaxf(m, __shfl_xor_sync(0xffffffffu, m, o));
            float s = 0.f;
            for (int j = lane; j < 192; j += 32) {
                float e = __expf(sc[r * SS + j] - m);
                sc[r * SS + j] = e;
                s += e;
            }
#pragma unroll
            for (int o = 16; o; o >>= 1) s += __shfl_xor_sync(0xffffffffu, s, o);
            float inv = 1.f / s;
            for (int j = lane; j < 192; j += 32) sc[r * SS + j] *= inv;
        }
    }
    __syncthreads();

    {
        const int ti = (t & 15) * 4;
        const int te = (t >> 4) * 4;
        float a[4][4];
#pragma unroll
        for (int i = 0; i < 4; i++)
#pragma unroll
            for (int e = 0; e < 4; e++) a[i][e] = 0.f;

        for (int j = 0; j < 192; j++) {
            float4 vv = *(const float4*)&ks[j * KS + te];
#pragma unroll
            for (int i = 0; i < 4; i++) {
                float pcoef = sc[(ti + i) * SS + j];
                a[i][0] = fmaf(pcoef, vv.x, a[i][0]);
                a[i][1] = fmaf(pcoef, vv.y, a[i][1]);
                a[i][2] = fmaf(pcoef, vv.z, a[i][2]);
                a[i][3] = fmaf(pcoef, vv.w, a[i][3]);
            }
        }
#pragma unroll
        for (int i = 0; i < 4; i++) {
            int n = w * M_ + ti + i;
            size_t o1 = ((size_t)(b * H_ + hh) * N_ + n) * D_ + te;
#pragma unroll
            for (int e = 0; e < 4; e++) attn_out[o1 + e] = a[i][e];

            // fused hi/lo bf16 write for projection GEMM ([hi|lo|hi])
            __nv_bfloat16 h0 = __float2bfloat16(a[i][0]);
            __nv_bfloat16 h1 = __float2bfloat16(a[i][1]);
            __nv_bfloat16 h2 = __float2bfloat16(a[i][2]);
            __nv_bfloat16 h3 = __float2bfloat16(a[i][3]);
            __nv_bfloat162 lo01 = __floats2bfloat162_rn(
                a[i][0] - __bfloat162float(h0), a[i][1] - __bfloat162float(h1));
            __nv_bfloat162 lo23 = __floats2bfloat162_rn(
                a[i][2] - __bfloat162float(h2), a[i][3] - __bfloat162float(h3));
            __nv_bfloat162 hi01; hi01.x = h0; hi01.y = h1;
            __nv_bfloat162 hi23; hi23.x = h2; hi23.y = h3;
            __nv_bfloat16* b3 = g_attn3 + ((size_t)b * N_ + n) * K3 + hh * D_ + te;
            *(__nv_bfloat162*)(b3 + 0) = hi01;
            *(__nv_bfloat162*)(b3 + 2) = hi23;
            *(__nv_bfloat162*)(b3 + 512) = lo01;
            *(__nv_bfloat162*)(b3 + 514) = lo23;
            *(__nv_bfloat162*)(b3 + 1024) = hi01;
            *(__nv_bfloat162*)(b3 + 1026) = hi23;
        }
    }
}

// ---------------- linear attention (heads 4..7) -------------------------------
__global__ void zero_ctx_kernel()
{
    const int total = 16 * 4096 + 16 * 64;
    for (int i = blockIdx.x * blockDim.x + threadIdx.x; i < total;
         i += gridDim.x * blockDim.x) {
        if (i < 16 * 4096) g_ctx[i] = 0.f;
        else g_csum[i - 16 * 4096] = 0.f;
    }
}

#define CT_SMEM (256 * 64 * 4)
__global__ __launch_bounds__(256) void ctx_kernel()
{
    extern __shared__ float tile[];
    const int bh = blockIdx.y;
    const int b = bh >> 2, hh = 4 + (bh & 3);
    const int n0 = blockIdx.x * 256;
    const int t = threadIdx.x;

    const float* src = g_KV + ((size_t)b * N_ + n0) * C_ + hh * D_;
    for (int idx = t; idx < 256 * 16; idx += 256) {
        int r = idx >> 4, c4 = (idx & 15) * 4;
        float4 v = *(const float4*)(src + (size_t)r * C_ + c4);
        float* dst = tile + r * 64 + c4;
        dst[0] = v.x; dst[1] = v.y; dst[2] = v.z; dst[3] = v.w;
    }
    __syncthreads();

    const int d = t >> 2, q = t & 3;
    float4 acc[4];
#pragma unroll
    for (int i = 0; i < 4; i++) acc[i] = make_float4(0.f, 0.f, 0.f, 0.f);
    float ssum = 0.f;

    for (int n = 0; n < 256; n++) {
        float ek = __expf(tile[n * 64 + d]);
        ssum += ek;
        const float4* vr = (const float4*)(tile + n * 64 + q * 16);
#pragma unroll
        for (int e4 = 0; e4 < 4; e4++) {
            float4 v = vr[e4];
            acc[e4].x = fmaf(ek, v.x, acc[e4].x);
            acc[e4].y = fmaf(ek, v.y, acc[e4].y);
            acc[e4].z = fmaf(ek, v.z, acc[e4].z);
            acc[e4].w = fmaf(ek, v.w, acc[e4].w);
        }
    }
    float* dst = g_ctx + bh * 4096 + d * 64 + q * 16;
#pragma unroll
    for (int e4 = 0; e4 < 4; e4++) {
        atomicAdd(dst + e4 * 4 + 0, acc[e4].x);
        atomicAdd(dst + e4 * 4 + 1, acc[e4].y);
        atomicAdd(dst + e4 * 4 + 2, acc[e4].z);
        atomicAdd(dst + e4 * 4 + 3, acc[e4].w);
    }
    if (q == 0) atomicAdd(&g_csum[bh * 64 + d], ssum);
}

__global__ __launch_bounds__(256) void lin_out_kernel(float* __restrict__ attn_out)
{
    __shared__ float ctx_s[4096];
    __shared__ float cinv_s[64];
    const int bh = blockIdx.y;
    const int b = bh >> 2, hh = 4 + (bh & 3);
    const int t = threadIdx.x;

    if (t < 64) cinv_s[t] = 1.f / g_csum[bh * 64 + t];
    for (int i = t; i < 4096; i += 256) ctx_s[i] = g_ctx[bh * 4096 + i];
    __syncthreads();

    const int warp = t >> 5, lane = t & 31;
    for (int r = warp; r < 64; r += 8) {
        const int n = blockIdx.x * 64 + r;
        const float* qrow = g_Q + ((size_t)b * N_ + n) * C_ + hh * D_;
        float q0 = qrow[lane], q1 = qrow[lane + 32];
        float m = fmaxf(q0, q1);
#pragma unroll
        for (int o = 16; o; o >>= 1) m = fmaxf(m, __shfl_xor_sync(0xffffffffu, m, o));
        float e0 = __expf(q0 - m), e1 = __expf(q1 - m);
        float s = e0 + e1;
#pragma unroll
        for (int o = 16; o; o >>= 1) s += __shfl_xor_sync(0xffffffffu, s, o);
        float inv = 0.125f / s;
        e0 *= inv * cinv_s[lane];
        e1 *= inv * cinv_s[lane + 32];

        float a0 = 0.f, a1 = 0.f;
#pragma unroll
        for (int dd = 0; dd < 64; dd++) {
            float sq = __shfl_sync(0xffffffffu, (dd < 32) ? e0 : e1, dd & 31);
            a0 = fmaf(sq, ctx_s[dd * 64 + lane], a0);
            a1 = fmaf(sq, ctx_s[dd * 64 + lane + 32], a1);
        }
        size_t o1 = ((size_t)(b * H_ + hh) * N_ + n) * D_;
        attn_out[o1 + lane] = a0;
        attn_out[o1 + lane + 32] = a1;

        // fused hi/lo bf16 write ([hi|lo|hi])
        __nv_bfloat16 a0h = __float2bfloat16(a0);
        __nv_bfloat16 a1h = __float2bfloat16(a1);
        __nv_bfloat16 a0l = __float2bfloat16(a0 - __bfloat162float(a0h));
        __nv_bfloat16 a1l = __float2bfloat16(a1 - __bfloat162float(a1h));
        __nv_bfloat16* b3 = g_attn3 + ((size_t)b * N_ + n) * K3 + hh * D_;
        b3[lane] = a0h;           b3[lane + 32] = a1h;
        b3[512 + lane] = a0l;     b3[512 + lane + 32] = a1l;
        b3[1024 + lane] = a0h;    b3[1024 + lane + 32] = a1h;
    }
}

// ---------------------------------- launch ------------------------------------
extern "C" void kernel_launch(void* const* d_in, const int* in_sizes, int n_in,
                              void* d_out, int out_size)
{
    (void)in_sizes; (void)n_in; (void)out_size;
    const float* x     = (const float*)d_in[0];
    const float* Wq    = (const float*)d_in[1];
    const float* Wkv   = (const float*)d_in[2];
    const float* Wproj = (const float*)d_in[3];
    const float* bproj = (const float*)d_in[4];

    float* y    = (float*)d_out;
    float* attn = y + (size_t)ROWS * C_;

    float *pQ, *pKV;
    __nv_bfloat16 *px3, *pa3, *pWq3, *pWkv3, *pWp3;
    cudaGetSymbolAddress((void**)&pQ, g_Q);
    cudaGetSymbolAddress((void**)&pKV, g_KV);
    cudaGetSymbolAddress((void**)&px3, g_x3);
    cudaGetSymbolAddress((void**)&pa3, g_attn3);
    cudaGetSymbolAddress((void**)&pWq3, g_Wq3);
    cudaGetSymbolAddress((void**)&pWkv3, g_Wkv3);
    cudaGetSymbolAddress((void**)&pWp3, g_Wp3);

    cudaFuncSetAttribute(gemm_mma,
                         cudaFuncAttributeMaxDynamicSharedMemorySize, GEMM_SMEM);
    cudaFuncSetAttribute(local_attn_kernel,
                         cudaFuncAttributeMaxDynamicSharedMemorySize, LA_SMEM);
    cudaFuncSetAttribute(ctx_kernel,
                         cudaFuncAttributeMaxDynamicSharedMemorySize, CT_SMEM);

    // conversions
    split_kernel<<<4096, 256>>>(x, px3, ROWS, 0);
    split_kernel<<<128, 256>>>(Wq, pWq3, C_, 1);
    split_kernel<<<128, 256>>>(Wkv, pWkv3, C_, 1);
    split_kernel<<<128, 256>>>(Wproj, pWp3, C_, 1);

    dim3 ggemm(C_ / 256, ROWS / 128);   // (2, 256)
    gemm_mma<<<ggemm, 512, GEMM_SMEM>>>(px3, pWq3, pQ, nullptr);
    gemm_mma<<<ggemm, 512, GEMM_SMEM>>>(px3, pWkv3, pKV, nullptr);

    local_attn_kernel<<<dim3(NW, 16), 256, LA_SMEM>>>(attn);

    zero_ctx_kernel<<<64, 256>>>();
    ctx_kernel<<<dim3(32, 16), 256, CT_SMEM>>>();
    lin_out_kernel<<<dim3(128, 16), 256>>>(attn);

    gemm_mma<<<ggemm, 512, GEMM_SMEM>>>(pa3, pWp3, y, bproj);
}

// round 5
// speedup vs baseline: 1.0951x; 1.0951x over previous
#include <cuda_runtime.h>
#include <cuda_bf16.h>
#include <cuda_fp16.h>
#include <math.h>
#include <stdint.h>

#define B_    4
#define N_    8192
#define C_    512
#define K3    1536
#define K2    1024
#define H_    8
#define D_    64
#define M_    64           // window
#define NW    (N_ / M_)    // 128
#define ROWS  (B_ * N_)    // 32768
#define NEG_INF_F (-1000000000.0f)

// ---------------- scratch (static device globals: allocation-free) ------------
__device__ __align__(16) __nv_bfloat16 g_x3[(size_t)ROWS * K3];    // 96 MB [hi|lo|hi]
__device__ __align__(16) __nv_bfloat16 g_W2[1024 * K3];            // Wq3 rows 0-511, Wkv3 rows 512-1023
__device__ __align__(16) __half       g_attnH[(size_t)ROWS * C_];  // 32 MB fp16 attn (B,N,C)
__device__ __align__(16) __half       g_Wp2[C_ * K2];              // [hi16|lo16]
__device__ float g_Q[(size_t)ROWS * C_];
__device__ float g_KV[(size_t)ROWS * C_];
__device__ float g_ctx[16 * 64 * 64];
__device__ float g_csum[16 * 64];

// ---------------- helpers -----------------------------------------------------
__device__ __forceinline__ uint32_t smem_u32(const void* p) {
    uint32_t a;
    asm("{ .reg .u64 t; cvta.to.shared.u64 t, %1; cvt.u32.u64 %0, t; }"
        : "=r"(a) : "l"(p));
    return a;
}
#define CP_ASYNC16(dst, src) \
    asm volatile("cp.async.cg.shared.global [%0], [%1], 16;" \
                 :: "r"(dst), "l"(src))
#define CP_COMMIT() asm volatile("cp.async.commit_group;" ::: "memory")
#define CP_WAIT2()  asm volatile("cp.async.wait_group 2;" ::: "memory")

__device__ __forceinline__ void ldsm_x4(uint32_t& r0, uint32_t& r1,
                                        uint32_t& r2, uint32_t& r3, uint32_t addr) {
    asm volatile("ldmatrix.sync.aligned.m8n8.x4.shared.b16 {%0,%1,%2,%3}, [%4];"
                 : "=r"(r0), "=r"(r1), "=r"(r2), "=r"(r3) : "r"(addr));
}
__device__ __forceinline__ void mma_bf16(float* c, uint32_t a0, uint32_t a1,
                                         uint32_t a2, uint32_t a3,
                                         uint32_t b0, uint32_t b1) {
    asm volatile(
        "mma.sync.aligned.m16n8k16.row.col.f32.bf16.bf16.f32 "
        "{%0,%1,%2,%3}, {%4,%5,%6,%7}, {%8,%9}, {%0,%1,%2,%3};"
        : "+f"(c[0]), "+f"(c[1]), "+f"(c[2]), "+f"(c[3])
        : "r"(a0), "r"(a1), "r"(a2), "r"(a3), "r"(b0), "r"(b1));
}
__device__ __forceinline__ void mma_f16(float* c, uint32_t a0, uint32_t a1,
                                        uint32_t a2, uint32_t a3,
                                        uint32_t b0, uint32_t b1) {
    asm volatile(
        "mma.sync.aligned.m16n8k16.row.col.f32.f16.f16.f32 "
        "{%0,%1,%2,%3}, {%4,%5,%6,%7}, {%8,%9}, {%0,%1,%2,%3};"
        : "+f"(c[0]), "+f"(c[1]), "+f"(c[2]), "+f"(c[3])
        : "r"(a0), "r"(a1), "r"(a2), "r"(a3), "r"(b0), "r"(b1));
}

// ---------------- bf16 hi/lo split conversion ---------------------------------
// mode 0 (A side): [hi | lo | hi]   mode 1 (B side): [hi | hi | lo]
__global__ __launch_bounds__(256) void split_kernel(
    const float* __restrict__ src, __nv_bfloat16* __restrict__ dst,
    int nrows, int mode)
{
    int total = nrows * (C_ / 4);
    for (int i = blockIdx.x * blockDim.x + threadIdx.x; i < total;
         i += gridDim.x * blockDim.x) {
        int r = i >> 7;             // C_/4 = 128
        int c = (i & 127) * 4;
        float4 v = *(const float4*)(src + (size_t)r * C_ + c);
        __nv_bfloat16 h0 = __float2bfloat16(v.x), h1 = __float2bfloat16(v.y);
        __nv_bfloat16 h2 = __float2bfloat16(v.z), h3 = __float2bfloat16(v.w);
        __nv_bfloat162 lo01 = __floats2bfloat162_rn(v.x - __bfloat162float(h0),
                                                    v.y - __bfloat162float(h1));
        __nv_bfloat162 lo23 = __floats2bfloat162_rn(v.z - __bfloat162float(h2),
                                                    v.w - __bfloat162float(h3));
        __nv_bfloat162 hi01; hi01.x = h0; hi01.y = h1;
        __nv_bfloat162 hi23; hi23.x = h2; hi23.y = h3;
        __nv_bfloat16* base = dst + (size_t)r * K3 + c;
        *(__nv_bfloat162*)(base + 0) = hi01;
        *(__nv_bfloat162*)(base + 2) = hi23;
        if (mode == 0) {
            *(__nv_bfloat162*)(base + 512) = lo01;
            *(__nv_bfloat162*)(base + 514) = lo23;
            *(__nv_bfloat162*)(base + 1024) = hi01;
            *(__nv_bfloat162*)(base + 1026) = hi23;
        } else {
            *(__nv_bfloat162*)(base + 512) = hi01;
            *(__nv_bfloat162*)(base + 514) = hi23;
            *(__nv_bfloat162*)(base + 1024) = lo01;
            *(__nv_bfloat162*)(base + 1026) = lo23;
        }
    }
}

// fp16 exact hi/lo split of weights: dst[r][0..511]=hi16, dst[r][512..1023]=lo16
__global__ __launch_bounds__(256) void split_h2_kernel(
    const float* __restrict__ src, __half* __restrict__ dst)
{
    int total = C_ * (C_ / 4);
    for (int i = blockIdx.x * blockDim.x + threadIdx.x; i < total;
         i += gridDim.x * blockDim.x) {
        int r = i >> 7;
        int c = (i & 127) * 4;
        float4 v = *(const float4*)(src + (size_t)r * C_ + c);
        __half h0 = __float2half_rn(v.x), h1 = __float2half_rn(v.y);
        __half h2 = __float2half_rn(v.z), h3 = __float2half_rn(v.w);
        __half2 hiA; hiA.x = h0; hiA.y = h1;
        __half2 hiB; hiB.x = h2; hiB.y = h3;
        __half2 loA = __floats2half2_rn(v.x - __half2float(h0),
                                        v.y - __half2float(h1));
        __half2 loB = __floats2half2_rn(v.z - __half2float(h2),
                                        v.w - __half2float(h3));
        __half* base = dst + (size_t)r * K2 + c;
        *(__half2*)(base + 0) = hiA;
        *(__half2*)(base + 2) = hiB;
        *(__half2*)(base + 512) = loA;
        *(__half2*)(base + 514) = loB;
    }
}

// ---------------- bf16 mma.sync GEMM (fused QKV): dual-output routing ---------
// 128x256 tile, BK=32, 512 threads, 4-stage cp.async ring.
#define GST     4
#define GA_ST   (128 * 40)
#define GB_ST   (256 * 40)
#define GB_BASE (GST * GA_ST)
#define GEMM_SMEM ((GB_BASE + GST * GB_ST) * 2)   // 122880 bytes
#define KITERS  (K3 / 32)             // 48

__global__ __launch_bounds__(512, 1) void gemm_mma(
    const __nv_bfloat16* __restrict__ A3, const __nv_bfloat16* __restrict__ B3,
    float* __restrict__ CoutA, float* __restrict__ CoutB)
{
    extern __shared__ __nv_bfloat16 smg[];
    const int tid = threadIdx.x;
    const int warp = tid >> 5, lane = tid & 31;
    const int wm = warp & 3, wn = warp >> 2;
    const int m0 = blockIdx.y * 128;
    const int n0 = blockIdx.x * 256;

    float acc[2][8][4];
#pragma unroll
    for (int i = 0; i < 2; i++)
#pragma unroll
        for (int j = 0; j < 8; j++)
#pragma unroll
            for (int e = 0; e < 4; e++) acc[i][j][e] = 0.f;

    const __nv_bfloat16* Ab = A3 + (size_t)m0 * K3;
    const __nv_bfloat16* Bb = B3 + (size_t)n0 * K3;

    const int lrow = tid >> 2;
    const int lchk = (tid & 3) * 8;

#define LOADT(s, j) do { \
    const int ko = (j) * 32; \
    CP_ASYNC16(smem_u32(smg + (s) * GA_ST + lrow * 40 + lchk), \
               Ab + (size_t)lrow * K3 + ko + lchk); \
    CP_ASYNC16(smem_u32(smg + GB_BASE + (size_t)(s) * GB_ST + lrow * 40 + lchk), \
               Bb + (size_t)lrow * K3 + ko + lchk); \
    CP_ASYNC16(smem_u32(smg + GB_BASE + (size_t)(s) * GB_ST + (lrow + 128) * 40 + lchk), \
               Bb + (size_t)(lrow + 128) * K3 + ko + lchk); \
} while (0)

    LOADT(0, 0); CP_COMMIT();
    LOADT(1, 1); CP_COMMIT();
    LOADT(2, 2); CP_COMMIT();

    const int a_row = wm * 32 + (lane & 15);
    const int a_col = (lane >> 4) << 3;
    const int b_row = wn * 64 + ((lane >> 4) << 3) + (lane & 7);
    const int b_col = ((lane >> 3) & 1) << 3;

    for (int j = 0; j < KITERS; ++j) {
        const int s = j & 3;
        CP_WAIT2();
        __syncthreads();
        if (j + 3 < KITERS) LOADT((j + 3) & 3, j + 3);
        CP_COMMIT();

        const __nv_bfloat16* As = smg + s * GA_ST;
        const __nv_bfloat16* Bs = smg + GB_BASE + (size_t)s * GB_ST;
#pragma unroll
        for (int kk = 0; kk < 2; kk++) {
            const int k16 = kk * 16;
            uint32_t a[2][4];
#pragma unroll
            for (int i = 0; i < 2; i++)
                ldsm_x4(a[i][0], a[i][1], a[i][2], a[i][3],
                        smem_u32(As + (a_row + i * 16) * 40 + k16 + a_col));
            uint32_t b[4][4];
#pragma unroll
            for (int jb = 0; jb < 4; jb++)
                ldsm_x4(b[jb][0], b[jb][1], b[jb][2], b[jb][3],
                        smem_u32(Bs + (b_row + jb * 16) * 40 + k16 + b_col));
#pragma unroll
            for (int i = 0; i < 2; i++)
#pragma unroll
                for (int jn = 0; jn < 8; jn++) {
                    const int jb = jn >> 1, hf = (jn & 1) * 2;
                    mma_bf16(acc[i][jn], a[i][0], a[i][1], a[i][2], a[i][3],
                             b[jb][hf], b[jb][hf + 1]);
                }
        }
    }

    // epilogue: route to CoutA (n0<512) or CoutB
    float* Cout = (n0 < 512) ? CoutA : CoutB;
    const int nc0 = (n0 < 512) ? n0 : n0 - 512;
#pragma unroll
    for (int i = 0; i < 2; i++) {
        const int r0 = m0 + wm * 32 + i * 16 + (lane >> 2);
#pragma unroll
        for (int jn = 0; jn < 8; jn++) {
            const int c0 = nc0 + wn * 64 + jn * 8 + (lane & 3) * 2;
            *(float2*)(Cout + (size_t)r0 * C_ + c0) =
                make_float2(acc[i][jn][0], acc[i][jn][1]);
            *(float2*)(Cout + (size_t)(r0 + 8) * C_ + c0) =
                make_float2(acc[i][jn][2], acc[i][jn][3]);
        }
    }
}

// ---------------- fp16 proj GEMM: y = attnH @ [Whi|Wlo]^T + bias --------------
// A has 512 cols; K'=1024 iterated as two passes over the same A columns.
#define KIT2 (K2 / 32)   // 32

__global__ __launch_bounds__(512, 1) void gemm_proj_f16(
    const __half* __restrict__ Ah, const __half* __restrict__ B2,
    float* __restrict__ Cout, const float* __restrict__ bias)
{
    extern __shared__ __half smh[];
    const int tid = threadIdx.x;
    const int warp = tid >> 5, lane = tid & 31;
    const int wm = warp & 3, wn = warp >> 2;
    const int m0 = blockIdx.y * 128;
    const int n0 = blockIdx.x * 256;

    float acc[2][8][4];
#pragma unroll
    for (int i = 0; i < 2; i++)
#pragma unroll
        for (int j = 0; j < 8; j++)
#pragma unroll
            for (int e = 0; e < 4; e++) acc[i][j][e] = 0.f;

    const __half* Ab = Ah + (size_t)m0 * C_;
    const __half* Bb = B2 + (size_t)n0 * K2;

    const int lrow = tid >> 2;
    const int lchk = (tid & 3) * 8;

#define LOADP(s, j) do { \
    const int koa = (((j) < 16) ? (j) : ((j) - 16)) * 32; \
    const int kob = (j) * 32; \
    CP_ASYNC16(smem_u32(smh + (s) * GA_ST + lrow * 40 + lchk), \
               Ab + (size_t)lrow * C_ + koa + lchk); \
    CP_ASYNC16(smem_u32(smh + GB_BASE + (size_t)(s) * GB_ST + lrow * 40 + lchk), \
               Bb + (size_t)lrow * K2 + kob + lchk); \
    CP_ASYNC16(smem_u32(smh + GB_BASE + (size_t)(s) * GB_ST + (lrow + 128) * 40 + lchk), \
               Bb + (size_t)(lrow + 128) * K2 + kob + lchk); \
} while (0)

    LOADP(0, 0); CP_COMMIT();
    LOADP(1, 1); CP_COMMIT();
    LOADP(2, 2); CP_COMMIT();

    const int a_row = wm * 32 + (lane & 15);
    const int a_col = (lane >> 4) << 3;
    const int b_row = wn * 64 + ((lane >> 4) << 3) + (lane & 7);
    const int b_col = ((lane >> 3) & 1) << 3;

    for (int j = 0; j < KIT2; ++j) {
        const int s = j & 3;
        CP_WAIT2();
        __syncthreads();
        if (j + 3 < KIT2) LOADP((j + 3) & 3, j + 3);
        CP_COMMIT();

        const __half* As = smh + s * GA_ST;
        const __half* Bs = smh + GB_BASE + (size_t)s * GB_ST;
#pragma unroll
        for (int kk = 0; kk < 2; kk++) {
            const int k16 = kk * 16;
            uint32_t a[2][4];
#pragma unroll
            for (int i = 0; i < 2; i++)
                ldsm_x4(a[i][0], a[i][1], a[i][2], a[i][3],
                        smem_u32(As + (a_row + i * 16) * 40 + k16 + a_col));
            uint32_t b[4][4];
#pragma unroll
            for (int jb = 0; jb < 4; jb++)
                ldsm_x4(b[jb][0], b[jb][1], b[jb][2], b[jb][3],
                        smem_u32(Bs + (b_row + jb * 16) * 40 + k16 + b_col));
#pragma unroll
            for (int i = 0; i < 2; i++)
#pragma unroll
                for (int jn = 0; jn < 8; jn++) {
                    const int jb = jn >> 1, hf = (jn & 1) * 2;
                    mma_f16(acc[i][jn], a[i][0], a[i][1], a[i][2], a[i][3],
                            b[jb][hf], b[jb][hf + 1]);
                }
        }
    }

#pragma unroll
    for (int i = 0; i < 2; i++) {
        const int r0 = m0 + wm * 32 + i * 16 + (lane >> 2);
#pragma unroll
        for (int jn = 0; jn < 8; jn++) {
            const int c0 = n0 + wn * 64 + jn * 8 + (lane & 3) * 2;
            float b0 = bias[c0], b1 = bias[c0 + 1];
            *(float2*)(Cout + (size_t)r0 * C_ + c0) =
                make_float2(acc[i][jn][0] + b0, acc[i][jn][1] + b1);
            *(float2*)(Cout + (size_t)(r0 + 8) * C_ + c0) =
                make_float2(acc[i][jn][2] + b0, acc[i][jn][3] + b1);
        }
    }
}

// ---------------- local window attention (heads 0..3) -------------------------
#define QS 68
#define KS 68
#define SS 196
#define LA_SMEM ((64 * QS + 192 * KS + 64 * SS) * 4)

__global__ __launch_bounds__(256) void local_attn_kernel(float* __restrict__ attn_out)
{
    extern __shared__ float sm[];
    float* qs = sm;
    float* ks = qs + 64 * QS;
    float* sc = ks + 192 * KS;

    const int w = blockIdx.x;
    const int bh = blockIdx.y;
    const int b = bh >> 2, hh = bh & 3;
    const int t = threadIdx.x;
    const size_t rowbase = (size_t)b * N_ + (size_t)w * M_;
    const int col0 = hh * D_;

    for (int idx = t; idx < 64 * 16; idx += 256) {
        int r = idx >> 4, c4 = (idx & 15) * 4;
        float4 v = *(const float4*)(g_Q + (rowbase + r) * C_ + col0 + c4);
        float* dst = qs + r * QS + c4;
        dst[0] = v.x * 0.125f; dst[1] = v.y * 0.125f;
        dst[2] = v.z * 0.125f; dst[3] = v.w * 0.125f;
    }
    const int nbase = (w - 1) * M_;
    for (int idx = t; idx < 192 * 16; idx += 256) {
        int r = idx >> 4, c4 = (idx & 15) * 4;
        int n = nbase + r;
        float4 v = make_float4(0.f, 0.f, 0.f, 0.f);
        if (n >= 0 && n < N_)
            v = *(const float4*)(g_KV + ((size_t)b * N_ + n) * C_ + col0 + c4);
        float* dst = ks + r * KS + c4;
        dst[0] = v.x; dst[1] = v.y; dst[2] = v.z; dst[3] = v.w;
    }
    __syncthreads();

    {
        const int ti = (t & 15) * 4;
        const int tj = (t >> 4) * 12;
        float a[4][12];
#pragma unroll
        for (int i = 0; i < 4; i++)
#pragma unroll
            for (int j = 0; j < 12; j++) a[i][j] = 0.f;

        for (int k4 = 0; k4 < 64; k4 += 4) {
            float4 qv[4];
#pragma unroll
            for (int i = 0; i < 4; i++)
                qv[i] = *(const float4*)&qs[(ti + i) * QS + k4];
#pragma unroll
            for (int j = 0; j < 12; j++) {
                float4 kv = *(const float4*)&ks[(tj + j) * KS + k4];
#pragma unroll
                for (int i = 0; i < 4; i++) {
                    a[i][j] = fmaf(qv[i].x, kv.x, a[i][j]);
                    a[i][j] = fmaf(qv[i].y, kv.y, a[i][j]);
                    a[i][j] = fmaf(qv[i].z, kv.z, a[i][j]);
                    a[i][j] = fmaf(qv[i].w, kv.w, a[i][j]);
                }
            }
        }
        const bool leftInv = (w == 0), rightInv = (w == NW - 1);
#pragma unroll
        for (int i = 0; i < 4; i++)
#pragma unroll
            for (int j = 0; j < 12; j++) {
                int jj = tj + j;
                float s = a[i][j];
                if ((jj < 64 && leftInv) || (jj >= 128 && rightInv)) s = NEG_INF_F;
                sc[(ti + i) * SS + jj] = s;
            }
    }
    __syncthreads();

    {
        const int warp = t >> 5, lane = t & 31;
        for (int r = warp; r < 64; r += 8) {
            float m = -1e30f;
            for (int j = lane; j < 192; j += 32) m = fmaxf(m, sc[r * SS + j]);
#pragma unroll
            for (int o = 16; o; o >>= 1) m = fmaxf(m, __shfl_xor_sync(0xffffffffu, m, o));
            float s = 0.f;
            for (int j = lane; j < 192; j += 32) {
                float e = __expf(sc[r * SS + j] - m);
                sc[r * SS + j] = e;
                s += e;
            }
#pragma unroll
            for (int o = 16; o; o >>= 1) s += __shfl_xor_sync(0xffffffffu, s, o);
            float inv = 1.f / s;
            for (int j = lane; j < 192; j += 32) sc[r * SS + j] *= inv;
        }
    }
    __syncthreads();

    {
        const int ti = (t & 15) * 4;
        const int te = (t >> 4) * 4;
        float a[4][4];
#pragma unroll
        for (int i = 0; i < 4; i++)
#pragma unroll
            for (int e = 0; e < 4; e++) a[i][e] = 0.f;

        // j-blocked by 4: float4 prob loads (broadcast) + float4 v loads
        for (int j4 = 0; j4 < 48; j4++) {
            float pr[4][4];
#pragma unroll
            for (int i = 0; i < 4; i++) {
                float4 p = *(const float4*)&sc[(ti + i) * SS + j4 * 4];
                pr[i][0] = p.x; pr[i][1] = p.y; pr[i][2] = p.z; pr[i][3] = p.w;
            }
#pragma unroll
            for (int jj = 0; jj < 4; jj++) {
                float4 vv = *(const float4*)&ks[(j4 * 4 + jj) * KS + te];
#pragma unroll
                for (int i = 0; i < 4; i++) {
                    a[i][0] = fmaf(pr[i][jj], vv.x, a[i][0]);
                    a[i][1] = fmaf(pr[i][jj], vv.y, a[i][1]);
                    a[i][2] = fmaf(pr[i][jj], vv.z, a[i][2]);
                    a[i][3] = fmaf(pr[i][jj], vv.w, a[i][3]);
                }
            }
        }
#pragma unroll
        for (int i = 0; i < 4; i++) {
            int n = w * M_ + ti + i;
            size_t o1 = ((size_t)(b * H_ + hh) * N_ + n) * D_ + te;
#pragma unroll
            for (int e = 0; e < 4; e++) attn_out[o1 + e] = a[i][e];

            // fp16 write for proj GEMM
            __half* hdst = g_attnH + ((size_t)b * N_ + n) * C_ + hh * D_ + te;
            *(__half2*)(hdst + 0) = __floats2half2_rn(a[i][0], a[i][1]);
            *(__half2*)(hdst + 2) = __floats2half2_rn(a[i][2], a[i][3]);
        }
    }
}

// ---------------- linear attention (heads 4..7) -------------------------------
__global__ void zero_ctx_kernel()
{
    const int total = 16 * 4096 + 16 * 64;
    for (int i = blockIdx.x * blockDim.x + threadIdx.x; i < total;
         i += gridDim.x * blockDim.x) {
        if (i < 16 * 4096) g_ctx[i] = 0.f;
        else g_csum[i - 16 * 4096] = 0.f;
    }
}

#define CT_SMEM (256 * 64 * 4)
__global__ __launch_bounds__(256) void ctx_kernel()
{
    extern __shared__ float tile[];
    const int bh = blockIdx.y;
    const int b = bh >> 2, hh = 4 + (bh & 3);
    const int n0 = blockIdx.x * 256;
    const int t = threadIdx.x;

    const float* src = g_KV + ((size_t)b * N_ + n0) * C_ + hh * D_;
    for (int idx = t; idx < 256 * 16; idx += 256) {
        int r = idx >> 4, c4 = (idx & 15) * 4;
        float4 v = *(const float4*)(src + (size_t)r * C_ + c4);
        float* dst = tile + r * 64 + c4;
        dst[0] = v.x; dst[1] = v.y; dst[2] = v.z; dst[3] = v.w;
    }
    __syncthreads();

    const int d = t >> 2, q = t & 3;
    float4 acc[4];
#pragma unroll
    for (int i = 0; i < 4; i++) acc[i] = make_float4(0.f, 0.f, 0.f, 0.f);
    float ssum = 0.f;

    for (int n = 0; n < 256; n++) {
        float ek = __expf(tile[n * 64 + d]);
        ssum += ek;
        const float4* vr = (const float4*)(tile + n * 64 + q * 16);
#pragma unroll
        for (int e4 = 0; e4 < 4; e4++) {
            float4 v = vr[e4];
            acc[e4].x = fmaf(ek, v.x, acc[e4].x);
            acc[e4].y = fmaf(ek, v.y, acc[e4].y);
            acc[e4].z = fmaf(ek, v.z, acc[e4].z);
            acc[e4].w = fmaf(ek, v.w, acc[e4].w);
        }
    }
    float* dst = g_ctx + bh * 4096 + d * 64 + q * 16;
#pragma unroll
    for (int e4 = 0; e4 < 4; e4++) {
        atomicAdd(dst + e4 * 4 + 0, acc[e4].x);
        atomicAdd(dst + e4 * 4 + 1, acc[e4].y);
        atomicAdd(dst + e4 * 4 + 2, acc[e4].z);
        atomicAdd(dst + e4 * 4 + 3, acc[e4].w);
    }
    if (q == 0) atomicAdd(&g_csum[bh * 64 + d], ssum);
}

__global__ __launch_bounds__(256) void lin_out_kernel(float* __restrict__ attn_out)
{
    __shared__ float ctx_s[4096];
    __shared__ float cinv_s[64];
    const int bh = blockIdx.y;
    const int b = bh >> 2, hh = 4 + (bh & 3);
    const int t = threadIdx.x;

    if (t < 64) cinv_s[t] = 1.f / g_csum[bh * 64 + t];
    for (int i = t; i < 4096; i += 256) ctx_s[i] = g_ctx[bh * 4096 + i];
    __syncthreads();

    const int warp = t >> 5, lane = t & 31;
    for (int r = warp; r < 64; r += 8) {
        const int n = blockIdx.x * 64 + r;
        const float* qrow = g_Q + ((size_t)b * N_ + n) * C_ + hh * D_;
        float q0 = qrow[lane], q1 = qrow[lane + 32];
        float m = fmaxf(q0, q1);
#pragma unroll
        for (int o = 16; o; o >>= 1) m = fmaxf(m, __shfl_xor_sync(0xffffffffu, m, o));
        float e0 = __expf(q0 - m), e1 = __expf(q1 - m);
        float s = e0 + e1;
#pragma unroll
        for (int o = 16; o; o >>= 1) s += __shfl_xor_sync(0xffffffffu, s, o);
        float inv = 0.125f / s;
        e0 *= inv * cinv_s[lane];
        e1 *= inv * cinv_s[lane + 32];

        float a0 = 0.f, a1 = 0.f;
#pragma unroll
        for (int dd = 0; dd < 64; dd++) {
            float sq = __shfl_sync(0xffffffffu, (dd < 32) ? e0 : e1, dd & 31);
            a0 = fmaf(sq, ctx_s[dd * 64 + lane], a0);
            a1 = fmaf(sq, ctx_s[dd * 64 + lane + 32], a1);
        }
        size_t o1 = ((size_t)(b * H_ + hh) * N_ + n) * D_;
        attn_out[o1 + lane] = a0;
        attn_out[o1 + lane + 32] = a1;

        __half* hdst = g_attnH + ((size_t)b * N_ + n) * C_ + hh * D_;
        hdst[lane] = __float2half_rn(a0);
        hdst[lane + 32] = __float2half_rn(a1);
    }
}

// ---------------------------------- launch ------------------------------------
extern "C" void kernel_launch(void* const* d_in, const int* in_sizes, int n_in,
                              void* d_out, int out_size)
{
    (void)in_sizes; (void)n_in; (void)out_size;
    const float* x     = (const float*)d_in[0];
    const float* Wq    = (const float*)d_in[1];
    const float* Wkv   = (const float*)d_in[2];
    const float* Wproj = (const float*)d_in[3];
    const float* bproj = (const float*)d_in[4];

    float* y    = (float*)d_out;
    float* attn = y + (size_t)ROWS * C_;

    float *pQ, *pKV;
    __nv_bfloat16 *px3, *pW2;
    __half *paH, *pWp2;
    cudaGetSymbolAddress((void**)&pQ, g_Q);
    cudaGetSymbolAddress((void**)&pKV, g_KV);
    cudaGetSymbolAddress((void**)&px3, g_x3);
    cudaGetSymbolAddress((void**)&pW2, g_W2);
    cudaGetSymbolAddress((void**)&paH, g_attnH);
    cudaGetSymbolAddress((void**)&pWp2, g_Wp2);

    cudaFuncSetAttribute(gemm_mma,
                         cudaFuncAttributeMaxDynamicSharedMemorySize, GEMM_SMEM);
    cudaFuncSetAttribute(gemm_proj_f16,
                         cudaFuncAttributeMaxDynamicSharedMemorySize, GEMM_SMEM);
    cudaFuncSetAttribute(local_attn_kernel,
                         cudaFuncAttributeMaxDynamicSharedMemorySize, LA_SMEM);
    cudaFuncSetAttribute(ctx_kernel,
                         cudaFuncAttributeMaxDynamicSharedMemorySize, CT_SMEM);

    // conversions
    split_kernel<<<4096, 256>>>(x, px3, ROWS, 0);
    split_kernel<<<128, 256>>>(Wq, pW2, C_, 1);
    split_kernel<<<128, 256>>>(Wkv, pW2 + (size_t)512 * K3, C_, 1);
    split_h2_kernel<<<128, 256>>>(Wproj, pWp2);

    // fused Q+KV GEMM: N=1024 (cols 0-511 -> Q, 512-1023 -> KV)
    gemm_mma<<<dim3(4, ROWS / 128), 512, GEMM_SMEM>>>(px3, pW2, pQ, pKV);

    local_attn_kernel<<<dim3(NW, 16), 256, LA_SMEM>>>(attn);

    zero_ctx_kernel<<<64, 256>>>();
    ctx_kernel<<<dim3(32, 16), 256, CT_SMEM>>>();
    lin_out_kernel<<<dim3(128, 16), 256>>>(attn);

    gemm_proj_f16<<<dim3(2, ROWS / 128), 512, GEMM_SMEM>>>(paH, pWp2, y, bproj);
}

// round 6
// speedup vs baseline: 1.1968x; 1.0928x over previous
#include <cuda_runtime.h>
#include <cuda_bf16.h>
#include <cuda_fp16.h>
#include <math.h>
#include <stdint.h>

#define B_    4
#define N_    8192
#define C_    512
#define K2    1024
#define H_    8
#define D_    64
#define M_    64           // window
#define NW    (N_ / M_)    // 128
#define ROWS  (B_ * N_)    // 32768
#define NEG_INF_F (-1000000000.0f)

// ---------------- scratch (static device globals: allocation-free) ------------
__device__ __align__(16) __half g_x2[(size_t)ROWS * K2];     // 64 MB [hi|lo]
__device__ __align__(16) __half g_attn2[(size_t)ROWS * K2];  // 64 MB [hi|lo]
__device__ __align__(16) __half g_W16[1024 * C_];            // fp16 Wq rows 0-511, Wkv rows 512-1023
__device__ __align__(16) __half g_Wp16[C_ * C_];             // fp16 Wproj
__device__ float g_Q[(size_t)ROWS * C_];
__device__ float g_KV[(size_t)ROWS * C_];
__device__ float g_ctx[16 * 64 * 64];
__device__ float g_csum[16 * 64];

// ---------------- helpers -----------------------------------------------------
__device__ __forceinline__ uint32_t smem_u32(const void* p) {
    uint32_t a;
    asm("{ .reg .u64 t; cvta.to.shared.u64 t, %1; cvt.u32.u64 %0, t; }"
        : "=r"(a) : "l"(p));
    return a;
}
#define CP_ASYNC16(dst, src) \
    asm volatile("cp.async.cg.shared.global [%0], [%1], 16;" \
                 :: "r"(dst), "l"(src))
#define CP_COMMIT() asm volatile("cp.async.commit_group;" ::: "memory")
#define CP_WAIT2()  asm volatile("cp.async.wait_group 2;" ::: "memory")

__device__ __forceinline__ void ldsm_x4(uint32_t& r0, uint32_t& r1,
                                        uint32_t& r2, uint32_t& r3, uint32_t addr) {
    asm volatile("ldmatrix.sync.aligned.m8n8.x4.shared.b16 {%0,%1,%2,%3}, [%4];"
                 : "=r"(r0), "=r"(r1), "=r"(r2), "=r"(r3) : "r"(addr));
}
__device__ __forceinline__ void mma_f16(float* c, uint32_t a0, uint32_t a1,
                                        uint32_t a2, uint32_t a3,
                                        uint32_t b0, uint32_t b1) {
    asm volatile(
        "mma.sync.aligned.m16n8k16.row.col.f32.f16.f16.f32 "
        "{%0,%1,%2,%3}, {%4,%5,%6,%7}, {%8,%9}, {%0,%1,%2,%3};"
        : "+f"(c[0]), "+f"(c[1]), "+f"(c[2]), "+f"(c[3])
        : "r"(a0), "r"(a1), "r"(a2), "r"(a3), "r"(b0), "r"(b1));
}

// ---------------- conversions --------------------------------------------------
// exact fp16 hi/lo split of activations: dst[r][0..511]=hi, [512..1023]=lo
__global__ __launch_bounds__(256) void split_h2_kernel(
    const float* __restrict__ src, __half* __restrict__ dst, int nrows)
{
    int total = nrows * (C_ / 4);
    for (int i = blockIdx.x * blockDim.x + threadIdx.x; i < total;
         i += gridDim.x * blockDim.x) {
        int r = i >> 7;
        int c = (i & 127) * 4;
        float4 v = *(const float4*)(src + (size_t)r * C_ + c);
        __half h0 = __float2half_rn(v.x), h1 = __float2half_rn(v.y);
        __half h2 = __float2half_rn(v.z), h3 = __float2half_rn(v.w);
        __half2 hiA; hiA.x = h0; hiA.y = h1;
        __half2 hiB; hiB.x = h2; hiB.y = h3;
        __half2 loA = __floats2half2_rn(v.x - __half2float(h0),
                                        v.y - __half2float(h1));
        __half2 loB = __floats2half2_rn(v.z - __half2float(h2),
                                        v.w - __half2float(h3));
        __half* base = dst + (size_t)r * K2 + c;
        *(__half2*)(base + 0) = hiA;
        *(__half2*)(base + 2) = hiB;
        *(__half2*)(base + 512) = loA;
        *(__half2*)(base + 514) = loB;
    }
}

// plain fp32 -> fp16 rounding (weights), row stride C_ both sides
__global__ __launch_bounds__(256) void round_h_kernel(
    const float* __restrict__ src, __half* __restrict__ dst, int nrows)
{
    int total = nrows * (C_ / 4);
    for (int i = blockIdx.x * blockDim.x + threadIdx.x; i < total;
         i += gridDim.x * blockDim.x) {
        int r = i >> 7;
        int c = (i & 127) * 4;
        float4 v = *(const float4*)(src + (size_t)r * C_ + c);
        __half* base = dst + (size_t)r * C_ + c;
        *(__half2*)(base + 0) = __floats2half2_rn(v.x, v.y);
        *(__half2*)(base + 2) = __floats2half2_rn(v.z, v.w);
    }
}

// ---------------- fp16 mma GEMM: C[m,n] = sum_k A2[m,k'] Bh[n, k' mod 512] ----
// A2: [rows x 1024] fp16 ([hi|lo]); Bh: [nrows x 512] fp16.
// 128x256 tile, BK=32, 512 threads, 4-stage cp.async ring, K'=1024 (32 iters).
#define GST     4
#define GA_ST   (128 * 40)
#define GB_ST   (256 * 40)
#define GB_BASE (GST * GA_ST)
#define GEMM_SMEM ((GB_BASE + GST * GB_ST) * 2)   // 122880 bytes
#define KIT     (K2 / 32)             // 32

__global__ __launch_bounds__(512, 1) void gemm_f16(
    const __half* __restrict__ A2, const __half* __restrict__ Bh,
    float* __restrict__ CoutA, float* __restrict__ CoutB,
    const float* __restrict__ bias)
{
    extern __shared__ __half smh[];
    const int tid = threadIdx.x;
    const int warp = tid >> 5, lane = tid & 31;
    const int wm = warp & 3, wn = warp >> 2;
    const int m0 = blockIdx.y * 128;
    const int n0 = blockIdx.x * 256;

    float acc[2][8][4];
#pragma unroll
    for (int i = 0; i < 2; i++)
#pragma unroll
        for (int j = 0; j < 8; j++)
#pragma unroll
            for (int e = 0; e < 4; e++) acc[i][j][e] = 0.f;

    const __half* Ab = A2 + (size_t)m0 * K2;
    const __half* Bb = Bh + (size_t)n0 * C_;

    const int lrow = tid >> 2;
    const int lchk = (tid & 3) * 8;

#define LOADQ(s, j) do { \
    const int koa = (j) * 32; \
    const int kob = ((j) & 15) * 32; \
    CP_ASYNC16(smem_u32(smh + (s) * GA_ST + lrow * 40 + lchk), \
               Ab + (size_t)lrow * K2 + koa + lchk); \
    CP_ASYNC16(smem_u32(smh + GB_BASE + (size_t)(s) * GB_ST + lrow * 40 + lchk), \
               Bb + (size_t)lrow * C_ + kob + lchk); \
    CP_ASYNC16(smem_u32(smh + GB_BASE + (size_t)(s) * GB_ST + (lrow + 128) * 40 + lchk), \
               Bb + (size_t)(lrow + 128) * C_ + kob + lchk); \
} while (0)

    LOADQ(0, 0); CP_COMMIT();
    LOADQ(1, 1); CP_COMMIT();
    LOADQ(2, 2); CP_COMMIT();

    const int a_row = wm * 32 + (lane & 15);
    const int a_col = (lane >> 4) << 3;
    const int b_row = wn * 64 + ((lane >> 4) << 3) + (lane & 7);
    const int b_col = ((lane >> 3) & 1) << 3;

    for (int j = 0; j < KIT; ++j) {
        const int s = j & 3;
        CP_WAIT2();
        __syncthreads();
        if (j + 3 < KIT) LOADQ((j + 3) & 3, j + 3);
        CP_COMMIT();

        const __half* As = smh + s * GA_ST;
        const __half* Bs = smh + GB_BASE + (size_t)s * GB_ST;
#pragma unroll
        for (int kk = 0; kk < 2; kk++) {
            const int k16 = kk * 16;
            uint32_t a[2][4];
#pragma unroll
            for (int i = 0; i < 2; i++)
                ldsm_x4(a[i][0], a[i][1], a[i][2], a[i][3],
                        smem_u32(As + (a_row + i * 16) * 40 + k16 + a_col));
            uint32_t b[4][4];
#pragma unroll
            for (int jb = 0; jb < 4; jb++)
                ldsm_x4(b[jb][0], b[jb][1], b[jb][2], b[jb][3],
                        smem_u32(Bs + (b_row + jb * 16) * 40 + k16 + b_col));
#pragma unroll
            for (int i = 0; i < 2; i++)
#pragma unroll
                for (int jn = 0; jn < 8; jn++) {
                    const int jb = jn >> 1, hf = (jn & 1) * 2;
                    mma_f16(acc[i][jn], a[i][0], a[i][1], a[i][2], a[i][3],
                            b[jb][hf], b[jb][hf + 1]);
                }
        }
    }

    // epilogue: route to CoutA (n0<512) or CoutB
    float* Cout = (n0 < 512) ? CoutA : CoutB;
    const int nc0 = (n0 < 512) ? n0 : n0 - 512;
#pragma unroll
    for (int i = 0; i < 2; i++) {
        const int r0 = m0 + wm * 32 + i * 16 + (lane >> 2);
#pragma unroll
        for (int jn = 0; jn < 8; jn++) {
            const int c0 = nc0 + wn * 64 + jn * 8 + (lane & 3) * 2;
            float b0 = bias ? bias[c0] : 0.f;
            float b1 = bias ? bias[c0 + 1] : 0.f;
            *(float2*)(Cout + (size_t)r0 * C_ + c0) =
                make_float2(acc[i][jn][0] + b0, acc[i][jn][1] + b1);
            *(float2*)(Cout + (size_t)(r0 + 8) * C_ + c0) =
                make_float2(acc[i][jn][2] + b0, acc[i][jn][3] + b1);
        }
    }
}

// ---------------- local window attention (heads 0..3) -------------------------
#define QS 68
#define KS 68
#define SS 196
#define LA_SMEM ((64 * QS + 192 * KS + 64 * SS) * 4)

__global__ __launch_bounds__(256) void local_attn_kernel(float* __restrict__ attn_out)
{
    extern __shared__ float sm[];
    float* qs = sm;
    float* ks = qs + 64 * QS;
    float* sc = ks + 192 * KS;

    const int w = blockIdx.x;
    const int bh = blockIdx.y;
    const int b = bh >> 2, hh = bh & 3;
    const int t = threadIdx.x;
    const size_t rowbase = (size_t)b * N_ + (size_t)w * M_;
    const int col0 = hh * D_;

    for (int idx = t; idx < 64 * 16; idx += 256) {
        int r = idx >> 4, c4 = (idx & 15) * 4;
        float4 v = *(const float4*)(g_Q + (rowbase + r) * C_ + col0 + c4);
        float* dst = qs + r * QS + c4;
        dst[0] = v.x * 0.125f; dst[1] = v.y * 0.125f;
        dst[2] = v.z * 0.125f; dst[3] = v.w * 0.125f;
    }
    const int nbase = (w - 1) * M_;
    for (int idx = t; idx < 192 * 16; idx += 256) {
        int r = idx >> 4, c4 = (idx & 15) * 4;
        int n = nbase + r;
        float4 v = make_float4(0.f, 0.f, 0.f, 0.f);
        if (n >= 0 && n < N_)
            v = *(const float4*)(g_KV + ((size_t)b * N_ + n) * C_ + col0 + c4);
        float* dst = ks + r * KS + c4;
        dst[0] = v.x; dst[1] = v.y; dst[2] = v.z; dst[3] = v.w;
    }
    __syncthreads();

    {
        const int ti = (t & 15) * 4;
        const int tj = (t >> 4) * 12;
        float a[4][12];
#pragma unroll
        for (int i = 0; i < 4; i++)
#pragma unroll
            for (int j = 0; j < 12; j++) a[i][j] = 0.f;

        for (int k4 = 0; k4 < 64; k4 += 4) {
            float4 qv[4];
#pragma unroll
            for (int i = 0; i < 4; i++)
                qv[i] = *(const float4*)&qs[(ti + i) * QS + k4];
#pragma unroll
            for (int j = 0; j < 12; j++) {
                float4 kv = *(const float4*)&ks[(tj + j) * KS + k4];
#pragma unroll
                for (int i = 0; i < 4; i++) {
                    a[i][j] = fmaf(qv[i].x, kv.x, a[i][j]);
                    a[i][j] = fmaf(qv[i].y, kv.y, a[i][j]);
                    a[i][j] = fmaf(qv[i].z, kv.z, a[i][j]);
                    a[i][j] = fmaf(qv[i].w, kv.w, a[i][j]);
                }
            }
        }
        const bool leftInv = (w == 0), rightInv = (w == NW - 1);
#pragma unroll
        for (int i = 0; i < 4; i++)
#pragma unroll
            for (int j = 0; j < 12; j++) {
                int jj = tj + j;
                float s = a[i][j];
                if ((jj < 64 && leftInv) || (jj >= 128 && rightInv)) s = NEG_INF_F;
                sc[(ti + i) * SS + jj] = s;
            }
    }
    __syncthreads();

    {
        const int warp = t >> 5, lane = t & 31;
        for (int r = warp; r < 64; r += 8) {
            float m = -1e30f;
            for (int j = lane; j < 192; j += 32) m = fmaxf(m, sc[r * SS + j]);
#pragma unroll
            for (int o = 16; o; o >>= 1) m = fmaxf(m, __shfl_xor_sync(0xffffffffu, m, o));
            float s = 0.f;
            for (int j = lane; j < 192; j += 32) {
                float e = __expf(sc[r * SS + j] - m);
                sc[r * SS + j] = e;
                s += e;
            }
#pragma unroll
            for (int o = 16; o; o >>= 1) s += __shfl_xor_sync(0xffffffffu, s, o);
            float inv = 1.f / s;
            for (int j = lane; j < 192; j += 32) sc[r * SS + j] *= inv;
        }
    }
    __syncthreads();

    {
        const int ti = (t & 15) * 4;
        const int te = (t >> 4) * 4;
        float a[4][4];
#pragma unroll
        for (int i = 0; i < 4; i++)
#pragma unroll
            for (int e = 0; e < 4; e++) a[i][e] = 0.f;

        for (int j4 = 0; j4 < 48; j4++) {
            float pr[4][4];
#pragma unroll
            for (int i = 0; i < 4; i++) {
                float4 p = *(const float4*)&sc[(ti + i) * SS + j4 * 4];
                pr[i][0] = p.x; pr[i][1] = p.y; pr[i][2] = p.z; pr[i][3] = p.w;
            }
#pragma unroll
            for (int jj = 0; jj < 4; jj++) {
                float4 vv = *(const float4*)&ks[(j4 * 4 + jj) * KS + te];
#pragma unroll
                for (int i = 0; i < 4; i++) {
                    a[i][0] = fmaf(pr[i][jj], vv.x, a[i][0]);
                    a[i][1] = fmaf(pr[i][jj], vv.y, a[i][1]);
                    a[i][2] = fmaf(pr[i][jj], vv.z, a[i][2]);
                    a[i][3] = fmaf(pr[i][jj], vv.w, a[i][3]);
                }
            }
        }
#pragma unroll
        for (int i = 0; i < 4; i++) {
            int n = w * M_ + ti + i;
            size_t o1 = ((size_t)(b * H_ + hh) * N_ + n) * D_ + te;
#pragma unroll
            for (int e = 0; e < 4; e++) attn_out[o1 + e] = a[i][e];

            // fused exact fp16 hi/lo write for proj GEMM
            __half h0 = __float2half_rn(a[i][0]);
            __half h1 = __float2half_rn(a[i][1]);
            __half h2 = __float2half_rn(a[i][2]);
            __half h3 = __float2half_rn(a[i][3]);
            __half2 hiA; hiA.x = h0; hiA.y = h1;
            __half2 hiB; hiB.x = h2; hiB.y = h3;
            __half2 loA = __floats2half2_rn(a[i][0] - __half2float(h0),
                                            a[i][1] - __half2float(h1));
            __half2 loB = __floats2half2_rn(a[i][2] - __half2float(h2),
                                            a[i][3] - __half2float(h3));
            __half* hdst = g_attn2 + ((size_t)b * N_ + n) * K2 + hh * D_ + te;
            *(__half2*)(hdst + 0) = hiA;
            *(__half2*)(hdst + 2) = hiB;
            *(__half2*)(hdst + 512) = loA;
            *(__half2*)(hdst + 514) = loB;
        }
    }
}

// ---------------- linear attention (heads 4..7) -------------------------------
__global__ void zero_ctx_kernel()
{
    const int total = 16 * 4096 + 16 * 64;
    for (int i = blockIdx.x * blockDim.x + threadIdx.x; i < total;
         i += gridDim.x * blockDim.x) {
        if (i < 16 * 4096) g_ctx[i] = 0.f;
        else g_csum[i - 16 * 4096] = 0.f;
    }
}

#define CT_SMEM (256 * 64 * 4)
__global__ __launch_bounds__(256) void ctx_kernel()
{
    extern __shared__ float tile[];
    const int bh = blockIdx.y;
    const int b = bh >> 2, hh = 4 + (bh & 3);
    const int n0 = blockIdx.x * 256;
    const int t = threadIdx.x;

    const float* src = g_KV + ((size_t)b * N_ + n0) * C_ + hh * D_;
    for (int idx = t; idx < 256 * 16; idx += 256) {
        int r = idx >> 4, c4 = (idx & 15) * 4;
        float4 v = *(const float4*)(src + (size_t)r * C_ + c4);
        float* dst = tile + r * 64 + c4;
        dst[0] = v.x; dst[1] = v.y; dst[2] = v.z; dst[3] = v.w;
    }
    __syncthreads();

    const int d = t >> 2, q = t & 3;
    float4 acc[4];
#pragma unroll
    for (int i = 0; i < 4; i++) acc[i] = make_float4(0.f, 0.f, 0.f, 0.f);
    float ssum = 0.f;

    for (int n = 0; n < 256; n++) {
        float ek = __expf(tile[n * 64 + d]);
        ssum += ek;
        const float4* vr = (const float4*)(tile + n * 64 + q * 16);
#pragma unroll
        for (int e4 = 0; e4 < 4; e4++) {
            float4 v = vr[e4];
            acc[e4].x = fmaf(ek, v.x, acc[e4].x);
            acc[e4].y = fmaf(ek, v.y, acc[e4].y);
            acc[e4].z = fmaf(ek, v.z, acc[e4].z);
            acc[e4].w = fmaf(ek, v.w, acc[e4].w);
        }
    }
    float* dst = g_ctx + bh * 4096 + d * 64 + q * 16;
#pragma unroll
    for (int e4 = 0; e4 < 4; e4++) {
        atomicAdd(dst + e4 * 4 + 0, acc[e4].x);
        atomicAdd(dst + e4 * 4 + 1, acc[e4].y);
        atomicAdd(dst + e4 * 4 + 2, acc[e4].z);
        atomicAdd(dst + e4 * 4 + 3, acc[e4].w);
    }
    if (q == 0) atomicAdd(&g_csum[bh * 64 + d], ssum);
}

__global__ __launch_bounds__(256) void lin_out_kernel(float* __restrict__ attn_out)
{
    __shared__ float ctx_s[4096];
    __shared__ float cinv_s[64];
    const int bh = blockIdx.y;
    const int b = bh >> 2, hh = 4 + (bh & 3);
    const int t = threadIdx.x;

    if (t < 64) cinv_s[t] = 1.f / g_csum[bh * 64 + t];
    for (int i = t; i < 4096; i += 256) ctx_s[i] = g_ctx[bh * 4096 + i];
    __syncthreads();

    const int warp = t >> 5, lane = t & 31;
    for (int r = warp; r < 64; r += 8) {
        const int n = blockIdx.x * 64 + r;
        const float* qrow = g_Q + ((size_t)b * N_ + n) * C_ + hh * D_;
        float q0 = qrow[lane], q1 = qrow[lane + 32];
        float m = fmaxf(q0, q1);
#pragma unroll
        for (int o = 16; o; o >>= 1) m = fmaxf(m, __shfl_xor_sync(0xffffffffu, m, o));
        float e0 = __expf(q0 - m), e1 = __expf(q1 - m);
        float s = e0 + e1;
#pragma unroll
        for (int o = 16; o; o >>= 1) s += __shfl_xor_sync(0xffffffffu, s, o);
        float inv = 0.125f / s;
        e0 *= inv * cinv_s[lane];
        e1 *= inv * cinv_s[lane + 32];

        float a0 = 0.f, a1 = 0.f;
#pragma unroll
        for (int dd = 0; dd < 64; dd++) {
            float sq = __shfl_sync(0xffffffffu, (dd < 32) ? e0 : e1, dd & 31);
            a0 = fmaf(sq, ctx_s[dd * 64 + lane], a0);
            a1 = fmaf(sq, ctx_s[dd * 64 + lane + 32], a1);
        }
        size_t o1 = ((size_t)(b * H_ + hh) * N_ + n) * D_;
        attn_out[o1 + lane] = a0;
        attn_out[o1 + lane + 32] = a1;

        // fused exact fp16 hi/lo write
        __half a0h = __float2half_rn(a0);
        __half a1h = __float2half_rn(a1);
        __half a0l = __float2half_rn(a0 - __half2float(a0h));
        __half a1l = __float2half_rn(a1 - __half2float(a1h));
        __half* hdst = g_attn2 + ((size_t)b * N_ + n) * K2 + hh * D_;
        hdst[lane] = a0h;           hdst[lane + 32] = a1h;
        hdst[512 + lane] = a0l;     hdst[512 + lane + 32] = a1l;
    }
}

// ---------------------------------- launch ------------------------------------
extern "C" void kernel_launch(void* const* d_in, const int* in_sizes, int n_in,
                              void* d_out, int out_size)
{
    (void)in_sizes; (void)n_in; (void)out_size;
    const float* x     = (const float*)d_in[0];
    const float* Wq    = (const float*)d_in[1];
    const float* Wkv   = (const float*)d_in[2];
    const float* Wproj = (const float*)d_in[3];
    const float* bproj = (const float*)d_in[4];

    float* y    = (float*)d_out;
    float* attn = y + (size_t)ROWS * C_;

    float *pQ, *pKV;
    __half *px2, *pa2, *pW16, *pWp16;
    cudaGetSymbolAddress((void**)&pQ, g_Q);
    cudaGetSymbolAddress((void**)&pKV, g_KV);
    cudaGetSymbolAddress((void**)&px2, g_x2);
    cudaGetSymbolAddress((void**)&pa2, g_attn2);
    cudaGetSymbolAddress((void**)&pW16, g_W16);
    cudaGetSymbolAddress((void**)&pWp16, g_Wp16);

    cudaFuncSetAttribute(gemm_f16,
                         cudaFuncAttributeMaxDynamicSharedMemorySize, GEMM_SMEM);
    cudaFuncSetAttribute(local_attn_kernel,
                         cudaFuncAttributeMaxDynamicSharedMemorySize, LA_SMEM);
    cudaFuncSetAttribute(ctx_kernel,
                         cudaFuncAttributeMaxDynamicSharedMemorySize, CT_SMEM);

    // conversions
    split_h2_kernel<<<4096, 256>>>(x, px2, ROWS);
    round_h_kernel<<<128, 256>>>(Wq, pW16, C_);
    round_h_kernel<<<128, 256>>>(Wkv, pW16 + (size_t)512 * C_, C_);
    round_h_kernel<<<128, 256>>>(Wproj, pWp16, C_);

    // fused Q+KV GEMM: N=1024 (cols 0-511 -> Q, 512-1023 -> KV), K'=1024
    gemm_f16<<<dim3(4, ROWS / 128), 512, GEMM_SMEM>>>(px2, pW16, pQ, pKV, nullptr);

    local_attn_kernel<<<dim3(NW, 16), 256, LA_SMEM>>>(attn);

    zero_ctx_kernel<<<64, 256>>>();
    ctx_kernel<<<dim3(32, 16), 256, CT_SMEM>>>();
    lin_out_kernel<<<dim3(128, 16), 256>>>(attn);

    // proj GEMM: y = attn2 @ Wp16^T + bias, K'=1024
    gemm_f16<<<dim3(2, ROWS / 128), 512, GEMM_SMEM>>>(pa2, pWp16, y, y, bproj);
}

// round 7
// speedup vs baseline: 1.7317x; 1.4470x over previous
#include <cuda_runtime.h>
#include <cuda_bf16.h>
#include <cuda_fp16.h>
#include <math.h>
#include <stdint.h>

#define B_    4
#define N_    8192
#define C_    512
#define K2    1024
#define H_    8
#define D_    64
#define M_    64           // window
#define NW    (N_ / M_)    // 128
#define ROWS  (B_ * N_)    // 32768
#define NEG_INF_F (-1000000000.0f)

// ---------------- scratch (static device globals: allocation-free) ------------
__device__ __align__(16) __half g_x2[(size_t)ROWS * K2];     // 64 MB [hi|lo]
__device__ __align__(16) __half g_attn2[(size_t)ROWS * K2];  // 64 MB [hi|lo]
__device__ __align__(16) __half g_W16[1024 * C_];            // fp16 Wq | Wkv
__device__ __align__(16) __half g_Wp16[C_ * C_];             // fp16 Wproj
__device__ float g_Q[(size_t)ROWS * C_];
__device__ float g_KV[(size_t)ROWS * C_];
__device__ float g_ctx[16 * 64 * 64];
__device__ float g_csum[16 * 64];

// ---------------- helpers -----------------------------------------------------
__device__ __forceinline__ uint32_t smem_u32(const void* p) {
    uint32_t a;
    asm("{ .reg .u64 t; cvta.to.shared.u64 t, %1; cvt.u32.u64 %0, t; }"
        : "=r"(a) : "l"(p));
    return a;
}
#define CP_ASYNC16(dst, src) \
    asm volatile("cp.async.cg.shared.global [%0], [%1], 16;" \
                 :: "r"(dst), "l"(src))
#define CP_COMMIT() asm volatile("cp.async.commit_group;" ::: "memory")
#define CP_WAIT2()  asm volatile("cp.async.wait_group 2;" ::: "memory")

__device__ __forceinline__ void ldsm_x4(uint32_t& r0, uint32_t& r1,
                                        uint32_t& r2, uint32_t& r3, uint32_t addr) {
    asm volatile("ldmatrix.sync.aligned.m8n8.x4.shared.b16 {%0,%1,%2,%3}, [%4];"
                 : "=r"(r0), "=r"(r1), "=r"(r2), "=r"(r3) : "r"(addr));
}
__device__ __forceinline__ void mma_f16(float* c, uint32_t a0, uint32_t a1,
                                        uint32_t a2, uint32_t a3,
                                        uint32_t b0, uint32_t b1) {
    asm volatile(
        "mma.sync.aligned.m16n8k16.row.col.f32.f16.f16.f32 "
        "{%0,%1,%2,%3}, {%4,%5,%6,%7}, {%8,%9}, {%0,%1,%2,%3};"
        : "+f"(c[0]), "+f"(c[1]), "+f"(c[2]), "+f"(c[3])
        : "r"(a0), "r"(a1), "r"(a2), "r"(a3), "r"(b0), "r"(b1));
}

// ---------------- conversions --------------------------------------------------
__global__ __launch_bounds__(256) void split_h2_kernel(
    const float* __restrict__ src, __half* __restrict__ dst, int nrows)
{
    int total = nrows * (C_ / 4);
    for (int i = blockIdx.x * blockDim.x + threadIdx.x; i < total;
         i += gridDim.x * blockDim.x) {
        int r = i >> 7;
        int c = (i & 127) * 4;
        float4 v = *(const float4*)(src + (size_t)r * C_ + c);
        __half h0 = __float2half_rn(v.x), h1 = __float2half_rn(v.y);
        __half h2 = __float2half_rn(v.z), h3 = __float2half_rn(v.w);
        __half2 hiA; hiA.x = h0; hiA.y = h1;
        __half2 hiB; hiB.x = h2; hiB.y = h3;
        __half2 loA = __floats2half2_rn(v.x - __half2float(h0),
                                        v.y - __half2float(h1));
        __half2 loB = __floats2half2_rn(v.z - __half2float(h2),
                                        v.w - __half2float(h3));
        __half* base = dst + (size_t)r * K2 + c;
        *(__half2*)(base + 0) = hiA;
        *(__half2*)(base + 2) = hiB;
        *(__half2*)(base + 512) = loA;
        *(__half2*)(base + 514) = loB;
    }
}

__global__ __launch_bounds__(256) void round_h_kernel(
    const float* __restrict__ src, __half* __restrict__ dst, int nrows)
{
    int total = nrows * (C_ / 4);
    for (int i = blockIdx.x * blockDim.x + threadIdx.x; i < total;
         i += gridDim.x * blockDim.x) {
        int r = i >> 7;
        int c = (i & 127) * 4;
        float4 v = *(const float4*)(src + (size_t)r * C_ + c);
        __half* base = dst + (size_t)r * C_ + c;
        *(__half2*)(base + 0) = __floats2half2_rn(v.x, v.y);
        *(__half2*)(base + 2) = __floats2half2_rn(v.z, v.w);
    }
}

// ---------------- fp16 mma GEMM (same as round 6) ------------------------------
#define GST     4
#define GA_ST   (128 * 40)
#define GB_ST   (256 * 40)
#define GB_BASE (GST * GA_ST)
#define GEMM_SMEM ((GB_BASE + GST * GB_ST) * 2)
#define KIT     (K2 / 32)             // 32

__global__ __launch_bounds__(512, 1) void gemm_f16(
    const __half* __restrict__ A2, const __half* __restrict__ Bh,
    float* __restrict__ CoutA, float* __restrict__ CoutB,
    const float* __restrict__ bias)
{
    extern __shared__ __half smh[];
    const int tid = threadIdx.x;
    const int warp = tid >> 5, lane = tid & 31;
    const int wm = warp & 3, wn = warp >> 2;
    const int m0 = blockIdx.y * 128;
    const int n0 = blockIdx.x * 256;

    float acc[2][8][4];
#pragma unroll
    for (int i = 0; i < 2; i++)
#pragma unroll
        for (int j = 0; j < 8; j++)
#pragma unroll
            for (int e = 0; e < 4; e++) acc[i][j][e] = 0.f;

    const __half* Ab = A2 + (size_t)m0 * K2;
    const __half* Bb = Bh + (size_t)n0 * C_;

    const int lrow = tid >> 2;
    const int lchk = (tid & 3) * 8;

#define LOADQ(s, j) do { \
    const int koa = (j) * 32; \
    const int kob = ((j) & 15) * 32; \
    CP_ASYNC16(smem_u32(smh + (s) * GA_ST + lrow * 40 + lchk), \
               Ab + (size_t)lrow * K2 + koa + lchk); \
    CP_ASYNC16(smem_u32(smh + GB_BASE + (size_t)(s) * GB_ST + lrow * 40 + lchk), \
               Bb + (size_t)lrow * C_ + kob + lchk); \
    CP_ASYNC16(smem_u32(smh + GB_BASE + (size_t)(s) * GB_ST + (lrow + 128) * 40 + lchk), \
               Bb + (size_t)(lrow + 128) * C_ + kob + lchk); \
} while (0)

    LOADQ(0, 0); CP_COMMIT();
    LOADQ(1, 1); CP_COMMIT();
    LOADQ(2, 2); CP_COMMIT();

    const int a_row = wm * 32 + (lane & 15);
    const int a_col = (lane >> 4) << 3;
    const int b_row = wn * 64 + ((lane >> 4) << 3) + (lane & 7);
    const int b_col = ((lane >> 3) & 1) << 3;

    for (int j = 0; j < KIT; ++j) {
        const int s = j & 3;
        CP_WAIT2();
        __syncthreads();
        if (j + 3 < KIT) LOADQ((j + 3) & 3, j + 3);
        CP_COMMIT();

        const __half* As = smh + s * GA_ST;
        const __half* Bs = smh + GB_BASE + (size_t)s * GB_ST;
#pragma unroll
        for (int kk = 0; kk < 2; kk++) {
            const int k16 = kk * 16;
            uint32_t a[2][4];
#pragma unroll
            for (int i = 0; i < 2; i++)
                ldsm_x4(a[i][0], a[i][1], a[i][2], a[i][3],
                        smem_u32(As + (a_row + i * 16) * 40 + k16 + a_col));
            uint32_t b[4][4];
#pragma unroll
            for (int jb = 0; jb < 4; jb++)
                ldsm_x4(b[jb][0], b[jb][1], b[jb][2], b[jb][3],
                        smem_u32(Bs + (b_row + jb * 16) * 40 + k16 + b_col));
#pragma unroll
            for (int i = 0; i < 2; i++)
#pragma unroll
                for (int jn = 0; jn < 8; jn++) {
                    const int jb = jn >> 1, hf = (jn & 1) * 2;
                    mma_f16(acc[i][jn], a[i][0], a[i][1], a[i][2], a[i][3],
                            b[jb][hf], b[jb][hf + 1]);
                }
        }
    }

    float* Cout = (n0 < 512) ? CoutA : CoutB;
    const int nc0 = (n0 < 512) ? n0 : n0 - 512;
#pragma unroll
    for (int i = 0; i < 2; i++) {
        const int r0 = m0 + wm * 32 + i * 16 + (lane >> 2);
#pragma unroll
        for (int jn = 0; jn < 8; jn++) {
            const int c0 = nc0 + wn * 64 + jn * 8 + (lane & 3) * 2;
            float b0 = bias ? bias[c0] : 0.f;
            float b1 = bias ? bias[c0 + 1] : 0.f;
            *(float2*)(Cout + (size_t)r0 * C_ + c0) =
                make_float2(acc[i][jn][0] + b0, acc[i][jn][1] + b1);
            *(float2*)(Cout + (size_t)(r0 + 8) * C_ + c0) =
                make_float2(acc[i][jn][2] + b0, acc[i][jn][3] + b1);
        }
    }
}

// ---------------- local window attention via mma (heads 0..3) ------------------
// Per block (w, bh): 256 threads, 8 warps as (4m x 2n).
// Scores: m64 n192 k'=128 (q exact hi/lo fp16 vs k fp16).
// Softmax in registers (quad shfl + cross-warp smem bufs).
// AV: m64 n64 k'=384 (probs exact hi/lo fp16 vs v fp16).
#define QS_STRIDE 136   // halfs: 128 + 8 pad   (272 B/row)
#define KS_STRIDE 72    // halfs: 64 + 8        (144 B/row)
#define VT_STRIDE 200   // halfs: 192 + 8       (400 B/row)
#define PR_STRIDE 408   // halfs: 384 + 24      (816 B/row)
#define OFF_QS 0
#define OFF_KS (OFF_QS + 64 * QS_STRIDE * 2)          // 17408
#define OFF_VT (OFF_KS + 192 * KS_STRIDE * 2)         // 45056
#define OFF_PR (OFF_VT + 64 * VT_STRIDE * 2)          // 70656
#define OFF_RED (OFF_PR + 64 * PR_STRIDE * 2)         // 122880
#define OFF_SUM (OFF_RED + 512)                       // 123392
#define LA_SMEM (OFF_SUM + 512)                       // 123904

__global__ __launch_bounds__(256, 1) void local_attn_mma(float* __restrict__ attn_out)
{
    extern __shared__ char smla[];
    __half* qs = (__half*)(smla + OFF_QS);
    __half* ks = (__half*)(smla + OFF_KS);
    __half* vt = (__half*)(smla + OFF_VT);
    __half* pr = (__half*)(smla + OFF_PR);
    float* redbuf = (float*)(smla + OFF_RED);    // [2][64]
    float* sumbuf = (float*)(smla + OFF_SUM);    // [2][64]

    const int w = blockIdx.x;
    const int bh = blockIdx.y;
    const int b = bh >> 2, hh = bh & 3;
    const int t = threadIdx.x;
    const int warp = t >> 5, lane = t & 31;
    const int wm = warp & 3, wn = warp >> 2;
    const size_t rowbase = (size_t)b * N_ + (size_t)w * M_;
    const int col0 = hh * D_;

    // ---- load q (scaled, exact fp16 hi/lo) ----
    for (int idx = t; idx < 64 * 16; idx += 256) {
        int r = idx >> 4, c4 = (idx & 15) * 4;
        float4 v = *(const float4*)(g_Q + (rowbase + r) * C_ + col0 + c4);
        v.x *= 0.125f; v.y *= 0.125f; v.z *= 0.125f; v.w *= 0.125f;
        __half h0 = __float2half_rn(v.x), h1 = __float2half_rn(v.y);
        __half h2 = __float2half_rn(v.z), h3 = __float2half_rn(v.w);
        __half2 hiA; hiA.x = h0; hiA.y = h1;
        __half2 hiB; hiB.x = h2; hiB.y = h3;
        __half2 loA = __floats2half2_rn(v.x - __half2float(h0),
                                        v.y - __half2float(h1));
        __half2 loB = __floats2half2_rn(v.z - __half2float(h2),
                                        v.w - __half2float(h3));
        __half* q = qs + r * QS_STRIDE + c4;
        *(__half2*)(q + 0) = hiA;  *(__half2*)(q + 2) = hiB;
        *(__half2*)(q + 64) = loA; *(__half2*)(q + 66) = loB;
    }
    // ---- load k (= v) fp16: ks row-major [j][d] and vt transposed [d][j] ----
    const int nbase = (w - 1) * M_;
    for (int idx = t; idx < 192 * 16; idx += 256) {
        int j = idx >> 4, c4 = (idx & 15) * 4;
        int n = nbase + j;
        float4 v = make_float4(0.f, 0.f, 0.f, 0.f);
        if (n >= 0 && n < N_)
            v = *(const float4*)(g_KV + ((size_t)b * N_ + n) * C_ + col0 + c4);
        __half h0 = __float2half_rn(v.x), h1 = __float2half_rn(v.y);
        __half h2 = __float2half_rn(v.z), h3 = __float2half_rn(v.w);
        __half* kp = ks + j * KS_STRIDE + c4;
        __half2 p01; p01.x = h0; p01.y = h1;
        __half2 p23; p23.x = h2; p23.y = h3;
        *(__half2*)(kp + 0) = p01; *(__half2*)(kp + 2) = p23;
        vt[(c4 + 0) * VT_STRIDE + j] = h0;
        vt[(c4 + 1) * VT_STRIDE + j] = h1;
        vt[(c4 + 2) * VT_STRIDE + j] = h2;
        vt[(c4 + 3) * VT_STRIDE + j] = h3;
    }
    __syncthreads();

    // ---- scores: warp tile 16 x 96, k' = 128 ----
    float c[12][4];
#pragma unroll
    for (int jn = 0; jn < 12; jn++)
#pragma unroll
        for (int e = 0; e < 4; e++) c[jn][e] = 0.f;

    const int a_rw = wm * 16 + (lane & 15);
    const int a_cl = (lane >> 4) << 3;
    const int b_rw = wn * 96 + ((lane >> 4) << 3) + (lane & 7);
    const int b_cl = ((lane >> 3) & 1) << 3;

#pragma unroll
    for (int k16 = 0; k16 < 128; k16 += 16) {
        uint32_t a0, a1, a2, a3;
        ldsm_x4(a0, a1, a2, a3, smem_u32(qs + a_rw * QS_STRIDE + k16 + a_cl));
        uint32_t bf[6][4];
#pragma unroll
        for (int jb = 0; jb < 6; jb++)
            ldsm_x4(bf[jb][0], bf[jb][1], bf[jb][2], bf[jb][3],
                    smem_u32(ks + (b_rw + jb * 16) * KS_STRIDE + (k16 & 63) + b_cl));
#pragma unroll
        for (int jn = 0; jn < 12; jn++) {
            const int jb = jn >> 1, hf = (jn & 1) * 2;
            mma_f16(c[jn], a0, a1, a2, a3, bf[jb][hf], bf[jb][hf + 1]);
        }
    }

    // ---- mask ----
    const bool leftInv = (w == 0), rightInv = (w == NW - 1);
    if (leftInv || rightInv) {
#pragma unroll
        for (int jn = 0; jn < 12; jn++) {
            const int cb = wn * 96 + jn * 8 + (lane & 3) * 2;
#pragma unroll
            for (int e = 0; e < 4; e++) {
                const int jj = cb + (e & 1);
                if ((jj < 64 && leftInv) || (jj >= 128 && rightInv))
                    c[jn][e] = NEG_INF_F;
            }
        }
    }

    // ---- softmax: rows grA = wm*16 + (lane>>2), grB = grA + 8 ----
    const int grA = wm * 16 + (lane >> 2);
    float mA = -1e30f, mB = -1e30f;
#pragma unroll
    for (int jn = 0; jn < 12; jn++) {
        mA = fmaxf(mA, fmaxf(c[jn][0], c[jn][1]));
        mB = fmaxf(mB, fmaxf(c[jn][2], c[jn][3]));
    }
    mA = fmaxf(mA, __shfl_xor_sync(0xffffffffu, mA, 1));
    mA = fmaxf(mA, __shfl_xor_sync(0xffffffffu, mA, 2));
    mB = fmaxf(mB, __shfl_xor_sync(0xffffffffu, mB, 1));
    mB = fmaxf(mB, __shfl_xor_sync(0xffffffffu, mB, 2));
    if ((lane & 3) == 0) {
        redbuf[wn * 64 + grA] = mA;
        redbuf[wn * 64 + grA + 8] = mB;
    }
    __syncthreads();
    mA = fmaxf(redbuf[grA], redbuf[64 + grA]);
    mB = fmaxf(redbuf[grA + 8], redbuf[64 + grA + 8]);

    float sA = 0.f, sB = 0.f;
#pragma unroll
    for (int jn = 0; jn < 12; jn++) {
        c[jn][0] = __expf(c[jn][0] - mA); sA += c[jn][0];
        c[jn][1] = __expf(c[jn][1] - mA); sA += c[jn][1];
        c[jn][2] = __expf(c[jn][2] - mB); sB += c[jn][2];
        c[jn][3] = __expf(c[jn][3] - mB); sB += c[jn][3];
    }
    sA += __shfl_xor_sync(0xffffffffu, sA, 1);
    sA += __shfl_xor_sync(0xffffffffu, sA, 2);
    sB += __shfl_xor_sync(0xffffffffu, sB, 1);
    sB += __shfl_xor_sync(0xffffffffu, sB, 2);
    if ((lane & 3) == 0) {
        sumbuf[wn * 64 + grA] = sA;
        sumbuf[wn * 64 + grA + 8] = sB;
    }
    __syncthreads();
    const float invA = 1.f / (sumbuf[grA] + sumbuf[64 + grA]);
    const float invB = 1.f / (sumbuf[grA + 8] + sumbuf[64 + grA + 8]);

    // ---- write probs fp16 hi/lo: pr[row][jj] hi, pr[row][192+jj] lo ----
#pragma unroll
    for (int jn = 0; jn < 12; jn++) {
        const int cb = wn * 96 + jn * 8 + (lane & 3) * 2;
        float p0 = c[jn][0] * invA, p1 = c[jn][1] * invA;
        float p2 = c[jn][2] * invB, p3 = c[jn][3] * invB;
        __half h0 = __float2half_rn(p0), h1 = __float2half_rn(p1);
        __half h2 = __float2half_rn(p2), h3 = __float2half_rn(p3);
        __half2 hiA; hiA.x = h0; hiA.y = h1;
        __half2 hiB; hiB.x = h2; hiB.y = h3;
        __half2 loA = __floats2half2_rn(p0 - __half2float(h0),
                                        p1 - __half2float(h1));
        __half2 loB = __floats2half2_rn(p2 - __half2float(h2),
                                        p3 - __half2float(h3));
        __half* pA = pr + grA * PR_STRIDE + cb;
        __half* pB = pr + (grA + 8) * PR_STRIDE + cb;
        *(__half2*)(pA + 0) = hiA;   *(__half2*)(pA + 192) = loA;
        *(__half2*)(pB + 0) = hiB;   *(__half2*)(pB + 192) = loB;
    }
    __syncthreads();

    // ---- AV: warp tile 16 x 32, k' = 384 ----
    float o[4][4];
#pragma unroll
    for (int jn = 0; jn < 4; jn++)
#pragma unroll
        for (int e = 0; e < 4; e++) o[jn][e] = 0.f;

    const int av_brw = wn * 32 + ((lane >> 4) << 3) + (lane & 7);
#pragma unroll
    for (int k16 = 0; k16 < 384; k16 += 16) {
        uint32_t a0, a1, a2, a3;
        ldsm_x4(a0, a1, a2, a3, smem_u32(pr + a_rw * PR_STRIDE + k16 + a_cl));
        const int jcol = (k16 % 192) + b_cl;
        uint32_t bf[2][4];
#pragma unroll
        for (int jb = 0; jb < 2; jb++)
            ldsm_x4(bf[jb][0], bf[jb][1], bf[jb][2], bf[jb][3],
                    smem_u32(vt + (av_brw + jb * 16) * VT_STRIDE + jcol));
#pragma unroll
        for (int jn = 0; jn < 4; jn++) {
            const int jb = jn >> 1, hf = (jn & 1) * 2;
            mma_f16(o[jn], a0, a1, a2, a3, bf[jb][hf], bf[jb][hf + 1]);
        }
    }

    // ---- epilogue ----
#pragma unroll
    for (int jn = 0; jn < 4; jn++) {
        const int cb = wn * 32 + jn * 8 + (lane & 3) * 2;
#pragma unroll
        for (int half = 0; half < 2; half++) {
            const int row = grA + half * 8;
            const int n = w * M_ + row;
            const float v0 = o[jn][half * 2], v1 = o[jn][half * 2 + 1];
            float* ad = attn_out + ((size_t)(b * H_ + hh) * N_ + n) * D_ + cb;
            ad[0] = v0; ad[1] = v1;
            __half h0 = __float2half_rn(v0), h1 = __float2half_rn(v1);
            __half2 hi2; hi2.x = h0; hi2.y = h1;
            __half2 lo2 = __floats2half2_rn(v0 - __half2float(h0),
                                            v1 - __half2float(h1));
            __half* hdst = g_attn2 + ((size_t)b * N_ + n) * K2 + hh * D_ + cb;
            *(__half2*)(hdst + 0) = hi2;
            *(__half2*)(hdst + 512) = lo2;
        }
    }
}

// ---------------- linear attention (heads 4..7) -------------------------------
__global__ void zero_ctx_kernel()
{
    const int total = 16 * 4096 + 16 * 64;
    for (int i = blockIdx.x * blockDim.x + threadIdx.x; i < total;
         i += gridDim.x * blockDim.x) {
        if (i < 16 * 4096) g_ctx[i] = 0.f;
        else g_csum[i - 16 * 4096] = 0.f;
    }
}

#define CT_SMEM (256 * 64 * 4)
__global__ __launch_bounds__(256) void ctx_kernel()
{
    extern __shared__ float tile[];
    const int bh = blockIdx.y;
    const int b = bh >> 2, hh = 4 + (bh & 3);
    const int n0 = blockIdx.x * 256;
    const int t = threadIdx.x;

    const float* src = g_KV + ((size_t)b * N_ + n0) * C_ + hh * D_;
    for (int idx = t; idx < 256 * 16; idx += 256) {
        int r = idx >> 4, c4 = (idx & 15) * 4;
        float4 v = *(const float4*)(src + (size_t)r * C_ + c4);
        float* dst = tile + r * 64 + c4;
        dst[0] = v.x; dst[1] = v.y; dst[2] = v.z; dst[3] = v.w;
    }
    __syncthreads();

    const int d = t >> 2, q = t & 3;
    float4 acc[4];
#pragma unroll
    for (int i = 0; i < 4; i++) acc[i] = make_float4(0.f, 0.f, 0.f, 0.f);
    float ssum = 0.f;

    for (int n = 0; n < 256; n++) {
        float ek = __expf(tile[n * 64 + d]);
        ssum += ek;
        const float4* vr = (const float4*)(tile + n * 64 + q * 16);
#pragma unroll
        for (int e4 = 0; e4 < 4; e4++) {
            float4 v = vr[e4];
            acc[e4].x = fmaf(ek, v.x, acc[e4].x);
            acc[e4].y = fmaf(ek, v.y, acc[e4].y);
            acc[e4].z = fmaf(ek, v.z, acc[e4].z);
            acc[e4].w = fmaf(ek, v.w, acc[e4].w);
        }
    }
    float* dst = g_ctx + bh * 4096 + d * 64 + q * 16;
#pragma unroll
    for (int e4 = 0; e4 < 4; e4++) {
        atomicAdd(dst + e4 * 4 + 0, acc[e4].x);
        atomicAdd(dst + e4 * 4 + 1, acc[e4].y);
        atomicAdd(dst + e4 * 4 + 2, acc[e4].z);
        atomicAdd(dst + e4 * 4 + 3, acc[e4].w);
    }
    if (q == 0) atomicAdd(&g_csum[bh * 64 + d], ssum);
}

__global__ __launch_bounds__(256) void lin_out_kernel(float* __restrict__ attn_out)
{
    __shared__ float ctx_s[4096];
    __shared__ float cinv_s[64];
    const int bh = blockIdx.y;
    const int b = bh >> 2, hh = 4 + (bh & 3);
    const int t = threadIdx.x;

    if (t < 64) cinv_s[t] = 1.f / g_csum[bh * 64 + t];
    for (int i = t; i < 4096; i += 256) ctx_s[i] = g_ctx[bh * 4096 + i];
    __syncthreads();

    const int warp = t >> 5, lane = t & 31;
    for (int r = warp; r < 64; r += 8) {
        const int n = blockIdx.x * 64 + r;
        const float* qrow = g_Q + ((size_t)b * N_ + n) * C_ + hh * D_;
        float q0 = qrow[lane], q1 = qrow[lane + 32];
        float m = fmaxf(q0, q1);
#pragma unroll
        for (int o = 16; o; o >>= 1) m = fmaxf(m, __shfl_xor_sync(0xffffffffu, m, o));
        float e0 = __expf(q0 - m), e1 = __expf(q1 - m);
        float s = e0 + e1;
#pragma unroll
        for (int o = 16; o; o >>= 1) s += __shfl_xor_sync(0xffffffffu, s, o);
        float inv = 0.125f / s;
        e0 *= inv * cinv_s[lane];
        e1 *= inv * cinv_s[lane + 32];

        float a0 = 0.f, a1 = 0.f;
#pragma unroll
        for (int dd = 0; dd < 64; dd++) {
            float sq = __shfl_sync(0xffffffffu, (dd < 32) ? e0 : e1, dd & 31);
            a0 = fmaf(sq, ctx_s[dd * 64 + lane], a0);
            a1 = fmaf(sq, ctx_s[dd * 64 + lane + 32], a1);
        }
        size_t o1 = ((size_t)(b * H_ + hh) * N_ + n) * D_;
        attn_out[o1 + lane] = a0;
        attn_out[o1 + lane + 32] = a1;

        __half a0h = __float2half_rn(a0);
        __half a1h = __float2half_rn(a1);
        __half a0l = __float2half_rn(a0 - __half2float(a0h));
        __half a1l = __float2half_rn(a1 - __half2float(a1h));
        __half* hdst = g_attn2 + ((size_t)b * N_ + n) * K2 + hh * D_;
        hdst[lane] = a0h;           hdst[lane + 32] = a1h;
        hdst[512 + lane] = a0l;     hdst[512 + lane + 32] = a1l;
    }
}

// ---------------------------------- launch ------------------------------------
extern "C" void kernel_launch(void* const* d_in, const int* in_sizes, int n_in,
                              void* d_out, int out_size)
{
    (void)in_sizes; (void)n_in; (void)out_size;
    const float* x     = (const float*)d_in[0];
    const float* Wq    = (const float*)d_in[1];
    const float* Wkv   = (const float*)d_in[2];
    const float* Wproj = (const float*)d_in[3];
    const float* bproj = (const float*)d_in[4];

    float* y    = (float*)d_out;
    float* attn = y + (size_t)ROWS * C_;

    float *pQ, *pKV;
    __half *px2, *pa2, *pW16, *pWp16;
    cudaGetSymbolAddress((void**)&pQ, g_Q);
    cudaGetSymbolAddress((void**)&pKV, g_KV);
    cudaGetSymbolAddress((void**)&px2, g_x2);
    cudaGetSymbolAddress((void**)&pa2, g_attn2);
    cudaGetSymbolAddress((void**)&pW16, g_W16);
    cudaGetSymbolAddress((void**)&pWp16, g_Wp16);

    cudaFuncSetAttribute(gemm_f16,
                         cudaFuncAttributeMaxDynamicSharedMemorySize, GEMM_SMEM);
    cudaFuncSetAttribute(local_attn_mma,
                         cudaFuncAttributeMaxDynamicSharedMemorySize, LA_SMEM);
    cudaFuncSetAttribute(ctx_kernel,
                         cudaFuncAttributeMaxDynamicSharedMemorySize, CT_SMEM);

    // conversions
    split_h2_kernel<<<4096, 256>>>(x, px2, ROWS);
    round_h_kernel<<<128, 256>>>(Wq, pW16, C_);
    round_h_kernel<<<128, 256>>>(Wkv, pW16 + (size_t)512 * C_, C_);
    round_h_kernel<<<128, 256>>>(Wproj, pWp16, C_);

    // fused Q+KV GEMM: N=1024 (cols 0-511 -> Q, 512-1023 -> KV), K'=1024
    gemm_f16<<<dim3(4, ROWS / 128), 512, GEMM_SMEM>>>(px2, pW16, pQ, pKV, nullptr);

    local_attn_mma<<<dim3(NW, 16), 256, LA_SMEM>>>(attn);

    zero_ctx_kernel<<<64, 256>>>();
    ctx_kernel<<<dim3(32, 16), 256, CT_SMEM>>>();
    lin_out_kernel<<<dim3(128, 16), 256>>>(attn);

    // proj GEMM: y = attn2 @ Wp16^T + bias, K'=1024
    gemm_f16<<<dim3(2, ROWS / 128), 512, GEMM_SMEM>>>(pa2, pWp16, y, y, bproj);
}

// round 8
// speedup vs baseline: 2.2128x; 1.2778x over previous
#include <cuda_runtime.h>
#include <cuda_bf16.h>
#include <cuda_fp16.h>
#include <math.h>
#include <stdint.h>

#define B_    4
#define N_    8192
#define C_    512
#define H_    8
#define D_    64
#define M_    64           // window
#define NW    (N_ / M_)    // 128
#define ROWS  (B_ * N_)    // 32768
#define NEG_INF_F (-1000000000.0f)

// ---------------- scratch (static device globals: allocation-free) ------------
__device__ __align__(16) __half g_xh[(size_t)ROWS * C_];     // 32 MB fp16 x
__device__ __align__(16) __half g_attnH[(size_t)ROWS * C_];  // 32 MB fp16 attn
__device__ __align__(16) __half g_W16[1024 * C_];            // fp16 Wq | Wkv
__device__ __align__(16) __half g_Wp16[C_ * C_];             // fp16 Wproj
__device__ float g_Q[(size_t)ROWS * C_];
__device__ float g_KV[(size_t)ROWS * C_];
__device__ float g_ctx[16 * 64 * 64];
__device__ float g_csum[16 * 64];

// ---------------- helpers -----------------------------------------------------
__device__ __forceinline__ uint32_t smem_u32(const void* p) {
    uint32_t a;
    asm("{ .reg .u64 t; cvta.to.shared.u64 t, %1; cvt.u32.u64 %0, t; }"
        : "=r"(a) : "l"(p));
    return a;
}
#define CP_ASYNC16(dst, src) \
    asm volatile("cp.async.cg.shared.global [%0], [%1], 16;" \
                 :: "r"(dst), "l"(src))
#define CP_COMMIT() asm volatile("cp.async.commit_group;" ::: "memory")
#define CP_WAIT2()  asm volatile("cp.async.wait_group 2;" ::: "memory")

__device__ __forceinline__ void ldsm_x4(uint32_t& r0, uint32_t& r1,
                                        uint32_t& r2, uint32_t& r3, uint32_t addr) {
    asm volatile("ldmatrix.sync.aligned.m8n8.x4.shared.b16 {%0,%1,%2,%3}, [%4];"
                 : "=r"(r0), "=r"(r1), "=r"(r2), "=r"(r3) : "r"(addr));
}
__device__ __forceinline__ void mma_f16(float* c, uint32_t a0, uint32_t a1,
                                        uint32_t a2, uint32_t a3,
                                        uint32_t b0, uint32_t b1) {
    asm volatile(
        "mma.sync.aligned.m16n8k16.row.col.f32.f16.f16.f32 "
        "{%0,%1,%2,%3}, {%4,%5,%6,%7}, {%8,%9}, {%0,%1,%2,%3};"
        : "+f"(c[0]), "+f"(c[1]), "+f"(c[2]), "+f"(c[3])
        : "r"(a0), "r"(a1), "r"(a2), "r"(a3), "r"(b0), "r"(b1));
}

// ---------------- conversions --------------------------------------------------
// plain fp32 -> fp16 rounding, row stride C_ both sides
__global__ __launch_bounds__(256) void round_h_kernel(
    const float* __restrict__ src, __half* __restrict__ dst, int nrows)
{
    int total = nrows * (C_ / 4);
    for (int i = blockIdx.x * blockDim.x + threadIdx.x; i < total;
         i += gridDim.x * blockDim.x) {
        int r = i >> 7;
        int c = (i & 127) * 4;
        float4 v = *(const float4*)(src + (size_t)r * C_ + c);
        __half* base = dst + (size_t)r * C_ + c;
        *(__half2*)(base + 0) = __floats2half2_rn(v.x, v.y);
        *(__half2*)(base + 2) = __floats2half2_rn(v.z, v.w);
    }
}

// ---------------- fp16 mma GEMM: C[m,n] = sum_k Ah[m,k] Bh[n,k], K=512 --------
// 128x256 tile, BK=32, 512 threads (16 warps 4m x 4n), 4-stage cp.async ring.
#define GST     4
#define GA_ST   (128 * 40)
#define GB_ST   (256 * 40)
#define GB_BASE (GST * GA_ST)
#define GEMM_SMEM ((GB_BASE + GST * GB_ST) * 2)
#define KITS    (C_ / 32)             // 16

__global__ __launch_bounds__(512, 1) void gemm_f16(
    const __half* __restrict__ Ah, const __half* __restrict__ Bh,
    float* __restrict__ CoutA, float* __restrict__ CoutB,
    const float* __restrict__ bias)
{
    extern __shared__ __half smh[];
    const int tid = threadIdx.x;
    const int warp = tid >> 5, lane = tid & 31;
    const int wm = warp & 3, wn = warp >> 2;
    const int m0 = blockIdx.y * 128;
    const int n0 = blockIdx.x * 256;

    float acc[2][8][4];
#pragma unroll
    for (int i = 0; i < 2; i++)
#pragma unroll
        for (int j = 0; j < 8; j++)
#pragma unroll
            for (int e = 0; e < 4; e++) acc[i][j][e] = 0.f;

    const __half* Ab = Ah + (size_t)m0 * C_;
    const __half* Bb = Bh + (size_t)n0 * C_;

    const int lrow = tid >> 2;
    const int lchk = (tid & 3) * 8;

#define LOADQ(s, j) do { \
    const int ko = (j) * 32; \
    CP_ASYNC16(smem_u32(smh + (s) * GA_ST + lrow * 40 + lchk), \
               Ab + (size_t)lrow * C_ + ko + lchk); \
    CP_ASYNC16(smem_u32(smh + GB_BASE + (size_t)(s) * GB_ST + lrow * 40 + lchk), \
               Bb + (size_t)lrow * C_ + ko + lchk); \
    CP_ASYNC16(smem_u32(smh + GB_BASE + (size_t)(s) * GB_ST + (lrow + 128) * 40 + lchk), \
               Bb + (size_t)(lrow + 128) * C_ + ko + lchk); \
} while (0)

    LOADQ(0, 0); CP_COMMIT();
    LOADQ(1, 1); CP_COMMIT();
    LOADQ(2, 2); CP_COMMIT();

    const int a_row = wm * 32 + (lane & 15);
    const int a_col = (lane >> 4) << 3;
    const int b_row = wn * 64 + ((lane >> 4) << 3) + (lane & 7);
    const int b_col = ((lane >> 3) & 1) << 3;

    for (int j = 0; j < KITS; ++j) {
        const int s = j & 3;
        CP_WAIT2();
        __syncthreads();
        if (j + 3 < KITS) LOADQ((j + 3) & 3, j + 3);
        CP_COMMIT();

        const __half* As = smh + s * GA_ST;
        const __half* Bs = smh + GB_BASE + (size_t)s * GB_ST;
#pragma unroll
        for (int kk = 0; kk < 2; kk++) {
            const int k16 = kk * 16;
            uint32_t a[2][4];
#pragma unroll
            for (int i = 0; i < 2; i++)
                ldsm_x4(a[i][0], a[i][1], a[i][2], a[i][3],
                        smem_u32(As + (a_row + i * 16) * 40 + k16 + a_col));
            uint32_t b[4][4];
#pragma unroll
            for (int jb = 0; jb < 4; jb++)
                ldsm_x4(b[jb][0], b[jb][1], b[jb][2], b[jb][3],
                        smem_u32(Bs + (b_row + jb * 16) * 40 + k16 + b_col));
#pragma unroll
            for (int i = 0; i < 2; i++)
#pragma unroll
                for (int jn = 0; jn < 8; jn++) {
                    const int jb = jn >> 1, hf = (jn & 1) * 2;
                    mma_f16(acc[i][jn], a[i][0], a[i][1], a[i][2], a[i][3],
                            b[jb][hf], b[jb][hf + 1]);
                }
        }
    }

    float* Cout = (n0 < 512) ? CoutA : CoutB;
    const int nc0 = (n0 < 512) ? n0 : n0 - 512;
#pragma unroll
    for (int i = 0; i < 2; i++) {
        const int r0 = m0 + wm * 32 + i * 16 + (lane >> 2);
#pragma unroll
        for (int jn = 0; jn < 8; jn++) {
            const int c0 = nc0 + wn * 64 + jn * 8 + (lane & 3) * 2;
            float b0 = bias ? bias[c0] : 0.f;
            float b1 = bias ? bias[c0 + 1] : 0.f;
            *(float2*)(Cout + (size_t)r0 * C_ + c0) =
                make_float2(acc[i][jn][0] + b0, acc[i][jn][1] + b1);
            *(float2*)(Cout + (size_t)(r0 + 8) * C_ + c0) =
                make_float2(acc[i][jn][2] + b0, acc[i][jn][3] + b1);
        }
    }
}

// ---------------- local window attention via mma (heads 0..3) ------------------
#define QS_STRIDE 136
#define KS_STRIDE 72
#define VT_STRIDE 200
#define PR_STRIDE 408
#define OFF_QS 0
#define OFF_KS (OFF_QS + 64 * QS_STRIDE * 2)
#define OFF_VT (OFF_KS + 192 * KS_STRIDE * 2)
#define OFF_PR (OFF_VT + 64 * VT_STRIDE * 2)
#define OFF_RED (OFF_PR + 64 * PR_STRIDE * 2)
#define OFF_SUM (OFF_RED + 512)
#define LA_SMEM (OFF_SUM + 512)

__global__ __launch_bounds__(256, 1) void local_attn_mma(float* __restrict__ attn_out)
{
    extern __shared__ char smla[];
    __half* qs = (__half*)(smla + OFF_QS);
    __half* ks = (__half*)(smla + OFF_KS);
    __half* vt = (__half*)(smla + OFF_VT);
    __half* pr = (__half*)(smla + OFF_PR);
    float* redbuf = (float*)(smla + OFF_RED);
    float* sumbuf = (float*)(smla + OFF_SUM);

    const int w = blockIdx.x;
    const int bh = blockIdx.y;
    const int b = bh >> 2, hh = bh & 3;
    const int t = threadIdx.x;
    const int warp = t >> 5, lane = t & 31;
    const int wm = warp & 3, wn = warp >> 2;
    const size_t rowbase = (size_t)b * N_ + (size_t)w * M_;
    const int col0 = hh * D_;

    // ---- load q (scaled, exact fp16 hi/lo) ----
    for (int idx = t; idx < 64 * 16; idx += 256) {
        int r = idx >> 4, c4 = (idx & 15) * 4;
        float4 v = *(const float4*)(g_Q + (rowbase + r) * C_ + col0 + c4);
        v.x *= 0.125f; v.y *= 0.125f; v.z *= 0.125f; v.w *= 0.125f;
        __half h0 = __float2half_rn(v.x), h1 = __float2half_rn(v.y);
        __half h2 = __float2half_rn(v.z), h3 = __float2half_rn(v.w);
        __half2 hiA; hiA.x = h0; hiA.y = h1;
        __half2 hiB; hiB.x = h2; hiB.y = h3;
        __half2 loA = __floats2half2_rn(v.x - __half2float(h0),
                                        v.y - __half2float(h1));
        __half2 loB = __floats2half2_rn(v.z - __half2float(h2),
                                        v.w - __half2float(h3));
        __half* q = qs + r * QS_STRIDE + c4;
        *(__half2*)(q + 0) = hiA;  *(__half2*)(q + 2) = hiB;
        *(__half2*)(q + 64) = loA; *(__half2*)(q + 66) = loB;
    }
    // ---- load k (= v) fp16 ----
    const int nbase = (w - 1) * M_;
    for (int idx = t; idx < 192 * 16; idx += 256) {
        int j = idx >> 4, c4 = (idx & 15) * 4;
        int n = nbase + j;
        float4 v = make_float4(0.f, 0.f, 0.f, 0.f);
        if (n >= 0 && n < N_)
            v = *(const float4*)(g_KV + ((size_t)b * N_ + n) * C_ + col0 + c4);
        __half h0 = __float2half_rn(v.x), h1 = __float2half_rn(v.y);
        __half h2 = __float2half_rn(v.z), h3 = __float2half_rn(v.w);
        __half* kp = ks + j * KS_STRIDE + c4;
        __half2 p01; p01.x = h0; p01.y = h1;
        __half2 p23; p23.x = h2; p23.y = h3;
        *(__half2*)(kp + 0) = p01; *(__half2*)(kp + 2) = p23;
        vt[(c4 + 0) * VT_STRIDE + j] = h0;
        vt[(c4 + 1) * VT_STRIDE + j] = h1;
        vt[(c4 + 2) * VT_STRIDE + j] = h2;
        vt[(c4 + 3) * VT_STRIDE + j] = h3;
    }
    __syncthreads();

    // ---- scores ----
    float c[12][4];
#pragma unroll
    for (int jn = 0; jn < 12; jn++)
#pragma unroll
        for (int e = 0; e < 4; e++) c[jn][e] = 0.f;

    const int a_rw = wm * 16 + (lane & 15);
    const int a_cl = (lane >> 4) << 3;
    const int b_rw = wn * 96 + ((lane >> 4) << 3) + (lane & 7);
    const int b_cl = ((lane >> 3) & 1) << 3;

#pragma unroll
    for (int k16 = 0; k16 < 128; k16 += 16) {
        uint32_t a0, a1, a2, a3;
        ldsm_x4(a0, a1, a2, a3, smem_u32(qs + a_rw * QS_STRIDE + k16 + a_cl));
        uint32_t bf[6][4];
#pragma unroll
        for (int jb = 0; jb < 6; jb++)
            ldsm_x4(bf[jb][0], bf[jb][1], bf[jb][2], bf[jb][3],
                    smem_u32(ks + (b_rw + jb * 16) * KS_STRIDE + (k16 & 63) + b_cl));
#pragma unroll
        for (int jn = 0; jn < 12; jn++) {
            const int jb = jn >> 1, hf = (jn & 1) * 2;
            mma_f16(c[jn], a0, a1, a2, a3, bf[jb][hf], bf[jb][hf + 1]);
        }
    }

    // ---- mask ----
    const bool leftInv = (w == 0), rightInv = (w == NW - 1);
    if (leftInv || rightInv) {
#pragma unroll
        for (int jn = 0; jn < 12; jn++) {
            const int cb = wn * 96 + jn * 8 + (lane & 3) * 2;
#pragma unroll
            for (int e = 0; e < 4; e++) {
                const int jj = cb + (e & 1);
                if ((jj < 64 && leftInv) || (jj >= 128 && rightInv))
                    c[jn][e] = NEG_INF_F;
            }
        }
    }

    // ---- softmax ----
    const int grA = wm * 16 + (lane >> 2);
    float mA = -1e30f, mB = -1e30f;
#pragma unroll
    for (int jn = 0; jn < 12; jn++) {
        mA = fmaxf(mA, fmaxf(c[jn][0], c[jn][1]));
        mB = fmaxf(mB, fmaxf(c[jn][2], c[jn][3]));
    }
    mA = fmaxf(mA, __shfl_xor_sync(0xffffffffu, mA, 1));
    mA = fmaxf(mA, __shfl_xor_sync(0xffffffffu, mA, 2));
    mB = fmaxf(mB, __shfl_xor_sync(0xffffffffu, mB, 1));
    mB = fmaxf(mB, __shfl_xor_sync(0xffffffffu, mB, 2));
    if ((lane & 3) == 0) {
        redbuf[wn * 64 + grA] = mA;
        redbuf[wn * 64 + grA + 8] = mB;
    }
    __syncthreads();
    mA = fmaxf(redbuf[grA], redbuf[64 + grA]);
    mB = fmaxf(redbuf[grA + 8], redbuf[64 + grA + 8]);

    float sA = 0.f, sB = 0.f;
#pragma unroll
    for (int jn = 0; jn < 12; jn++) {
        c[jn][0] = __expf(c[jn][0] - mA); sA += c[jn][0];
        c[jn][1] = __expf(c[jn][1] - mA); sA += c[jn][1];
        c[jn][2] = __expf(c[jn][2] - mB); sB += c[jn][2];
        c[jn][3] = __expf(c[jn][3] - mB); sB += c[jn][3];
    }
    sA += __shfl_xor_sync(0xffffffffu, sA, 1);
    sA += __shfl_xor_sync(0xffffffffu, sA, 2);
    sB += __shfl_xor_sync(0xffffffffu, sB, 1);
    sB += __shfl_xor_sync(0xffffffffu, sB, 2);
    if ((lane & 3) == 0) {
        sumbuf[wn * 64 + grA] = sA;
        sumbuf[wn * 64 + grA + 8] = sB;
    }
    __syncthreads();
    const float invA = 1.f / (sumbuf[grA] + sumbuf[64 + grA]);
    const float invB = 1.f / (sumbuf[grA + 8] + sumbuf[64 + grA + 8]);

    // ---- write probs fp16 hi/lo ----
#pragma unroll
    for (int jn = 0; jn < 12; jn++) {
        const int cb = wn * 96 + jn * 8 + (lane & 3) * 2;
        float p0 = c[jn][0] * invA, p1 = c[jn][1] * invA;
        float p2 = c[jn][2] * invB, p3 = c[jn][3] * invB;
        __half h0 = __float2half_rn(p0), h1 = __float2half_rn(p1);
        __half h2 = __float2half_rn(p2), h3 = __float2half_rn(p3);
        __half2 hiA; hiA.x = h0; hiA.y = h1;
        __half2 hiB; hiB.x = h2; hiB.y = h3;
        __half2 loA = __floats2half2_rn(p0 - __half2float(h0),
                                        p1 - __half2float(h1));
        __half2 loB = __floats2half2_rn(p2 - __half2float(h2),
                                        p3 - __half2float(h3));
        __half* pA = pr + grA * PR_STRIDE + cb;
        __half* pB = pr + (grA + 8) * PR_STRIDE + cb;
        *(__half2*)(pA + 0) = hiA;   *(__half2*)(pA + 192) = loA;
        *(__half2*)(pB + 0) = hiB;   *(__half2*)(pB + 192) = loB;
    }
    __syncthreads();

    // ---- AV ----
    float o[4][4];
#pragma unroll
    for (int jn = 0; jn < 4; jn++)
#pragma unroll
        for (int e = 0; e < 4; e++) o[jn][e] = 0.f;

    const int av_brw = wn * 32 + ((lane >> 4) << 3) + (lane & 7);
#pragma unroll
    for (int k16 = 0; k16 < 384; k16 += 16) {
        uint32_t a0, a1, a2, a3;
        ldsm_x4(a0, a1, a2, a3, smem_u32(pr + a_rw * PR_STRIDE + k16 + a_cl));
        const int jcol = (k16 % 192) + b_cl;
        uint32_t bf[2][4];
#pragma unroll
        for (int jb = 0; jb < 2; jb++)
            ldsm_x4(bf[jb][0], bf[jb][1], bf[jb][2], bf[jb][3],
                    smem_u32(vt + (av_brw + jb * 16) * VT_STRIDE + jcol));
#pragma unroll
        for (int jn = 0; jn < 4; jn++) {
            const int jb = jn >> 1, hf = (jn & 1) * 2;
            mma_f16(o[jn], a0, a1, a2, a3, bf[jb][hf], bf[jb][hf + 1]);
        }
    }

    // ---- epilogue ----
#pragma unroll
    for (int jn = 0; jn < 4; jn++) {
        const int cb = wn * 32 + jn * 8 + (lane & 3) * 2;
#pragma unroll
        for (int half = 0; half < 2; half++) {
            const int row = grA + half * 8;
            const int n = w * M_ + row;
            const float v0 = o[jn][half * 2], v1 = o[jn][half * 2 + 1];
            float* ad = attn_out + ((size_t)(b * H_ + hh) * N_ + n) * D_ + cb;
            ad[0] = v0; ad[1] = v1;
            __half* hdst = g_attnH + ((size_t)b * N_ + n) * C_ + hh * D_ + cb;
            *(__half2*)hdst = __floats2half2_rn(v0, v1);
        }
    }
}

// ---------------- linear attention (heads 4..7) -------------------------------
__global__ void zero_ctx_kernel()
{
    const int total = 16 * 4096 + 16 * 64;
    for (int i = blockIdx.x * blockDim.x + threadIdx.x; i < total;
         i += gridDim.x * blockDim.x) {
        if (i < 16 * 4096) g_ctx[i] = 0.f;
        else g_csum[i - 16 * 4096] = 0.f;
    }
}

#define CT_SMEM (256 * 64 * 4)
__global__ __launch_bounds__(256) void ctx_kernel()
{
    extern __shared__ float tile[];
    const int bh = blockIdx.y;
    const int b = bh >> 2, hh = 4 + (bh & 3);
    const int n0 = blockIdx.x * 256;
    const int t = threadIdx.x;

    const float* src = g_KV + ((size_t)b * N_ + n0) * C_ + hh * D_;
    for (int idx = t; idx < 256 * 16; idx += 256) {
        int r = idx >> 4, c4 = (idx & 15) * 4;
        float4 v = *(const float4*)(src + (size_t)r * C_ + c4);
        float* dst = tile + r * 64 + c4;
        dst[0] = v.x; dst[1] = v.y; dst[2] = v.z; dst[3] = v.w;
    }
    __syncthreads();

    const int d = t >> 2, q = t & 3;
    float4 acc[4];
#pragma unroll
    for (int i = 0; i < 4; i++) acc[i] = make_float4(0.f, 0.f, 0.f, 0.f);
    float ssum = 0.f;

    for (int n = 0; n < 256; n++) {
        float ek = __expf(tile[n * 64 + d]);
        ssum += ek;
        const float4* vr = (const float4*)(tile + n * 64 + q * 16);
#pragma unroll
        for (int e4 = 0; e4 < 4; e4++) {
            float4 v = vr[e4];
            acc[e4].x = fmaf(ek, v.x, acc[e4].x);
            acc[e4].y = fmaf(ek, v.y, acc[e4].y);
            acc[e4].z = fmaf(ek, v.z, acc[e4].z);
            acc[e4].w = fmaf(ek, v.w, acc[e4].w);
        }
    }
    float* dst = g_ctx + bh * 4096 + d * 64 + q * 16;
#pragma unroll
    for (int e4 = 0; e4 < 4; e4++) {
        atomicAdd(dst + e4 * 4 + 0, acc[e4].x);
        atomicAdd(dst + e4 * 4 + 1, acc[e4].y);
        atomicAdd(dst + e4 * 4 + 2, acc[e4].z);
        atomicAdd(dst + e4 * 4 + 3, acc[e4].w);
    }
    if (q == 0) atomicAdd(&g_csum[bh * 64 + d], ssum);
}

__global__ __launch_bounds__(256) void lin_out_kernel(float* __restrict__ attn_out)
{
    __shared__ float ctx_s[4096];
    __shared__ float cinv_s[64];
    const int bh = blockIdx.y;
    const int b = bh >> 2, hh = 4 + (bh & 3);
    const int t = threadIdx.x;

    if (t < 64) cinv_s[t] = 1.f / g_csum[bh * 64 + t];
    for (int i = t; i < 4096; i += 256) ctx_s[i] = g_ctx[bh * 4096 + i];
    __syncthreads();

    const int warp = t >> 5, lane = t & 31;
    for (int r = warp; r < 64; r += 8) {
        const int n = blockIdx.x * 64 + r;
        const float* qrow = g_Q + ((size_t)b * N_ + n) * C_ + hh * D_;
        float q0 = qrow[lane], q1 = qrow[lane + 32];
        float m = fmaxf(q0, q1);
#pragma unroll
        for (int o = 16; o; o >>= 1) m = fmaxf(m, __shfl_xor_sync(0xffffffffu, m, o));
        float e0 = __expf(q0 - m), e1 = __expf(q1 - m);
        float s = e0 + e1;
#pragma unroll
        for (int o = 16; o; o >>= 1) s += __shfl_xor_sync(0xffffffffu, s, o);
        float inv = 0.125f / s;
        e0 *= inv * cinv_s[lane];
        e1 *= inv * cinv_s[lane + 32];

        float a0 = 0.f, a1 = 0.f;
#pragma unroll
        for (int dd = 0; dd < 64; dd++) {
            float sq = __shfl_sync(0xffffffffu, (dd < 32) ? e0 : e1, dd & 31);
            a0 = fmaf(sq, ctx_s[dd * 64 + lane], a0);
            a1 = fmaf(sq, ctx_s[dd * 64 + lane + 32], a1);
        }
        size_t o1 = ((size_t)(b * H_ + hh) * N_ + n) * D_;
        attn_out[o1 + lane] = a0;
        attn_out[o1 + lane + 32] = a1;

        __half* hdst = g_attnH + ((size_t)b * N_ + n) * C_ + hh * D_;
        hdst[lane] = __float2half_rn(a0);
        hdst[lane + 32] = __float2half_rn(a1);
    }
}

// ---------------------------------- launch ------------------------------------
extern "C" void kernel_launch(void* const* d_in, const int* in_sizes, int n_in,
                              void* d_out, int out_size)
{
    (void)in_sizes; (void)n_in; (void)out_size;
    const float* x     = (const float*)d_in[0];
    const float* Wq    = (const float*)d_in[1];
    const float* Wkv   = (const float*)d_in[2];
    const float* Wproj = (const float*)d_in[3];
    const float* bproj = (const float*)d_in[4];

    float* y    = (float*)d_out;
    float* attn = y + (size_t)ROWS * C_;

    float *pQ, *pKV;
    __half *pxh, *paH, *pW16, *pWp16;
    cudaGetSymbolAddress((void**)&pQ, g_Q);
    cudaGetSymbolAddress((void**)&pKV, g_KV);
    cudaGetSymbolAddress((void**)&pxh, g_xh);
    cudaGetSymbolAddress((void**)&paH, g_attnH);
    cudaGetSymbolAddress((void**)&pW16, g_W16);
    cudaGetSymbolAddress((void**)&pWp16, g_Wp16);

    cudaFuncSetAttribute(gemm_f16,
                         cudaFuncAttributeMaxDynamicSharedMemorySize, GEMM_SMEM);
    cudaFuncSetAttribute(local_attn_mma,
                         cudaFuncAttributeMaxDynamicSharedMemorySize, LA_SMEM);
    cudaFuncSetAttribute(ctx_kernel,
                         cudaFuncAttributeMaxDynamicSharedMemorySize, CT_SMEM);

    // conversions
    round_h_kernel<<<2048, 256>>>(x, pxh, ROWS);
    round_h_kernel<<<128, 256>>>(Wq, pW16, C_);
    round_h_kernel<<<128, 256>>>(Wkv, pW16 + (size_t)512 * C_, C_);
    round_h_kernel<<<128, 256>>>(Wproj, pWp16, C_);

    // fused Q+KV GEMM: N=1024 (cols 0-511 -> Q, 512-1023 -> KV), K=512
    gemm_f16<<<dim3(4, ROWS / 128), 512, GEMM_SMEM>>>(pxh, pW16, pQ, pKV, nullptr);

    local_attn_mma<<<dim3(NW, 16), 256, LA_SMEM>>>(attn);

    zero_ctx_kernel<<<64, 256>>>();
    ctx_kernel<<<dim3(32, 16), 256, CT_SMEM>>>();
    lin_out_kernel<<<dim3(128, 16), 256>>>(attn);

    // proj GEMM: y = attnH @ Wp16^T + bias, K=512
    gemm_f16<<<dim3(2, ROWS / 128), 512, GEMM_SMEM>>>(paH, pWp16, y, y, bproj);
}

// round 11
// speedup vs baseline: 2.4290x; 1.0977x over previous
#include <cuda_runtime.h>
#include <cuda_bf16.h>
#include <cuda_fp16.h>
#include <math.h>
#include <stdint.h>

#define B_    4
#define N_    8192
#define C_    512
#define H_    8
#define D_    64
#define M_    64           // window
#define NW    (N_ / M_)    // 128
#define ROWS  (B_ * N_)    // 32768
#define NEG_INF_F (-1000000000.0f)

// ---------------- scratch (static device globals: allocation-free) ------------
__device__ __align__(16) __half g_xh[(size_t)ROWS * C_];     // fp16 x
__device__ __align__(16) __half g_attnH[(size_t)ROWS * C_];  // fp16 attn (B,N,C)
__device__ __align__(16) __half g_W16[1024 * C_];            // fp16 Wq | Wkv
__device__ __align__(16) __half g_Wp16[C_ * C_];             // fp16 Wproj
__device__ __align__(16) __half g_Qh[(size_t)ROWS * 256];    // fp16 q, local heads
__device__ __align__(16) __half g_KVh[(size_t)ROWS * 256];   // fp16 kv, local heads
__device__ float g_Qf[(size_t)ROWS * 256];                   // fp32 q, linear heads
__device__ float g_KVf[(size_t)ROWS * 256];                  // fp32 kv, linear heads
__device__ float g_ctx[16 * 64 * 64];
__device__ float g_csum[16 * 64];

// ---------------- helpers -----------------------------------------------------
__device__ __forceinline__ uint32_t smem_u32(const void* p) {
    uint32_t a;
    asm("{ .reg .u64 t; cvta.to.shared.u64 t, %1; cvt.u32.u64 %0, t; }"
        : "=r"(a) : "l"(p));
    return a;
}
#define CP_ASYNC16(dst, src) \
    asm volatile("cp.async.cg.shared.global [%0], [%1], 16;" \
                 :: "r"(dst), "l"(src))
#define CP_COMMIT() asm volatile("cp.async.commit_group;" ::: "memory")
#define CP_WAIT2()  asm volatile("cp.async.wait_group 2;" ::: "memory")

__device__ __forceinline__ void ldsm_x4(uint32_t& r0, uint32_t& r1,
                                        uint32_t& r2, uint32_t& r3, uint32_t addr) {
    asm volatile("ldmatrix.sync.aligned.m8n8.x4.shared.b16 {%0,%1,%2,%3}, [%4];"
                 : "=r"(r0), "=r"(r1), "=r"(r2), "=r"(r3) : "r"(addr));
}
__device__ __forceinline__ void mma_f16(float* c, uint32_t a0, uint32_t a1,
                                        uint32_t a2, uint32_t a3,
                                        uint32_t b0, uint32_t b1) {
    asm volatile(
        "mma.sync.aligned.m16n8k16.row.col.f32.f16.f16.f32 "
        "{%0,%1,%2,%3}, {%4,%5,%6,%7}, {%8,%9}, {%0,%1,%2,%3};"
        : "+f"(c[0]), "+f"(c[1]), "+f"(c[2]), "+f"(c[3])
        : "r"(a0), "r"(a1), "r"(a2), "r"(a3), "r"(b0), "r"(b1));
}

// ---------------- conversions --------------------------------------------------
__global__ __launch_bounds__(256) void round_h_kernel(
    const float* __restrict__ src, __half* __restrict__ dst, int nrows)
{
    int total = nrows * (C_ / 4);
    for (int i = blockIdx.x * blockDim.x + threadIdx.x; i < total;
         i += gridDim.x * blockDim.x) {
        int r = i >> 7;
        int c = (i & 127) * 4;
        float4 v = *(const float4*)(src + (size_t)r * C_ + c);
        __half* base = dst + (size_t)r * C_ + c;
        *(__half2*)(base + 0) = __floats2half2_rn(v.x, v.y);
        *(__half2*)(base + 2) = __floats2half2_rn(v.z, v.w);
    }
}

// weights (3 matrices, 512x512 each = 65536 quads) + ctx/csum zeroing
__global__ __launch_bounds__(256) void prep_kernel(
    const float* __restrict__ Wq, const float* __restrict__ Wkv,
    const float* __restrict__ Wproj)
{
    const int wtotal = 3 * 65536;               // FIXED: 512 rows x 128 quads per matrix
    const int total = wtotal + 16 * 4096 + 16 * 64;
    for (int i = blockIdx.x * blockDim.x + threadIdx.x; i < total;
         i += gridDim.x * blockDim.x) {
        if (i < wtotal) {
            int mat = i >> 16, wi = i & 65535;
            int r = wi >> 7, c = (wi & 127) * 4;
            const float* src = (mat == 0) ? Wq : (mat == 1) ? Wkv : Wproj;
            __half* dst = (mat == 0) ? g_W16
                        : (mat == 1) ? (g_W16 + (size_t)512 * C_) : g_Wp16;
            float4 v = *(const float4*)(src + (size_t)r * C_ + c);
            __half* base = dst + (size_t)r * C_ + c;
            *(__half2*)(base + 0) = __floats2half2_rn(v.x, v.y);
            *(__half2*)(base + 2) = __floats2half2_rn(v.z, v.w);
        } else if (i < wtotal + 65536) {
            g_ctx[i - wtotal] = 0.f;
        } else {
            g_csum[i - wtotal - 65536] = 0.f;
        }
    }
}

// ---------------- fp16 mma GEMM, K=512, 128x256 tile --------------------------
#define GST     4
#define GA_ST   (128 * 40)
#define GB_ST   (256 * 40)
#define GB_BASE (GST * GA_ST)
#define GEMM_SMEM ((GB_BASE + GST * GB_ST) * 2)
#define KITS    (C_ / 32)             // 16

__global__ __launch_bounds__(512, 1) void gemm_f16(
    const __half* __restrict__ Ah, const __half* __restrict__ Bh,
    float* __restrict__ f0, float* __restrict__ f1,
    __half* __restrict__ h0p, __half* __restrict__ h1p,
    const float* __restrict__ bias, int mode)
{
    extern __shared__ __half smh[];
    const int tid = threadIdx.x;
    const int warp = tid >> 5, lane = tid & 31;
    const int wm = warp & 3, wn = warp >> 2;
    const int m0 = blockIdx.y * 128;
    const int n0 = blockIdx.x * 256;

    float acc[2][8][4];
#pragma unroll
    for (int i = 0; i < 2; i++)
#pragma unroll
        for (int j = 0; j < 8; j++)
#pragma unroll
            for (int e = 0; e < 4; e++) acc[i][j][e] = 0.f;

    const __half* Ab = Ah + (size_t)m0 * C_;
    const __half* Bb = Bh + (size_t)n0 * C_;

    const int lrow = tid >> 2;
    const int lchk = (tid & 3) * 8;

#define LOADQ(s, j) do { \
    const int ko = (j) * 32; \
    CP_ASYNC16(smem_u32(smh + (s) * GA_ST + lrow * 40 + lchk), \
               Ab + (size_t)lrow * C_ + ko + lchk); \
    CP_ASYNC16(smem_u32(smh + GB_BASE + (size_t)(s) * GB_ST + lrow * 40 + lchk), \
               Bb + (size_t)lrow * C_ + ko + lchk); \
    CP_ASYNC16(smem_u32(smh + GB_BASE + (size_t)(s) * GB_ST + (lrow + 128) * 40 + lchk), \
               Bb + (size_t)(lrow + 128) * C_ + ko + lchk); \
} while (0)

    LOADQ(0, 0); CP_COMMIT();
    LOADQ(1, 1); CP_COMMIT();
    LOADQ(2, 2); CP_COMMIT();

    const int a_row = wm * 32 + (lane & 15);
    const int a_col = (lane >> 4) << 3;
    const int b_row = wn * 64 + ((lane >> 4) << 3) + (lane & 7);
    const int b_col = ((lane >> 3) & 1) << 3;

    for (int j = 0; j < KITS; ++j) {
        const int s = j & 3;
        CP_WAIT2();
        __syncthreads();
        if (j + 3 < KITS) LOADQ((j + 3) & 3, j + 3);
        CP_COMMIT();

        const __half* As = smh + s * GA_ST;
        const __half* Bs = smh + GB_BASE + (size_t)s * GB_ST;
#pragma unroll
        for (int kk = 0; kk < 2; kk++) {
            const int k16 = kk * 16;
            uint32_t a[2][4];
#pragma unroll
            for (int i = 0; i < 2; i++)
                ldsm_x4(a[i][0], a[i][1], a[i][2], a[i][3],
                        smem_u32(As + (a_row + i * 16) * 40 + k16 + a_col));
            uint32_t b[4][4];
#pragma unroll
            for (int jb = 0; jb < 4; jb++)
                ldsm_x4(b[jb][0], b[jb][1], b[jb][2], b[jb][3],
                        smem_u32(Bs + (b_row + jb * 16) * 40 + k16 + b_col));
#pragma unroll
            for (int i = 0; i < 2; i++)
#pragma unroll
                for (int jn = 0; jn < 8; jn++) {
                    const int jb = jn >> 1, hf = (jn & 1) * 2;
                    mma_f16(acc[i][jn], a[i][0], a[i][1], a[i][2], a[i][3],
                            b[jb][hf], b[jb][hf + 1]);
                }
        }
    }

    if (mode == 0) {
        if ((blockIdx.x & 1) == 0) {
            __half* Hd = (blockIdx.x == 0) ? h0p : h1p;
#pragma unroll
            for (int i = 0; i < 2; i++) {
                const int r0 = m0 + wm * 32 + i * 16 + (lane >> 2);
#pragma unroll
                for (int jn = 0; jn < 8; jn++) {
                    const int c0 = wn * 64 + jn * 8 + (lane & 3) * 2;
                    *(__half2*)(Hd + (size_t)r0 * 256 + c0) =
                        __floats2half2_rn(acc[i][jn][0], acc[i][jn][1]);
                    *(__half2*)(Hd + (size_t)(r0 + 8) * 256 + c0) =
                        __floats2half2_rn(acc[i][jn][2], acc[i][jn][3]);
                }
            }
        } else {
            float* Fd = (blockIdx.x == 1) ? f0 : f1;
#pragma unroll
            for (int i = 0; i < 2; i++) {
                const int r0 = m0 + wm * 32 + i * 16 + (lane >> 2);
#pragma unroll
                for (int jn = 0; jn < 8; jn++) {
                    const int c0 = wn * 64 + jn * 8 + (lane & 3) * 2;
                    *(float2*)(Fd + (size_t)r0 * 256 + c0) =
                        make_float2(acc[i][jn][0], acc[i][jn][1]);
                    *(float2*)(Fd + (size_t)(r0 + 8) * 256 + c0) =
                        make_float2(acc[i][jn][2], acc[i][jn][3]);
                }
            }
        }
    } else {
#pragma unroll
        for (int i = 0; i < 2; i++) {
            const int r0 = m0 + wm * 32 + i * 16 + (lane >> 2);
#pragma unroll
            for (int jn = 0; jn < 8; jn++) {
                const int c0 = n0 + wn * 64 + jn * 8 + (lane & 3) * 2;
                float b0 = bias[c0], b1 = bias[c0 + 1];
                *(float2*)(f0 + (size_t)r0 * C_ + c0) =
                    make_float2(acc[i][jn][0] + b0, acc[i][jn][1] + b1);
                *(float2*)(f0 + (size_t)(r0 + 8) * C_ + c0) =
                    make_float2(acc[i][jn][2] + b0, acc[i][jn][3] + b1);
            }
        }
    }
}

// ---------------- local window attention via mma (heads 0..3) ------------------
// fp16 inputs; scores K=64; P -> smem (hi/lo) -> AV K'=384
#define QS2 72          // halfs: 64 + 8
#define KS2 72
#define VT2 200         // halfs: 192 + 8
#define PR_STRIDE 408   // halfs: 384 + 24
#define OFF_QS 0
#define OFF_KS (OFF_QS + 64 * QS2 * 2)        // 9216
#define OFF_VT (OFF_KS + 192 * KS2 * 2)       // 36864
#define OFF_PR (OFF_VT + 64 * VT2 * 2)        // 62464
#define OFF_RED (OFF_PR + 64 * PR_STRIDE * 2) // 114688
#define OFF_SUM (OFF_RED + 512)               // 115200
#define LA_SMEM (OFF_SUM + 512)               // 115712

__global__ __launch_bounds__(256, 1) void local_attn_mma(float* __restrict__ attn_out)
{
    extern __shared__ char smla[];
    __half* qs = (__half*)(smla + OFF_QS);
    __half* ks = (__half*)(smla + OFF_KS);
    __half* vt = (__half*)(smla + OFF_VT);
    __half* pr = (__half*)(smla + OFF_PR);
    float* redbuf = (float*)(smla + OFF_RED);
    float* sumbuf = (float*)(smla + OFF_SUM);

    const int w = blockIdx.x;
    const int bh = blockIdx.y;
    const int b = bh >> 2, hh = bh & 3;
    const int t = threadIdx.x;
    const int warp = t >> 5, lane = t & 31;
    const int wm = warp & 3, wn = warp >> 2;
    const size_t rowbase = (size_t)b * N_ + (size_t)w * M_;
    const int col0h = hh * D_;

    // ---- load q (fp16, scale by exact 0.125) ----
    {
        const __half2 sc = __floats2half2_rn(0.125f, 0.125f);
        for (int idx = t; idx < 64 * 8; idx += 256) {
            int r = idx >> 3, c8 = (idx & 7) * 8;
            uint4 v = *(const uint4*)(g_Qh + (rowbase + r) * 256 + col0h + c8);
            __half2* hv = (__half2*)&v;
            hv[0] = __hmul2(hv[0], sc); hv[1] = __hmul2(hv[1], sc);
            hv[2] = __hmul2(hv[2], sc); hv[3] = __hmul2(hv[3], sc);
            *(uint4*)(qs + r * QS2 + c8) = v;
        }
    }
    // ---- load k (= v) fp16: ks [j][d] and vt [d][j] ----
    const int nbase = (w - 1) * M_;
    for (int idx = t; idx < 192 * 8; idx += 256) {
        int j = idx >> 3, c8 = (idx & 7) * 8;
        int n = nbase + j;
        uint4 v = make_uint4(0, 0, 0, 0);
        if (n >= 0 && n < N_)
            v = *(const uint4*)(g_KVh + ((size_t)b * N_ + n) * 256 + col0h + c8);
        *(uint4*)(ks + j * KS2 + c8) = v;
        const __half* hv = (const __half*)&v;
#pragma unroll
        for (int e = 0; e < 8; e++)
            vt[(c8 + e) * VT2 + j] = hv[e];
    }
    __syncthreads();

    // ---- scores: warp tile 16 x 96, K=64 ----
    float c[12][4];
#pragma unroll
    for (int jn = 0; jn < 12; jn++)
#pragma unroll
        for (int e = 0; e < 4; e++) c[jn][e] = 0.f;

    const int a_rw = wm * 16 + (lane & 15);
    const int a_cl = (lane >> 4) << 3;
    const int b_rw = wn * 96 + ((lane >> 4) << 3) + (lane & 7);
    const int b_cl = ((lane >> 3) & 1) << 3;

#pragma unroll
    for (int k16 = 0; k16 < 64; k16 += 16) {
        uint32_t a0, a1, a2, a3;
        ldsm_x4(a0, a1, a2, a3, smem_u32(qs + a_rw * QS2 + k16 + a_cl));
        uint32_t bf[6][4];
#pragma unroll
        for (int jb = 0; jb < 6; jb++)
            ldsm_x4(bf[jb][0], bf[jb][1], bf[jb][2], bf[jb][3],
                    smem_u32(ks + (b_rw + jb * 16) * KS2 + k16 + b_cl));
#pragma unroll
        for (int jn = 0; jn < 12; jn++) {
            const int jb = jn >> 1, hf = (jn & 1) * 2;
            mma_f16(c[jn], a0, a1, a2, a3, bf[jb][hf], bf[jb][hf + 1]);
        }
    }

    // ---- mask ----
    const bool leftInv = (w == 0), rightInv = (w == NW - 1);
    if (leftInv || rightInv) {
#pragma unroll
        for (int jn = 0; jn < 12; jn++) {
            const int cb = wn * 96 + jn * 8 + (lane & 3) * 2;
#pragma unroll
            for (int e = 0; e < 4; e++) {
                const int jj = cb + (e & 1);
                if ((jj < 64 && leftInv) || (jj >= 128 && rightInv))
                    c[jn][e] = NEG_INF_F;
            }
        }
    }

    // ---- softmax (rows grA, grA+8) ----
    const int grA = wm * 16 + (lane >> 2);
    float mA = -1e30f, mB = -1e30f;
#pragma unroll
    for (int jn = 0; jn < 12; jn++) {
        mA = fmaxf(mA, fmaxf(c[jn][0], c[jn][1]));
        mB = fmaxf(mB, fmaxf(c[jn][2], c[jn][3]));
    }
    mA = fmaxf(mA, __shfl_xor_sync(0xffffffffu, mA, 1));
    mA = fmaxf(mA, __shfl_xor_sync(0xffffffffu, mA, 2));
    mB = fmaxf(mB, __shfl_xor_sync(0xffffffffu, mB, 1));
    mB = fmaxf(mB, __shfl_xor_sync(0xffffffffu, mB, 2));
    if ((lane & 3) == 0) {
        redbuf[wn * 64 + grA] = mA;
        redbuf[wn * 64 + grA + 8] = mB;
    }
    __syncthreads();
    mA = fmaxf(redbuf[grA], redbuf[64 + grA]);
    mB = fmaxf(redbuf[grA + 8], redbuf[64 + grA + 8]);

    float sA = 0.f, sB = 0.f;
#pragma unroll
    for (int jn = 0; jn < 12; jn++) {
        c[jn][0] = __expf(c[jn][0] - mA); sA += c[jn][0];
        c[jn][1] = __expf(c[jn][1] - mA); sA += c[jn][1];
        c[jn][2] = __expf(c[jn][2] - mB); sB += c[jn][2];
        c[jn][3] = __expf(c[jn][3] - mB); sB += c[jn][3];
    }
    sA += __shfl_xor_sync(0xffffffffu, sA, 1);
    sA += __shfl_xor_sync(0xffffffffu, sA, 2);
    sB += __shfl_xor_sync(0xffffffffu, sB, 1);
    sB += __shfl_xor_sync(0xffffffffu, sB, 2);
    if ((lane & 3) == 0) {
        sumbuf[wn * 64 + grA] = sA;
        sumbuf[wn * 64 + grA + 8] = sB;
    }
    __syncthreads();
    const float invA = 1.f / (sumbuf[grA] + sumbuf[64 + grA]);
    const float invB = 1.f / (sumbuf[grA + 8] + sumbuf[64 + grA + 8]);

    // ---- write probs fp16 hi/lo to smem ----
#pragma unroll
    for (int jn = 0; jn < 12; jn++) {
        const int cb = wn * 96 + jn * 8 + (lane & 3) * 2;
        float p0 = c[jn][0] * invA, p1 = c[jn][1] * invA;
        float p2 = c[jn][2] * invB, p3 = c[jn][3] * invB;
        __half h0 = __float2half_rn(p0), h1 = __float2half_rn(p1);
        __half h2 = __float2half_rn(p2), h3 = __float2half_rn(p3);
        __half2 hiA; hiA.x = h0; hiA.y = h1;
        __half2 hiB; hiB.x = h2; hiB.y = h3;
        __half2 loA = __floats2half2_rn(p0 - __half2float(h0),
                                        p1 - __half2float(h1));
        __half2 loB = __floats2half2_rn(p2 - __half2float(h2),
                                        p3 - __half2float(h3));
        __half* pA = pr + grA * PR_STRIDE + cb;
        __half* pB = pr + (grA + 8) * PR_STRIDE + cb;
        *(__half2*)(pA + 0) = hiA;   *(__half2*)(pA + 192) = loA;
        *(__half2*)(pB + 0) = hiB;   *(__half2*)(pB + 192) = loB;
    }
    __syncthreads();

    // ---- AV: warp tile 16 x 32, k' = 384 ----
    float o[4][4];
#pragma unroll
    for (int jn = 0; jn < 4; jn++)
#pragma unroll
        for (int e = 0; e < 4; e++) o[jn][e] = 0.f;

    const int av_brw = wn * 32 + ((lane >> 4) << 3) + (lane & 7);
#pragma unroll
    for (int k16 = 0; k16 < 384; k16 += 16) {
        uint32_t a0, a1, a2, a3;
        ldsm_x4(a0, a1, a2, a3, smem_u32(pr + a_rw * PR_STRIDE + k16 + a_cl));
        const int jcol = (k16 % 192) + b_cl;
        uint32_t bf[2][4];
#pragma unroll
        for (int jb = 0; jb < 2; jb++)
            ldsm_x4(bf[jb][0], bf[jb][1], bf[jb][2], bf[jb][3],
                    smem_u32(vt + (av_brw + jb * 16) * VT2 + jcol));
#pragma unroll
        for (int jn = 0; jn < 4; jn++) {
            const int jb = jn >> 1, hf = (jn & 1) * 2;
            mma_f16(o[jn], a0, a1, a2, a3, bf[jb][hf], bf[jb][hf + 1]);
        }
    }

    // ---- epilogue ----
#pragma unroll
    for (int jn = 0; jn < 4; jn++) {
        const int cb = wn * 32 + jn * 8 + (lane & 3) * 2;
#pragma unroll
        for (int half = 0; half < 2; half++) {
            const int row = grA + half * 8;
            const int n = w * M_ + row;
            const float v0 = o[jn][half * 2], v1 = o[jn][half * 2 + 1];
            float* ad = attn_out + ((size_t)(b * H_ + hh) * N_ + n) * D_ + cb;
            ad[0] = v0; ad[1] = v1;
            *(__half2*)(g_attnH + ((size_t)b * N_ + n) * C_ + hh * D_ + cb) =
                __floats2half2_rn(v0, v1);
        }
    }
}

// ---------------- linear attention (heads 4..7) -------------------------------
#define CT_SMEM (256 * 64 * 4)
__global__ __launch_bounds__(256) void ctx_kernel()
{
    extern __shared__ float tile[];
    const int bh = blockIdx.y;
    const int b = bh >> 2, hh = 4 + (bh & 3);
    const int n0 = blockIdx.x * 256;
    const int t = threadIdx.x;

    const float* src = g_KVf + ((size_t)b * N_ + n0) * 256 + (hh - 4) * D_;
    for (int idx = t; idx < 256 * 16; idx += 256) {
        int r = idx >> 4, c4 = (idx & 15) * 4;
        float4 v = *(const float4*)(src + (size_t)r * 256 + c4);
        float* dst = tile + r * 64 + c4;
        dst[0] = v.x; dst[1] = v.y; dst[2] = v.z; dst[3] = v.w;
    }
    __syncthreads();

    const int d = t >> 2, q = t & 3;
    float4 acc[4];
#pragma unroll
    for (int i = 0; i < 4; i++) acc[i] = make_float4(0.f, 0.f, 0.f, 0.f);
    float ssum = 0.f;

    for (int n = 0; n < 256; n++) {
        float ek = __expf(tile[n * 64 + d]);
        ssum += ek;
        const float4* vr = (const float4*)(tile + n * 64 + q * 16);
#pragma unroll
        for (int e4 = 0; e4 < 4; e4++) {
            float4 v = vr[e4];
            acc[e4].x = fmaf(ek, v.x, acc[e4].x);
            acc[e4].y = fmaf(ek, v.y, acc[e4].y);
            acc[e4].z = fmaf(ek, v.z, acc[e4].z);
            acc[e4].w = fmaf(ek, v.w, acc[e4].w);
        }
    }
    float* dst = g_ctx + bh * 4096 + d * 64 + q * 16;
#pragma unroll
    for (int e4 = 0; e4 < 4; e4++) {
        atomicAdd(dst + e4 * 4 + 0, acc[e4].x);
        atomicAdd(dst + e4 * 4 + 1, acc[e4].y);
        atomicAdd(dst + e4 * 4 + 2, acc[e4].z);
        atomicAdd(dst + e4 * 4 + 3, acc[e4].w);
    }
    if (q == 0) atomicAdd(&g_csum[bh * 64 + d], ssum);
}

__global__ __launch_bounds__(256) void lin_out_kernel(float* __restrict__ attn_out)
{
    __shared__ float ctx_s[4096];
    __shared__ float cinv_s[64];
    const int bh = blockIdx.y;
    const int b = bh >> 2, hh = 4 + (bh & 3);
    const int t = threadIdx.x;

    if (t < 64) cinv_s[t] = 1.f / g_csum[bh * 64 + t];
    for (int i = t; i < 4096; i += 256) ctx_s[i] = g_ctx[bh * 4096 + i];
    __syncthreads();

    const int warp = t >> 5, lane = t & 31;
    for (int r = warp; r < 64; r += 8) {
        const int n = blockIdx.x * 64 + r;
        const float* qrow = g_Qf + ((size_t)b * N_ + n) * 256 + (hh - 4) * D_;
        float q0 = qrow[lane], q1 = qrow[lane + 32];
        float m = fmaxf(q0, q1);
#pragma unroll
        for (int o = 16; o; o >>= 1) m = fmaxf(m, __shfl_xor_sync(0xffffffffu, m, o));
        float e0 = __expf(q0 - m), e1 = __expf(q1 - m);
        float s = e0 + e1;
#pragma unroll
        for (int o = 16; o; o >>= 1) s += __shfl_xor_sync(0xffffffffu, s, o);
        float inv = 0.125f / s;
        e0 *= inv * cinv_s[lane];
        e1 *= inv * cinv_s[lane + 32];

        float a0 = 0.f, a1 = 0.f;
#pragma unroll
        for (int dd = 0; dd < 64; dd++) {
            float sq = __shfl_sync(0xffffffffu, (dd < 32) ? e0 : e1, dd & 31);
            a0 = fmaf(sq, ctx_s[dd * 64 + lane], a0);
            a1 = fmaf(sq, ctx_s[dd * 64 + lane + 32], a1);
        }
        size_t o1 = ((size_t)(b * H_ + hh) * N_ + n) * D_;
        attn_out[o1 + lane] = a0;
        attn_out[o1 + lane + 32] = a1;

        __half* hdst = g_attnH + ((size_t)b * N_ + n) * C_ + hh * D_;
        hdst[lane] = __float2half_rn(a0);
        hdst[lane + 32] = __float2half_rn(a1);
    }
}

// ---------------------------------- launch ------------------------------------
extern "C" void kernel_launch(void* const* d_in, const int* in_sizes, int n_in,
                              void* d_out, int out_size)
{
    (void)in_sizes; (void)n_in; (void)out_size;
    const float* x     = (const float*)d_in[0];
    const float* Wq    = (const float*)d_in[1];
    const float* Wkv   = (const float*)d_in[2];
    const float* Wproj = (const float*)d_in[3];
    const float* bproj = (const float*)d_in[4];

    float* y    = (float*)d_out;
    float* attn = y + (size_t)ROWS * C_;

    float *pQf, *pKVf;
    __half *pxh, *paH, *pW16, *pWp16, *pQh, *pKVh;
    cudaGetSymbolAddress((void**)&pQf, g_Qf);
    cudaGetSymbolAddress((void**)&pKVf, g_KVf);
    cudaGetSymbolAddress((void**)&pQh, g_Qh);
    cudaGetSymbolAddress((void**)&pKVh, g_KVh);
    cudaGetSymbolAddress((void**)&pxh, g_xh);
    cudaGetSymbolAddress((void**)&paH, g_attnH);
    cudaGetSymbolAddress((void**)&pW16, g_W16);
    cudaGetSymbolAddress((void**)&pWp16, g_Wp16);

    cudaFuncSetAttribute(gemm_f16,
                         cudaFuncAttributeMaxDynamicSharedMemorySize, GEMM_SMEM);
    cudaFuncSetAttribute(local_attn_mma,
                         cudaFuncAttributeMaxDynamicSharedMemorySize, LA_SMEM);
    cudaFuncSetAttribute(ctx_kernel,
                         cudaFuncAttributeMaxDynamicSharedMemorySize, CT_SMEM);

    // conversions + ctx zeroing
    prep_kernel<<<512, 256>>>(Wq, Wkv, Wproj);
    round_h_kernel<<<2048, 256>>>(x, pxh, ROWS);

    // fused Q+KV GEMM: n-tiles -> Qh | Qf | KVh | KVf
    gemm_f16<<<dim3(4, ROWS / 128), 512, GEMM_SMEM>>>(
        pxh, pW16, pQf, pKVf, pQh, pKVh, nullptr, 0);

    local_attn_mma<<<dim3(NW, 16), 256, LA_SMEM>>>(attn);

    ctx_kernel<<<dim3(32, 16), 256, CT_SMEM>>>();
    lin_out_kernel<<<dim3(128, 16), 256>>>(attn);

    // proj GEMM: y = attnH @ Wp16^T + bias
    gemm_f16<<<dim3(2, ROWS / 128), 512, GEMM_SMEM>>>(
        paH, pWp16, y, nullptr, nullptr, nullptr, bproj, 1);
}

// round 12
// speedup vs baseline: 2.5498x; 1.0498x over previous
#include <cuda_runtime.h>
#include <cuda_bf16.h>
#include <cuda_fp16.h>
#include <math.h>
#include <stdint.h>

#define B_    4
#define N_    8192
#define C_    512
#define H_    8
#define D_    64
#define M_    64           // window
#define NW    (N_ / M_)    // 128
#define ROWS  (B_ * N_)    // 32768
#define NEG_INF_F (-1000000000.0f)

// ---------------- scratch (static device globals: allocation-free) ------------
__device__ __align__(16) __half g_xh[(size_t)ROWS * C_];     // fp16 x
__device__ __align__(16) __half g_attnH[(size_t)ROWS * C_];  // fp16 attn (B,N,C)
__device__ __align__(16) __half g_W16[1024 * C_];            // fp16 Wq | Wkv
__device__ __align__(16) __half g_Wp16[C_ * C_];             // fp16 Wproj
__device__ __align__(16) __half g_Qh[(size_t)ROWS * 256];    // fp16 q, local heads
__device__ __align__(16) __half g_KVh[(size_t)ROWS * 256];   // fp16 kv, local heads
__device__ float g_Qf[(size_t)ROWS * 256];                   // fp32 q, linear heads
__device__ float g_KVf[(size_t)ROWS * 256];                  // fp32 kv, linear heads
__device__ float g_ctx[16 * 64 * 64];
__device__ float g_csum[16 * 64];

// ---------------- helpers -----------------------------------------------------
__device__ __forceinline__ uint32_t smem_u32(const void* p) {
    uint32_t a;
    asm("{ .reg .u64 t; cvta.to.shared.u64 t, %1; cvt.u32.u64 %0, t; }"
        : "=r"(a) : "l"(p));
    return a;
}
#define CP_ASYNC16(dst, src) \
    asm volatile("cp.async.cg.shared.global [%0], [%1], 16;" \
                 :: "r"(dst), "l"(src))
#define CP_COMMIT() asm volatile("cp.async.commit_group;" ::: "memory")
#define CP_WAIT2()  asm volatile("cp.async.wait_group 2;" ::: "memory")

__device__ __forceinline__ void ldsm_x4(uint32_t& r0, uint32_t& r1,
                                        uint32_t& r2, uint32_t& r3, uint32_t addr) {
    asm volatile("ldmatrix.sync.aligned.m8n8.x4.shared.b16 {%0,%1,%2,%3}, [%4];"
                 : "=r"(r0), "=r"(r1), "=r"(r2), "=r"(r3) : "r"(addr));
}
__device__ __forceinline__ void mma_f16(float* c, uint32_t a0, uint32_t a1,
                                        uint32_t a2, uint32_t a3,
                                        uint32_t b0, uint32_t b1) {
    asm volatile(
        "mma.sync.aligned.m16n8k16.row.col.f32.f16.f16.f32 "
        "{%0,%1,%2,%3}, {%4,%5,%6,%7}, {%8,%9}, {%0,%1,%2,%3};"
        : "+f"(c[0]), "+f"(c[1]), "+f"(c[2]), "+f"(c[3])
        : "r"(a0), "r"(a1), "r"(a2), "r"(a3), "r"(b0), "r"(b1));
}
__device__ __forceinline__ uint32_t pack_h2(float lo, float hi) {
    __half2 h = __floats2half2_rn(lo, hi);
    return *reinterpret_cast<uint32_t*>(&h);
}

// ---------------- conversions --------------------------------------------------
__global__ __launch_bounds__(256) void round_h_kernel(
    const float* __restrict__ src, __half* __restrict__ dst, int nrows)
{
    int total = nrows * (C_ / 4);
    for (int i = blockIdx.x * blockDim.x + threadIdx.x; i < total;
         i += gridDim.x * blockDim.x) {
        int r = i >> 7;
        int c = (i & 127) * 4;
        float4 v = *(const float4*)(src + (size_t)r * C_ + c);
        __half* base = dst + (size_t)r * C_ + c;
        *(__half2*)(base + 0) = __floats2half2_rn(v.x, v.y);
        *(__half2*)(base + 2) = __floats2half2_rn(v.z, v.w);
    }
}

// weights (3 matrices, 512x512 each = 65536 quads) + ctx/csum zeroing
__global__ __launch_bounds__(256) void prep_kernel(
    const float* __restrict__ Wq, const float* __restrict__ Wkv,
    const float* __restrict__ Wproj)
{
    const int wtotal = 3 * 65536;
    const int total = wtotal + 16 * 4096 + 16 * 64;
    for (int i = blockIdx.x * blockDim.x + threadIdx.x; i < total;
         i += gridDim.x * blockDim.x) {
        if (i < wtotal) {
            int mat = i >> 16, wi = i & 65535;
            int r = wi >> 7, c = (wi & 127) * 4;
            const float* src = (mat == 0) ? Wq : (mat == 1) ? Wkv : Wproj;
            __half* dst = (mat == 0) ? g_W16
                        : (mat == 1) ? (g_W16 + (size_t)512 * C_) : g_Wp16;
            float4 v = *(const float4*)(src + (size_t)r * C_ + c);
            __half* base = dst + (size_t)r * C_ + c;
            *(__half2*)(base + 0) = __floats2half2_rn(v.x, v.y);
            *(__half2*)(base + 2) = __floats2half2_rn(v.z, v.w);
        } else if (i < wtotal + 65536) {
            g_ctx[i - wtotal] = 0.f;
        } else {
            g_csum[i - wtotal - 65536] = 0.f;
        }
    }
}

// ---------------- fp16 mma GEMM, K=512, 128x256 tile --------------------------
#define GST     4
#define GA_ST   (128 * 40)
#define GB_ST   (256 * 40)
#define GB_BASE (GST * GA_ST)
#define GEMM_SMEM ((GB_BASE + GST * GB_ST) * 2)
#define KITS    (C_ / 32)             // 16

__global__ __launch_bounds__(512, 1) void gemm_f16(
    const __half* __restrict__ Ah, const __half* __restrict__ Bh,
    float* __restrict__ f0, float* __restrict__ f1,
    __half* __restrict__ h0p, __half* __restrict__ h1p,
    const float* __restrict__ bias, int mode)
{
    extern __shared__ __half smh[];
    const int tid = threadIdx.x;
    const int warp = tid >> 5, lane = tid & 31;
    const int wm = warp & 3, wn = warp >> 2;
    const int m0 = blockIdx.y * 128;
    const int n0 = blockIdx.x * 256;

    float acc[2][8][4];
#pragma unroll
    for (int i = 0; i < 2; i++)
#pragma unroll
        for (int j = 0; j < 8; j++)
#pragma unroll
            for (int e = 0; e < 4; e++) acc[i][j][e] = 0.f;

    const __half* Ab = Ah + (size_t)m0 * C_;
    const __half* Bb = Bh + (size_t)n0 * C_;

    const int lrow = tid >> 2;
    const int lchk = (tid & 3) * 8;

#define LOADQ(s, j) do { \
    const int ko = (j) * 32; \
    CP_ASYNC16(smem_u32(smh + (s) * GA_ST + lrow * 40 + lchk), \
               Ab + (size_t)lrow * C_ + ko + lchk); \
    CP_ASYNC16(smem_u32(smh + GB_BASE + (size_t)(s) * GB_ST + lrow * 40 + lchk), \
               Bb + (size_t)lrow * C_ + ko + lchk); \
    CP_ASYNC16(smem_u32(smh + GB_BASE + (size_t)(s) * GB_ST + (lrow + 128) * 40 + lchk), \
               Bb + (size_t)(lrow + 128) * C_ + ko + lchk); \
} while (0)

    LOADQ(0, 0); CP_COMMIT();
    LOADQ(1, 1); CP_COMMIT();
    LOADQ(2, 2); CP_COMMIT();

    const int a_row = wm * 32 + (lane & 15);
    const int a_col = (lane >> 4) << 3;
    const int b_row = wn * 64 + ((lane >> 4) << 3) + (lane & 7);
    const int b_col = ((lane >> 3) & 1) << 3;

    for (int j = 0; j < KITS; ++j) {
        const int s = j & 3;
        CP_WAIT2();
        __syncthreads();
        if (j + 3 < KITS) LOADQ((j + 3) & 3, j + 3);
        CP_COMMIT();

        const __half* As = smh + s * GA_ST;
        const __half* Bs = smh + GB_BASE + (size_t)s * GB_ST;
#pragma unroll
        for (int kk = 0; kk < 2; kk++) {
            const int k16 = kk * 16;
            uint32_t a[2][4];
#pragma unroll
            for (int i = 0; i < 2; i++)
                ldsm_x4(a[i][0], a[i][1], a[i][2], a[i][3],
                        smem_u32(As + (a_row + i * 16) * 40 + k16 + a_col));
            uint32_t b[4][4];
#pragma unroll
            for (int jb = 0; jb < 4; jb++)
                ldsm_x4(b[jb][0], b[jb][1], b[jb][2], b[jb][3],
                        smem_u32(Bs + (b_row + jb * 16) * 40 + k16 + b_col));
#pragma unroll
            for (int i = 0; i < 2; i++)
#pragma unroll
                for (int jn = 0; jn < 8; jn++) {
                    const int jb = jn >> 1, hf = (jn & 1) * 2;
                    mma_f16(acc[i][jn], a[i][0], a[i][1], a[i][2], a[i][3],
                            b[jb][hf], b[jb][hf + 1]);
                }
        }
    }

    if (mode == 0) {
        if ((blockIdx.x & 1) == 0) {
            __half* Hd = (blockIdx.x == 0) ? h0p : h1p;
#pragma unroll
            for (int i = 0; i < 2; i++) {
                const int r0 = m0 + wm * 32 + i * 16 + (lane >> 2);
#pragma unroll
                for (int jn = 0; jn < 8; jn++) {
                    const int c0 = wn * 64 + jn * 8 + (lane & 3) * 2;
                    *(__half2*)(Hd + (size_t)r0 * 256 + c0) =
                        __floats2half2_rn(acc[i][jn][0], acc[i][jn][1]);
                    *(__half2*)(Hd + (size_t)(r0 + 8) * 256 + c0) =
                        __floats2half2_rn(acc[i][jn][2], acc[i][jn][3]);
                }
            }
        } else {
            float* Fd = (blockIdx.x == 1) ? f0 : f1;
#pragma unroll
            for (int i = 0; i < 2; i++) {
                const int r0 = m0 + wm * 32 + i * 16 + (lane >> 2);
#pragma unroll
                for (int jn = 0; jn < 8; jn++) {
                    const int c0 = wn * 64 + jn * 8 + (lane & 3) * 2;
                    *(float2*)(Fd + (size_t)r0 * 256 + c0) =
                        make_float2(acc[i][jn][0], acc[i][jn][1]);
                    *(float2*)(Fd + (size_t)(r0 + 8) * 256 + c0) =
                        make_float2(acc[i][jn][2], acc[i][jn][3]);
                }
            }
        }
    } else {
#pragma unroll
        for (int i = 0; i < 2; i++) {
            const int r0 = m0 + wm * 32 + i * 16 + (lane >> 2);
#pragma unroll
            for (int jn = 0; jn < 8; jn++) {
                const int c0 = n0 + wn * 64 + jn * 8 + (lane & 3) * 2;
                float b0 = bias[c0], b1 = bias[c0 + 1];
                *(float2*)(f0 + (size_t)r0 * C_ + c0) =
                    make_float2(acc[i][jn][0] + b0, acc[i][jn][1] + b1);
                *(float2*)(f0 + (size_t)(r0 + 8) * C_ + c0) =
                    make_float2(acc[i][jn][2] + b0, acc[i][jn][3] + b1);
            }
        }
    }
}

// ---------------- local window attention via mma (heads 0..3) ------------------
// fp16 inputs; scores K=64; P kept in registers (hi/lo packed A-fragments);
// AV per warp over its 96 k-cols in two e-halves; cross-wn reduce via oacc.
#define QS2 72          // halfs: 64 + 8
#define KS2 72
#define VT2 200         // halfs: 192 + 8
#define OA2 36          // floats: 32 + 4
#define OFF_QS 0
#define OFF_KS (OFF_QS + 64 * QS2 * 2)        // 9216
#define OFF_VT (OFF_KS + 192 * KS2 * 2)       // 36864
#define OFF_OA (OFF_VT + 64 * VT2 * 2)        // 62464
#define OFF_RED (OFF_OA + 64 * OA2 * 4)       // 71680
#define OFF_SUM (OFF_RED + 512)               // 72192
#define LA_SMEM (OFF_SUM + 512)               // 72704

__global__ __launch_bounds__(256, 2) void local_attn_mma(float* __restrict__ attn_out)
{
    extern __shared__ char smla[];
    __half* qs = (__half*)(smla + OFF_QS);
    __half* ks = (__half*)(smla + OFF_KS);
    __half* vt = (__half*)(smla + OFF_VT);
    float* oacc = (float*)(smla + OFF_OA);
    float* redbuf = (float*)(smla + OFF_RED);
    float* sumbuf = (float*)(smla + OFF_SUM);

    const int w = blockIdx.x;
    const int bh = blockIdx.y;
    const int b = bh >> 2, hh = bh & 3;
    const int t = threadIdx.x;
    const int warp = t >> 5, lane = t & 31;
    const int wm = warp & 3, wn = warp >> 2;
    const size_t rowbase = (size_t)b * N_ + (size_t)w * M_;
    const int col0h = hh * D_;

    // ---- load q (fp16, scale by exact 0.125) ----
    {
        const __half2 sc = __floats2half2_rn(0.125f, 0.125f);
        for (int idx = t; idx < 64 * 8; idx += 256) {
            int r = idx >> 3, c8 = (idx & 7) * 8;
            uint4 v = *(const uint4*)(g_Qh + (rowbase + r) * 256 + col0h + c8);
            __half2* hv = (__half2*)&v;
            hv[0] = __hmul2(hv[0], sc); hv[1] = __hmul2(hv[1], sc);
            hv[2] = __hmul2(hv[2], sc); hv[3] = __hmul2(hv[3], sc);
            *(uint4*)(qs + r * QS2 + c8) = v;
        }
    }
    // ---- load k (= v) fp16: ks [j][d] and vt [d][j] ----
    const int nbase = (w - 1) * M_;
    for (int idx = t; idx < 192 * 8; idx += 256) {
        int j = idx >> 3, c8 = (idx & 7) * 8;
        int n = nbase + j;
        uint4 v = make_uint4(0, 0, 0, 0);
        if (n >= 0 && n < N_)
            v = *(const uint4*)(g_KVh + ((size_t)b * N_ + n) * 256 + col0h + c8);
        *(uint4*)(ks + j * KS2 + c8) = v;
        const __half* hv = (const __half*)&v;
#pragma unroll
        for (int e = 0; e < 8; e++)
            vt[(c8 + e) * VT2 + j] = hv[e];
    }
    __syncthreads();

    // ---- scores: warp tile 16 x 96, K=64 ----
    float c[12][4];
#pragma unroll
    for (int jn = 0; jn < 12; jn++)
#pragma unroll
        for (int e = 0; e < 4; e++) c[jn][e] = 0.f;

    const int a_rw = wm * 16 + (lane & 15);
    const int a_cl = (lane >> 4) << 3;
    const int b_rw = wn * 96 + ((lane >> 4) << 3) + (lane & 7);
    const int b_cl = ((lane >> 3) & 1) << 3;

#pragma unroll
    for (int k16 = 0; k16 < 64; k16 += 16) {
        uint32_t a0, a1, a2, a3;
        ldsm_x4(a0, a1, a2, a3, smem_u32(qs + a_rw * QS2 + k16 + a_cl));
        uint32_t bf[6][4];
#pragma unroll
        for (int jb = 0; jb < 6; jb++)
            ldsm_x4(bf[jb][0], bf[jb][1], bf[jb][2], bf[jb][3],
                    smem_u32(ks + (b_rw + jb * 16) * KS2 + k16 + b_cl));
#pragma unroll
        for (int jn = 0; jn < 12; jn++) {
            const int jb = jn >> 1, hf = (jn & 1) * 2;
            mma_f16(c[jn], a0, a1, a2, a3, bf[jb][hf], bf[jb][hf + 1]);
        }
    }

    // ---- mask ----
    const bool leftInv = (w == 0), rightInv = (w == NW - 1);
    if (leftInv || rightInv) {
#pragma unroll
        for (int jn = 0; jn < 12; jn++) {
            const int cb = wn * 96 + jn * 8 + (lane & 3) * 2;
#pragma unroll
            for (int e = 0; e < 4; e++) {
                const int jj = cb + (e & 1);
                if ((jj < 64 && leftInv) || (jj >= 128 && rightInv))
                    c[jn][e] = NEG_INF_F;
            }
        }
    }

    // ---- softmax (rows grA, grA+8) ----
    const int grA = wm * 16 + (lane >> 2);
    float mA = -1e30f, mB = -1e30f;
#pragma unroll
    for (int jn = 0; jn < 12; jn++) {
        mA = fmaxf(mA, fmaxf(c[jn][0], c[jn][1]));
        mB = fmaxf(mB, fmaxf(c[jn][2], c[jn][3]));
    }
    mA = fmaxf(mA, __shfl_xor_sync(0xffffffffu, mA, 1));
    mA = fmaxf(mA, __shfl_xor_sync(0xffffffffu, mA, 2));
    mB = fmaxf(mB, __shfl_xor_sync(0xffffffffu, mB, 1));
    mB = fmaxf(mB, __shfl_xor_sync(0xffffffffu, mB, 2));
    if ((lane & 3) == 0) {
        redbuf[wn * 64 + grA] = mA;
        redbuf[wn * 64 + grA + 8] = mB;
    }
    __syncthreads();
    mA = fmaxf(redbuf[grA], redbuf[64 + grA]);
    mB = fmaxf(redbuf[grA + 8], redbuf[64 + grA + 8]);

    float sA = 0.f, sB = 0.f;
#pragma unroll
    for (int jn = 0; jn < 12; jn++) {
        c[jn][0] = __expf(c[jn][0] - mA); sA += c[jn][0];
        c[jn][1] = __expf(c[jn][1] - mA); sA += c[jn][1];
        c[jn][2] = __expf(c[jn][2] - mB); sB += c[jn][2];
        c[jn][3] = __expf(c[jn][3] - mB); sB += c[jn][3];
    }
    sA += __shfl_xor_sync(0xffffffffu, sA, 1);
    sA += __shfl_xor_sync(0xffffffffu, sA, 2);
    sB += __shfl_xor_sync(0xffffffffu, sB, 1);
    sB += __shfl_xor_sync(0xffffffffu, sB, 2);
    if ((lane & 3) == 0) {
        sumbuf[wn * 64 + grA] = sA;
        sumbuf[wn * 64 + grA + 8] = sB;
    }
    __syncthreads();
    const float invA = 1.f / (sumbuf[grA] + sumbuf[64 + grA]);
    const float invB = 1.f / (sumbuf[grA + 8] + sumbuf[64 + grA + 8]);

    // ---- convert score fragments -> packed hi/lo A-fragments in registers ----
    // A-frag for AV k16-block kk: a0 = P[g][2t,2t+1] of jn=2kk, a1 = rows g+8
    // of jn=2kk, a2/a3 same for jn=2kk+1.
    uint32_t ah[6][4], al[6][4];
#pragma unroll
    for (int kk = 0; kk < 6; kk++) {
        const int jn0 = 2 * kk, jn1 = 2 * kk + 1;
        float p00 = c[jn0][0] * invA, p01 = c[jn0][1] * invA;
        float p02 = c[jn0][2] * invB, p03 = c[jn0][3] * invB;
        float p10 = c[jn1][0] * invA, p11 = c[jn1][1] * invA;
        float p12 = c[jn1][2] * invB, p13 = c[jn1][3] * invB;
        ah[kk][0] = pack_h2(p00, p01);
        ah[kk][1] = pack_h2(p02, p03);
        ah[kk][2] = pack_h2(p10, p11);
        ah[kk][3] = pack_h2(p12, p13);
        __half2 h0 = *reinterpret_cast<__half2*>(&ah[kk][0]);
        __half2 h1 = *reinterpret_cast<__half2*>(&ah[kk][1]);
        __half2 h2 = *reinterpret_cast<__half2*>(&ah[kk][2]);
        __half2 h3 = *reinterpret_cast<__half2*>(&ah[kk][3]);
        al[kk][0] = pack_h2(p00 - __low2float(h0), p01 - __high2float(h0));
        al[kk][1] = pack_h2(p02 - __low2float(h1), p03 - __high2float(h1));
        al[kk][2] = pack_h2(p10 - __low2float(h2), p11 - __high2float(h2));
        al[kk][3] = pack_h2(p12 - __low2float(h3), p13 - __high2float(h3));
    }

    // ---- AV in two e-halves: o[4][4], warp covers its own 96 k-cols ----
    const int ldrow = ((lane >> 4) << 3) + (lane & 7);
#pragma unroll
    for (int eh = 0; eh < 2; eh++) {
        float o[4][4];
#pragma unroll
        for (int jn = 0; jn < 4; jn++)
#pragma unroll
            for (int e = 0; e < 4; e++) o[jn][e] = 0.f;

#pragma unroll
        for (int kk = 0; kk < 6; kk++) {
            const int jcol = wn * 96 + kk * 16;
            uint32_t bf[2][4];
#pragma unroll
            for (int jb = 0; jb < 2; jb++)
                ldsm_x4(bf[jb][0], bf[jb][1], bf[jb][2], bf[jb][3],
                        smem_u32(vt + (eh * 32 + jb * 16 + ldrow) * VT2
                                 + jcol + b_cl));
#pragma unroll
            for (int jn = 0; jn < 4; jn++) {
                const int jb = jn >> 1, hf = (jn & 1) * 2;
                mma_f16(o[jn], ah[kk][0], ah[kk][1], ah[kk][2], ah[kk][3],
                        bf[jb][hf], bf[jb][hf + 1]);
                mma_f16(o[jn], al[kk][0], al[kk][1], al[kk][2], al[kk][3],
                        bf[jb][hf], bf[jb][hf + 1]);
            }
        }

        // cross-wn reduction via oacc (32 e-cols)
        if (wn == 0) {
#pragma unroll
            for (int jn = 0; jn < 4; jn++) {
                const int cb = jn * 8 + (lane & 3) * 2;
                oacc[grA * OA2 + cb] = o[jn][0];
                oacc[grA * OA2 + cb + 1] = o[jn][1];
                oacc[(grA + 8) * OA2 + cb] = o[jn][2];
                oacc[(grA + 8) * OA2 + cb + 1] = o[jn][3];
            }
        }
        __syncthreads();
        if (wn == 1) {
#pragma unroll
            for (int jn = 0; jn < 4; jn++) {
                const int cb = jn * 8 + (lane & 3) * 2;
#pragma unroll
                for (int half = 0; half < 2; half++) {
                    const int row = grA + half * 8;
                    const int n = w * M_ + row;
                    const int ecol = eh * 32 + cb;
                    const float v0 = o[jn][half * 2] + oacc[row * OA2 + cb];
                    const float v1 = o[jn][half * 2 + 1] + oacc[row * OA2 + cb + 1];
                    float* ad = attn_out +
                        ((size_t)(b * H_ + hh) * N_ + n) * D_ + ecol;
                    ad[0] = v0; ad[1] = v1;
                    *(__half2*)(g_attnH + ((size_t)b * N_ + n) * C_
                                + hh * D_ + ecol) = __floats2half2_rn(v0, v1);
                }
            }
        }
        __syncthreads();
    }
}

// ---------------- linear attention (heads 4..7) -------------------------------
#define CT_SMEM (256 * 64 * 4)
__global__ __launch_bounds__(256) void ctx_kernel()
{
    extern __shared__ float tile[];
    const int bh = blockIdx.y;
    const int b = bh >> 2, hh = 4 + (bh & 3);
    const int n0 = blockIdx.x * 256;
    const int t = threadIdx.x;

    const float* src = g_KVf + ((size_t)b * N_ + n0) * 256 + (hh - 4) * D_;
    for (int idx = t; idx < 256 * 16; idx += 256) {
        int r = idx >> 4, c4 = (idx & 15) * 4;
        float4 v = *(const float4*)(src + (size_t)r * 256 + c4);
        float* dst = tile + r * 64 + c4;
        dst[0] = v.x; dst[1] = v.y; dst[2] = v.z; dst[3] = v.w;
    }
    __syncthreads();

    const int d = t >> 2, q = t & 3;
    float4 acc[4];
#pragma unroll
    for (int i = 0; i < 4; i++) acc[i] = make_float4(0.f, 0.f, 0.f, 0.f);
    float ssum = 0.f;

    for (int n = 0; n < 256; n++) {
        float ek = __expf(tile[n * 64 + d]);
        ssum += ek;
        const float4* vr = (const float4*)(tile + n * 64 + q * 16);
#pragma unroll
        for (int e4 = 0; e4 < 4; e4++) {
            float4 v = vr[e4];
            acc[e4].x = fmaf(ek, v.x, acc[e4].x);
            acc[e4].y = fmaf(ek, v.y, acc[e4].y);
            acc[e4].z = fmaf(ek, v.z, acc[e4].z);
            acc[e4].w = fmaf(ek, v.w, acc[e4].w);
        }
    }
    float* dst = g_ctx + bh * 4096 + d * 64 + q * 16;
#pragma unroll
    for (int e4 = 0; e4 < 4; e4++) {
        atomicAdd(dst + e4 * 4 + 0, acc[e4].x);
        atomicAdd(dst + e4 * 4 + 1, acc[e4].y);
        atomicAdd(dst + e4 * 4 + 2, acc[e4].z);
        atomicAdd(dst + e4 * 4 + 3, acc[e4].w);
    }
    if (q == 0) atomicAdd(&g_csum[bh * 64 + d], ssum);
}

__global__ __launch_bounds__(256) void lin_out_kernel(float* __restrict__ attn_out)
{
    __shared__ float ctx_s[4096];
    __shared__ float cinv_s[64];
    const int bh = blockIdx.y;
    const int b = bh >> 2, hh = 4 + (bh & 3);
    const int t = threadIdx.x;

    if (t < 64) cinv_s[t] = 1.f / g_csum[bh * 64 + t];
    for (int i = t; i < 4096; i += 256) ctx_s[i] = g_ctx[bh * 4096 + i];
    __syncthreads();

    const int warp = t >> 5, lane = t & 31;
    for (int r = warp; r < 64; r += 8) {
        const int n = blockIdx.x * 64 + r;
        const float* qrow = g_Qf + ((size_t)b * N_ + n) * 256 + (hh - 4) * D_;
        float q0 = qrow[lane], q1 = qrow[lane + 32];
        float m = fmaxf(q0, q1);
#pragma unroll
        for (int o = 16; o; o >>= 1) m = fmaxf(m, __shfl_xor_sync(0xffffffffu, m, o));
        float e0 = __expf(q0 - m), e1 = __expf(q1 - m);
        float s = e0 + e1;
#pragma unroll
        for (int o = 16; o; o >>= 1) s += __shfl_xor_sync(0xffffffffu, s, o);
        float inv = 0.125f / s;
        e0 *= inv * cinv_s[lane];
        e1 *= inv * cinv_s[lane + 32];

        float a0 = 0.f, a1 = 0.f;
#pragma unroll
        for (int dd = 0; dd < 64; dd++) {
            float sq = __shfl_sync(0xffffffffu, (dd < 32) ? e0 : e1, dd & 31);
            a0 = fmaf(sq, ctx_s[dd * 64 + lane], a0);
            a1 = fmaf(sq, ctx_s[dd * 64 + lane + 32], a1);
        }
        size_t o1 = ((size_t)(b * H_ + hh) * N_ + n) * D_;
        attn_out[o1 + lane] = a0;
        attn_out[o1 + lane + 32] = a1;

        __half* hdst = g_attnH + ((size_t)b * N_ + n) * C_ + hh * D_;
        hdst[lane] = __float2half_rn(a0);
        hdst[lane + 32] = __float2half_rn(a1);
    }
}

// ---------------------------------- launch ------------------------------------
extern "C" void kernel_launch(void* const* d_in, const int* in_sizes, int n_in,
                              void* d_out, int out_size)
{
    (void)in_sizes; (void)n_in; (void)out_size;
    const float* x     = (const float*)d_in[0];
    const float* Wq    = (const float*)d_in[1];
    const float* Wkv   = (const float*)d_in[2];
    const float* Wproj = (const float*)d_in[3];
    const float* bproj = (const float*)d_in[4];

    float* y    = (float*)d_out;
    float* attn = y + (size_t)ROWS * C_;

    float *pQf, *pKVf;
    __half *pxh, *paH, *pW16, *pWp16, *pQh, *pKVh;
    cudaGetSymbolAddress((void**)&pQf, g_Qf);
    cudaGetSymbolAddress((void**)&pKVf, g_KVf);
    cudaGetSymbolAddress((void**)&pQh, g_Qh);
    cudaGetSymbolAddress((void**)&pKVh, g_KVh);
    cudaGetSymbolAddress((void**)&pxh, g_xh);
    cudaGetSymbolAddress((void**)&paH, g_attnH);
    cudaGetSymbolAddress((void**)&pW16, g_W16);
    cudaGetSymbolAddress((void**)&pWp16, g_Wp16);

    cudaFuncSetAttribute(gemm_f16,
                         cudaFuncAttributeMaxDynamicSharedMemorySize, GEMM_SMEM);
    cudaFuncSetAttribute(local_attn_mma,
                         cudaFuncAttributeMaxDynamicSharedMemorySize, LA_SMEM);
    cudaFuncSetAttribute(ctx_kernel,
                         cudaFuncAttributeMaxDynamicSharedMemorySize, CT_SMEM);

    // conversions + ctx zeroing
    prep_kernel<<<512, 256>>>(Wq, Wkv, Wproj);
    round_h_kernel<<<2048, 256>>>(x, pxh, ROWS);

    // fused Q+KV GEMM: n-tiles -> Qh | Qf | KVh | KVf
    gemm_f16<<<dim3(4, ROWS / 128), 512, GEMM_SMEM>>>(
        pxh, pW16, pQf, pKVf, pQh, pKVh, nullptr, 0);

    local_attn_mma<<<dim3(NW, 16), 256, LA_SMEM>>>(attn);

    ctx_kernel<<<dim3(32, 16), 256, CT_SMEM>>>();
    lin_out_kernel<<<dim3(128, 16), 256>>>(attn);

    // proj GEMM: y = attnH @ Wp16^T + bias
    gemm_f16<<<dim3(2, ROWS / 128), 512, GEMM_SMEM>>>(
        paH, pWp16, y, nullptr, nullptr, nullptr, bproj, 1);
}

// round 13
// speedup vs baseline: 2.6053x; 1.0217x over previous
#include <cuda_runtime.h>
#include <cuda_bf16.h>
#include <cuda_fp16.h>
#include <math.h>
#include <stdint.h>

#define B_    4
#define N_    8192
#define C_    512
#define H_    8
#define D_    64
#define M_    64           // window
#define NW    (N_ / M_)    // 128
#define ROWS  (B_ * N_)    // 32768
#define NEG_INF_F (-1000000000.0f)

// ---------------- scratch (static device globals: allocation-free) ------------
__device__ __align__(16) __half g_xh[(size_t)ROWS * C_];     // fp16 x
__device__ __align__(16) __half g_attnH[(size_t)ROWS * C_];  // fp16 attn (B,N,C)
__device__ __align__(16) __half g_W16[1024 * C_];            // fp16 Wq | Wkv
__device__ __align__(16) __half g_Wp16[C_ * C_];             // fp16 Wproj
__device__ __align__(16) __half g_Qh[(size_t)ROWS * 256];    // fp16 q, local heads
__device__ __align__(16) __half g_KVh[(size_t)ROWS * 256];   // fp16 kv, local heads
__device__ float g_Qf[(size_t)ROWS * 256];                   // fp32 q, linear heads
__device__ float g_KVf[(size_t)ROWS * 256];                  // fp32 kv, linear heads
__device__ float g_ctx[16 * 64 * 64];
__device__ float g_csum[16 * 64];

// ---------------- helpers -----------------------------------------------------
__device__ __forceinline__ uint32_t smem_u32(const void* p) {
    uint32_t a;
    asm("{ .reg .u64 t; cvta.to.shared.u64 t, %1; cvt.u32.u64 %0, t; }"
        : "=r"(a) : "l"(p));
    return a;
}
#define CP_ASYNC16(dst, src) \
    asm volatile("cp.async.cg.shared.global [%0], [%1], 16;" \
                 :: "r"(dst), "l"(src))
#define CP_COMMIT() asm volatile("cp.async.commit_group;" ::: "memory")
#define CP_WAIT2()  asm volatile("cp.async.wait_group 2;" ::: "memory")

__device__ __forceinline__ void ldsm_x4(uint32_t& r0, uint32_t& r1,
                                        uint32_t& r2, uint32_t& r3, uint32_t addr) {
    asm volatile("ldmatrix.sync.aligned.m8n8.x4.shared.b16 {%0,%1,%2,%3}, [%4];"
                 : "=r"(r0), "=r"(r1), "=r"(r2), "=r"(r3) : "r"(addr));
}
__device__ __forceinline__ void ldsm_x4_trans(uint32_t& r0, uint32_t& r1,
                                              uint32_t& r2, uint32_t& r3,
                                              uint32_t addr) {
    asm volatile("ldmatrix.sync.aligned.m8n8.x4.trans.shared.b16 {%0,%1,%2,%3}, [%4];"
                 : "=r"(r0), "=r"(r1), "=r"(r2), "=r"(r3) : "r"(addr));
}
__device__ __forceinline__ void mma_f16(float* c, uint32_t a0, uint32_t a1,
                                        uint32_t a2, uint32_t a3,
                                        uint32_t b0, uint32_t b1) {
    asm volatile(
        "mma.sync.aligned.m16n8k16.row.col.f32.f16.f16.f32 "
        "{%0,%1,%2,%3}, {%4,%5,%6,%7}, {%8,%9}, {%0,%1,%2,%3};"
        : "+f"(c[0]), "+f"(c[1]), "+f"(c[2]), "+f"(c[3])
        : "r"(a0), "r"(a1), "r"(a2), "r"(a3), "r"(b0), "r"(b1));
}
__device__ __forceinline__ uint32_t pack_h2(float lo, float hi) {
    __half2 h = __floats2half2_rn(lo, hi);
    return *reinterpret_cast<uint32_t*>(&h);
}

// ---------------- conversions --------------------------------------------------
__global__ __launch_bounds__(256) void round_h_kernel(
    const float* __restrict__ src, __half* __restrict__ dst, int nrows)
{
    int total = nrows * (C_ / 4);
    for (int i = blockIdx.x * blockDim.x + threadIdx.x; i < total;
         i += gridDim.x * blockDim.x) {
        int r = i >> 7;
        int c = (i & 127) * 4;
        float4 v = *(const float4*)(src + (size_t)r * C_ + c);
        __half* base = dst + (size_t)r * C_ + c;
        *(__half2*)(base + 0) = __floats2half2_rn(v.x, v.y);
        *(__half2*)(base + 2) = __floats2half2_rn(v.z, v.w);
    }
}

// weights (3 matrices, 512x512 each = 65536 quads) + ctx/csum zeroing
__global__ __launch_bounds__(256) void prep_kernel(
    const float* __restrict__ Wq, const float* __restrict__ Wkv,
    const float* __restrict__ Wproj)
{
    const int wtotal = 3 * 65536;
    const int total = wtotal + 16 * 4096 + 16 * 64;
    for (int i = blockIdx.x * blockDim.x + threadIdx.x; i < total;
         i += gridDim.x * blockDim.x) {
        if (i < wtotal) {
            int mat = i >> 16, wi = i & 65535;
            int r = wi >> 7, c = (wi & 127) * 4;
            const float* src = (mat == 0) ? Wq : (mat == 1) ? Wkv : Wproj;
            __half* dst = (mat == 0) ? g_W16
                        : (mat == 1) ? (g_W16 + (size_t)512 * C_) : g_Wp16;
            float4 v = *(const float4*)(src + (size_t)r * C_ + c);
            __half* base = dst + (size_t)r * C_ + c;
            *(__half2*)(base + 0) = __floats2half2_rn(v.x, v.y);
            *(__half2*)(base + 2) = __floats2half2_rn(v.z, v.w);
        } else if (i < wtotal + 65536) {
            g_ctx[i - wtotal] = 0.f;
        } else {
            g_csum[i - wtotal - 65536] = 0.f;
        }
    }
}

// ---------------- fp16 mma GEMM, K=512, 128x256 tile --------------------------
#define GST     4
#define GA_ST   (128 * 40)
#define GB_ST   (256 * 40)
#define GB_BASE (GST * GA_ST)
#define GEMM_SMEM ((GB_BASE + GST * GB_ST) * 2)
#define KITS    (C_ / 32)             // 16

__global__ __launch_bounds__(512, 1) void gemm_f16(
    const __half* __restrict__ Ah, const __half* __restrict__ Bh,
    float* __restrict__ f0, float* __restrict__ f1,
    __half* __restrict__ h0p, __half* __restrict__ h1p,
    const float* __restrict__ bias, int mode)
{
    extern __shared__ __half smh[];
    const int tid = threadIdx.x;
    const int warp = tid >> 5, lane = tid & 31;
    const int wm = warp & 3, wn = warp >> 2;
    const int m0 = blockIdx.y * 128;
    const int n0 = blockIdx.x * 256;

    float acc[2][8][4];
#pragma unroll
    for (int i = 0; i < 2; i++)
#pragma unroll
        for (int j = 0; j < 8; j++)
#pragma unroll
            for (int e = 0; e < 4; e++) acc[i][j][e] = 0.f;

    const __half* Ab = Ah + (size_t)m0 * C_;
    const __half* Bb = Bh + (size_t)n0 * C_;

    const int lrow = tid >> 2;
    const int lchk = (tid & 3) * 8;

#define LOADQ(s, j) do { \
    const int ko = (j) * 32; \
    CP_ASYNC16(smem_u32(smh + (s) * GA_ST + lrow * 40 + lchk), \
               Ab + (size_t)lrow * C_ + ko + lchk); \
    CP_ASYNC16(smem_u32(smh + GB_BASE + (size_t)(s) * GB_ST + lrow * 40 + lchk), \
               Bb + (size_t)lrow * C_ + ko + lchk); \
    CP_ASYNC16(smem_u32(smh + GB_BASE + (size_t)(s) * GB_ST + (lrow + 128) * 40 + lchk), \
               Bb + (size_t)(lrow + 128) * C_ + ko + lchk); \
} while (0)

    LOADQ(0, 0); CP_COMMIT();
    LOADQ(1, 1); CP_COMMIT();
    LOADQ(2, 2); CP_COMMIT();

    const int a_row = wm * 32 + (lane & 15);
    const int a_col = (lane >> 4) << 3;
    const int b_row = wn * 64 + ((lane >> 4) << 3) + (lane & 7);
    const int b_col = ((lane >> 3) & 1) << 3;

    for (int j = 0; j < KITS; ++j) {
        const int s = j & 3;
        CP_WAIT2();
        __syncthreads();
        if (j + 3 < KITS) LOADQ((j + 3) & 3, j + 3);
        CP_COMMIT();

        const __half* As = smh + s * GA_ST;
        const __half* Bs = smh + GB_BASE + (size_t)s * GB_ST;
#pragma unroll
        for (int kk = 0; kk < 2; kk++) {
            const int k16 = kk * 16;
            uint32_t a[2][4];
#pragma unroll
            for (int i = 0; i < 2; i++)
                ldsm_x4(a[i][0], a[i][1], a[i][2], a[i][3],
                        smem_u32(As + (a_row + i * 16) * 40 + k16 + a_col));
            uint32_t b[4][4];
#pragma unroll
            for (int jb = 0; jb < 4; jb++)
                ldsm_x4(b[jb][0], b[jb][1], b[jb][2], b[jb][3],
                        smem_u32(Bs + (b_row + jb * 16) * 40 + k16 + b_col));
#pragma unroll
            for (int i = 0; i < 2; i++)
#pragma unroll
                for (int jn = 0; jn < 8; jn++) {
                    const int jb = jn >> 1, hf = (jn & 1) * 2;
                    mma_f16(acc[i][jn], a[i][0], a[i][1], a[i][2], a[i][3],
                            b[jb][hf], b[jb][hf + 1]);
                }
        }
    }

    if (mode == 0) {
        if ((blockIdx.x & 1) == 0) {
            __half* Hd = (blockIdx.x == 0) ? h0p : h1p;
#pragma unroll
            for (int i = 0; i < 2; i++) {
                const int r0 = m0 + wm * 32 + i * 16 + (lane >> 2);
#pragma unroll
                for (int jn = 0; jn < 8; jn++) {
                    const int c0 = wn * 64 + jn * 8 + (lane & 3) * 2;
                    *(__half2*)(Hd + (size_t)r0 * 256 + c0) =
                        __floats2half2_rn(acc[i][jn][0], acc[i][jn][1]);
                    *(__half2*)(Hd + (size_t)(r0 + 8) * 256 + c0) =
                        __floats2half2_rn(acc[i][jn][2], acc[i][jn][3]);
                }
            }
        } else {
            float* Fd = (blockIdx.x == 1) ? f0 : f1;
#pragma unroll
            for (int i = 0; i < 2; i++) {
                const int r0 = m0 + wm * 32 + i * 16 + (lane >> 2);
#pragma unroll
                for (int jn = 0; jn < 8; jn++) {
                    const int c0 = wn * 64 + jn * 8 + (lane & 3) * 2;
                    *(float2*)(Fd + (size_t)r0 * 256 + c0) =
                        make_float2(acc[i][jn][0], acc[i][jn][1]);
                    *(float2*)(Fd + (size_t)(r0 + 8) * 256 + c0) =
                        make_float2(acc[i][jn][2], acc[i][jn][3]);
                }
            }
        }
    } else {
#pragma unroll
        for (int i = 0; i < 2; i++) {
            const int r0 = m0 + wm * 32 + i * 16 + (lane >> 2);
#pragma unroll
            for (int jn = 0; jn < 8; jn++) {
                const int c0 = n0 + wn * 64 + jn * 8 + (lane & 3) * 2;
                float b0 = bias[c0], b1 = bias[c0 + 1];
                *(float2*)(f0 + (size_t)r0 * C_ + c0) =
                    make_float2(acc[i][jn][0] + b0, acc[i][jn][1] + b1);
                *(float2*)(f0 + (size_t)(r0 + 8) * C_ + c0) =
                    make_float2(acc[i][jn][2] + b0, acc[i][jn][3] + b1);
            }
        }
    }
}

// ---------------- local window attention via mma (heads 0..3) ------------------
// fp16 inputs; scores K=64; P in registers (hi/lo packed A-fragments);
// AV B-operand loaded straight from ks via ldmatrix.trans (no vt buffer).
#define QS2 72          // halfs: 64 + 8
#define KS2 72
#define OA2 36          // floats: 32 + 4
#define OFF_QS 0
#define OFF_KS (OFF_QS + 64 * QS2 * 2)        // 9216
#define OFF_OA (OFF_KS + 192 * KS2 * 2)       // 36864
#define OFF_RED (OFF_OA + 64 * OA2 * 4)       // 46080
#define OFF_SUM (OFF_RED + 512)               // 46592
#define LA_SMEM (OFF_SUM + 512)               // 47104

__global__ __launch_bounds__(256, 2) void local_attn_mma(float* __restrict__ attn_out)
{
    extern __shared__ char smla[];
    __half* qs = (__half*)(smla + OFF_QS);
    __half* ks = (__half*)(smla + OFF_KS);
    float* oacc = (float*)(smla + OFF_OA);
    float* redbuf = (float*)(smla + OFF_RED);
    float* sumbuf = (float*)(smla + OFF_SUM);

    const int w = blockIdx.x;
    const int bh = blockIdx.y;
    const int b = bh >> 2, hh = bh & 3;
    const int t = threadIdx.x;
    const int warp = t >> 5, lane = t & 31;
    const int wm = warp & 3, wn = warp >> 2;
    const size_t rowbase = (size_t)b * N_ + (size_t)w * M_;
    const int col0h = hh * D_;

    // ---- load q (fp16, scale by exact 0.125) ----
    {
        const __half2 sc = __floats2half2_rn(0.125f, 0.125f);
        for (int idx = t; idx < 64 * 8; idx += 256) {
            int r = idx >> 3, c8 = (idx & 7) * 8;
            uint4 v = *(const uint4*)(g_Qh + (rowbase + r) * 256 + col0h + c8);
            __half2* hv = (__half2*)&v;
            hv[0] = __hmul2(hv[0], sc); hv[1] = __hmul2(hv[1], sc);
            hv[2] = __hmul2(hv[2], sc); hv[3] = __hmul2(hv[3], sc);
            *(uint4*)(qs + r * QS2 + c8) = v;
        }
    }
    // ---- load k (= v) fp16: ks [j][d] only ----
    const int nbase = (w - 1) * M_;
    for (int idx = t; idx < 192 * 8; idx += 256) {
        int j = idx >> 3, c8 = (idx & 7) * 8;
        int n = nbase + j;
        uint4 v = make_uint4(0, 0, 0, 0);
        if (n >= 0 && n < N_)
            v = *(const uint4*)(g_KVh + ((size_t)b * N_ + n) * 256 + col0h + c8);
        *(uint4*)(ks + j * KS2 + c8) = v;
    }
    __syncthreads();

    // ---- scores: warp tile 16 x 96, K=64 ----
    float c[12][4];
#pragma unroll
    for (int jn = 0; jn < 12; jn++)
#pragma unroll
        for (int e = 0; e < 4; e++) c[jn][e] = 0.f;

    const int a_rw = wm * 16 + (lane & 15);
    const int a_cl = (lane >> 4) << 3;
    const int b_rw = wn * 96 + ((lane >> 4) << 3) + (lane & 7);
    const int b_cl = ((lane >> 3) & 1) << 3;

#pragma unroll
    for (int k16 = 0; k16 < 64; k16 += 16) {
        uint32_t a0, a1, a2, a3;
        ldsm_x4(a0, a1, a2, a3, smem_u32(qs + a_rw * QS2 + k16 + a_cl));
        uint32_t bf[6][4];
#pragma unroll
        for (int jb = 0; jb < 6; jb++)
            ldsm_x4(bf[jb][0], bf[jb][1], bf[jb][2], bf[jb][3],
                    smem_u32(ks + (b_rw + jb * 16) * KS2 + k16 + b_cl));
#pragma unroll
        for (int jn = 0; jn < 12; jn++) {
            const int jb = jn >> 1, hf = (jn & 1) * 2;
            mma_f16(c[jn], a0, a1, a2, a3, bf[jb][hf], bf[jb][hf + 1]);
        }
    }

    // ---- mask ----
    const bool leftInv = (w == 0), rightInv = (w == NW - 1);
    if (leftInv || rightInv) {
#pragma unroll
        for (int jn = 0; jn < 12; jn++) {
            const int cb = wn * 96 + jn * 8 + (lane & 3) * 2;
#pragma unroll
            for (int e = 0; e < 4; e++) {
                const int jj = cb + (e & 1);
                if ((jj < 64 && leftInv) || (jj >= 128 && rightInv))
                    c[jn][e] = NEG_INF_F;
            }
        }
    }

    // ---- softmax (rows grA, grA+8) ----
    const int grA = wm * 16 + (lane >> 2);
    float mA = -1e30f, mB = -1e30f;
#pragma unroll
    for (int jn = 0; jn < 12; jn++) {
        mA = fmaxf(mA, fmaxf(c[jn][0], c[jn][1]));
        mB = fmaxf(mB, fmaxf(c[jn][2], c[jn][3]));
    }
    mA = fmaxf(mA, __shfl_xor_sync(0xffffffffu, mA, 1));
    mA = fmaxf(mA, __shfl_xor_sync(0xffffffffu, mA, 2));
    mB = fmaxf(mB, __shfl_xor_sync(0xffffffffu, mB, 1));
    mB = fmaxf(mB, __shfl_xor_sync(0xffffffffu, mB, 2));
    if ((lane & 3) == 0) {
        redbuf[wn * 64 + grA] = mA;
        redbuf[wn * 64 + grA + 8] = mB;
    }
    __syncthreads();
    mA = fmaxf(redbuf[grA], redbuf[64 + grA]);
    mB = fmaxf(redbuf[grA + 8], redbuf[64 + grA + 8]);

    float sA = 0.f, sB = 0.f;
#pragma unroll
    for (int jn = 0; jn < 12; jn++) {
        c[jn][0] = __expf(c[jn][0] - mA); sA += c[jn][0];
        c[jn][1] = __expf(c[jn][1] - mA); sA += c[jn][1];
        c[jn][2] = __expf(c[jn][2] - mB); sB += c[jn][2];
        c[jn][3] = __expf(c[jn][3] - mB); sB += c[jn][3];
    }
    sA += __shfl_xor_sync(0xffffffffu, sA, 1);
    sA += __shfl_xor_sync(0xffffffffu, sA, 2);
    sB += __shfl_xor_sync(0xffffffffu, sB, 1);
    sB += __shfl_xor_sync(0xffffffffu, sB, 2);
    if ((lane & 3) == 0) {
        sumbuf[wn * 64 + grA] = sA;
        sumbuf[wn * 64 + grA + 8] = sB;
    }
    __syncthreads();
    const float invA = 1.f / (sumbuf[grA] + sumbuf[64 + grA]);
    const float invB = 1.f / (sumbuf[grA + 8] + sumbuf[64 + grA + 8]);

    // ---- convert score fragments -> packed hi/lo A-fragments in registers ----
    uint32_t ah[6][4], al[6][4];
#pragma unroll
    for (int kk = 0; kk < 6; kk++) {
        const int jn0 = 2 * kk, jn1 = 2 * kk + 1;
        float p00 = c[jn0][0] * invA, p01 = c[jn0][1] * invA;
        float p02 = c[jn0][2] * invB, p03 = c[jn0][3] * invB;
        float p10 = c[jn1][0] * invA, p11 = c[jn1][1] * invA;
        float p12 = c[jn1][2] * invB, p13 = c[jn1][3] * invB;
        ah[kk][0] = pack_h2(p00, p01);
        ah[kk][1] = pack_h2(p02, p03);
        ah[kk][2] = pack_h2(p10, p11);
        ah[kk][3] = pack_h2(p12, p13);
        __half2 h0 = *reinterpret_cast<__half2*>(&ah[kk][0]);
        __half2 h1 = *reinterpret_cast<__half2*>(&ah[kk][1]);
        __half2 h2 = *reinterpret_cast<__half2*>(&ah[kk][2]);
        __half2 h3 = *reinterpret_cast<__half2*>(&ah[kk][3]);
        al[kk][0] = pack_h2(p00 - __low2float(h0), p01 - __high2float(h0));
        al[kk][1] = pack_h2(p02 - __low2float(h1), p03 - __high2float(h1));
        al[kk][2] = pack_h2(p10 - __low2float(h2), p11 - __high2float(h2));
        al[kk][3] = pack_h2(p12 - __low2float(h3), p13 - __high2float(h3));
    }

    // ---- AV in two e-halves; B loaded from ks via ldmatrix.trans ----
    // per-lane trans address row: j = jcol + ((lane>>3)&1)*8 + (lane&7),
    // col: e0 + ((lane>>4)<<3)   (reproduces the non-trans register mapping)
    const int t_jofs = (((lane >> 3) & 1) << 3) + (lane & 7);
    const int t_eofs = (lane >> 4) << 3;
#pragma unroll
    for (int eh = 0; eh < 2; eh++) {
        float o[4][4];
#pragma unroll
        for (int jn = 0; jn < 4; jn++)
#pragma unroll
            for (int e = 0; e < 4; e++) o[jn][e] = 0.f;

#pragma unroll
        for (int kk = 0; kk < 6; kk++) {
            const int jcol = wn * 96 + kk * 16;
            uint32_t bf[2][4];
#pragma unroll
            for (int jb = 0; jb < 2; jb++)
                ldsm_x4_trans(bf[jb][0], bf[jb][1], bf[jb][2], bf[jb][3],
                              smem_u32(ks + (jcol + t_jofs) * KS2
                                       + eh * 32 + jb * 16 + t_eofs));
#pragma unroll
            for (int jn = 0; jn < 4; jn++) {
                const int jb = jn >> 1, hf = (jn & 1) * 2;
                mma_f16(o[jn], ah[kk][0], ah[kk][1], ah[kk][2], ah[kk][3],
                        bf[jb][hf], bf[jb][hf + 1]);
                mma_f16(o[jn], al[kk][0], al[kk][1], al[kk][2], al[kk][3],
                        bf[jb][hf], bf[jb][hf + 1]);
            }
        }

        // cross-wn reduction via oacc (32 e-cols)
        if (wn == 0) {
#pragma unroll
            for (int jn = 0; jn < 4; jn++) {
                const int cb = jn * 8 + (lane & 3) * 2;
                oacc[grA * OA2 + cb] = o[jn][0];
                oacc[grA * OA2 + cb + 1] = o[jn][1];
                oacc[(grA + 8) * OA2 + cb] = o[jn][2];
                oacc[(grA + 8) * OA2 + cb + 1] = o[jn][3];
            }
        }
        __syncthreads();
        if (wn == 1) {
#pragma unroll
            for (int jn = 0; jn < 4; jn++) {
                const int cb = jn * 8 + (lane & 3) * 2;
#pragma unroll
                for (int half = 0; half < 2; half++) {
                    const int row = grA + half * 8;
                    const int n = w * M_ + row;
                    const int ecol = eh * 32 + cb;
                    const float v0 = o[jn][half * 2] + oacc[row * OA2 + cb];
                    const float v1 = o[jn][half * 2 + 1] + oacc[row * OA2 + cb + 1];
                    float* ad = attn_out +
                        ((size_t)(b * H_ + hh) * N_ + n) * D_ + ecol;
                    ad[0] = v0; ad[1] = v1;
                    *(__half2*)(g_attnH + ((size_t)b * N_ + n) * C_
                                + hh * D_ + ecol) = __floats2half2_rn(v0, v1);
                }
            }
        }
        __syncthreads();
    }
}

// ---------------- linear attention (heads 4..7) -------------------------------
#define CT_SMEM (256 * 64 * 4)
__global__ __launch_bounds__(256) void ctx_kernel()
{
    extern __shared__ float tile[];
    const int bh = blockIdx.y;
    const int b = bh >> 2, hh = 4 + (bh & 3);
    const int n0 = blockIdx.x * 256;
    const int t = threadIdx.x;

    const float* src = g_KVf + ((size_t)b * N_ + n0) * 256 + (hh - 4) * D_;
    for (int idx = t; idx < 256 * 16; idx += 256) {
        int r = idx >> 4, c4 = (idx & 15) * 4;
        float4 v = *(const float4*)(src + (size_t)r * 256 + c4);
        float* dst = tile + r * 64 + c4;
        dst[0] = v.x; dst[1] = v.y; dst[2] = v.z; dst[3] = v.w;
    }
    __syncthreads();

    const int d = t >> 2, q = t & 3;
    float4 acc[4];
#pragma unroll
    for (int i = 0; i < 4; i++) acc[i] = make_float4(0.f, 0.f, 0.f, 0.f);
    float ssum = 0.f;

    for (int n = 0; n < 256; n++) {
        float ek = __expf(tile[n * 64 + d]);
        ssum += ek;
        const float4* vr = (const float4*)(tile + n * 64 + q * 16);
#pragma unroll
        for (int e4 = 0; e4 < 4; e4++) {
            float4 v = vr[e4];
            acc[e4].x = fmaf(ek, v.x, acc[e4].x);
            acc[e4].y = fmaf(ek, v.y, acc[e4].y);
            acc[e4].z = fmaf(ek, v.z, acc[e4].z);
            acc[e4].w = fmaf(ek, v.w, acc[e4].w);
        }
    }
    float* dst = g_ctx + bh * 4096 + d * 64 + q * 16;
#pragma unroll
    for (int e4 = 0; e4 < 4; e4++) {
        atomicAdd(dst + e4 * 4 + 0, acc[e4].x);
        atomicAdd(dst + e4 * 4 + 1, acc[e4].y);
        atomicAdd(dst + e4 * 4 + 2, acc[e4].z);
        atomicAdd(dst + e4 * 4 + 3, acc[e4].w);
    }
    if (q == 0) atomicAdd(&g_csum[bh * 64 + d], ssum);
}

__global__ __launch_bounds__(256) void lin_out_kernel(float* __restrict__ attn_out)
{
    __shared__ float ctx_s[4096];
    __shared__ float cinv_s[64];
    const int bh = blockIdx.y;
    const int b = bh >> 2, hh = 4 + (bh & 3);
    const int t = threadIdx.x;

    if (t < 64) cinv_s[t] = 1.f / g_csum[bh * 64 + t];
    for (int i = t; i < 4096; i += 256) ctx_s[i] = g_ctx[bh * 4096 + i];
    __syncthreads();

    const int warp = t >> 5, lane = t & 31;
    for (int r = warp; r < 64; r += 8) {
        const int n = blockIdx.x * 64 + r;
        const float* qrow = g_Qf + ((size_t)b * N_ + n) * 256 + (hh - 4) * D_;
        float q0 = qrow[lane], q1 = qrow[lane + 32];
        float m = fmaxf(q0, q1);
#pragma unroll
        for (int o = 16; o; o >>= 1) m = fmaxf(m, __shfl_xor_sync(0xffffffffu, m, o));
        float e0 = __expf(q0 - m), e1 = __expf(q1 - m);
        float s = e0 + e1;
#pragma unroll
        for (int o = 16; o; o >>= 1) s += __shfl_xor_sync(0xffffffffu, s, o);
        float inv = 0.125f / s;
        e0 *= inv * cinv_s[lane];
        e1 *= inv * cinv_s[lane + 32];

        float a0 = 0.f, a1 = 0.f;
#pragma unroll
        for (int dd = 0; dd < 64; dd++) {
            float sq = __shfl_sync(0xffffffffu, (dd < 32) ? e0 : e1, dd & 31);
            a0 = fmaf(sq, ctx_s[dd * 64 + lane], a0);
            a1 = fmaf(sq, ctx_s[dd * 64 + lane + 32], a1);
        }
        size_t o1 = ((size_t)(b * H_ + hh) * N_ + n) * D_;
        attn_out[o1 + lane] = a0;
        attn_out[o1 + lane + 32] = a1;

        __half* hdst = g_attnH + ((size_t)b * N_ + n) * C_ + hh * D_;
        hdst[lane] = __float2half_rn(a0);
        hdst[lane + 32] = __float2half_rn(a1);
    }
}

// ---------------------------------- launch ------------------------------------
extern "C" void kernel_launch(void* const* d_in, const int* in_sizes, int n_in,
                              void* d_out, int out_size)
{
    (void)in_sizes; (void)n_in; (void)out_size;
    const float* x     = (const float*)d_in[0];
    const float* Wq    = (const float*)d_in[1];
    const float* Wkv   = (const float*)d_in[2];
    const float* Wproj = (const float*)d_in[3];
    const float* bproj = (const float*)d_in[4];

    float* y    = (float*)d_out;
    float* attn = y + (size_t)ROWS * C_;

    float *pQf, *pKVf;
    __half *pxh, *paH, *pW16, *pWp16, *pQh, *pKVh;
    cudaGetSymbolAddress((void**)&pQf, g_Qf);
    cudaGetSymbolAddress((void**)&pKVf, g_KVf);
    cudaGetSymbolAddress((void**)&pQh, g_Qh);
    cudaGetSymbolAddress((void**)&pKVh, g_KVh);
    cudaGetSymbolAddress((void**)&pxh, g_xh);
    cudaGetSymbolAddress((void**)&paH, g_attnH);
    cudaGetSymbolAddress((void**)&pW16, g_W16);
    cudaGetSymbolAddress((void**)&pWp16, g_Wp16);

    cudaFuncSetAttribute(gemm_f16,
                         cudaFuncAttributeMaxDynamicSharedMemorySize, GEMM_SMEM);
    cudaFuncSetAttribute(local_attn_mma,
                         cudaFuncAttributeMaxDynamicSharedMemorySize, LA_SMEM);
    cudaFuncSetAttribute(ctx_kernel,
                         cudaFuncAttributeMaxDynamicSharedMemorySize, CT_SMEM);

    // conversions + ctx zeroing
    prep_kernel<<<512, 256>>>(Wq, Wkv, Wproj);
    round_h_kernel<<<2048, 256>>>(x, pxh, ROWS);

    // fused Q+KV GEMM: n-tiles -> Qh | Qf | KVh | KVf
    gemm_f16<<<dim3(4, ROWS / 128), 512, GEMM_SMEM>>>(
        pxh, pW16, pQf, pKVf, pQh, pKVh, nullptr, 0);

    local_attn_mma<<<dim3(NW, 16), 256, LA_SMEM>>>(attn);

    ctx_kernel<<<dim3(32, 16), 256, CT_SMEM>>>();
    lin_out_kernel<<<dim3(128, 16), 256>>>(attn);

    // proj GEMM: y = attnH @ Wp16^T + bias
    gemm_f16<<<dim3(2, ROWS / 128), 512, GEMM_SMEM>>>(
        paH, pWp16, y, nullptr, nullptr, nullptr, bproj, 1);
}

// round 14
// speedup vs baseline: 3.5146x; 1.3490x over previous
#include <cuda_runtime.h>
#include <cuda_bf16.h>
#include <cuda_fp16.h>
#include <math.h>
#include <stdint.h>

#define B_    4
#define N_    8192
#define C_    512
#define H_    8
#define D_    64
#define M_    64           // window
#define NW    (N_ / M_)    // 128
#define ROWS  (B_ * N_)    // 32768
#define NEG_INF_F (-1000000000.0f)

// ---------------- scratch (static device globals: allocation-free) ------------
__device__ __align__(16) __half g_xh[(size_t)ROWS * C_];     // fp16 x
__device__ __align__(16) __half g_attnH[(size_t)ROWS * C_];  // fp16 attn (B,N,C)
__device__ __align__(16) __half g_W16[1024 * C_];            // fp16 Wq | Wkv
__device__ __align__(16) __half g_Wp16[C_ * C_];             // fp16 Wproj
__device__ __align__(16) __half g_Qh[(size_t)ROWS * 256];    // fp16 q, local heads
__device__ __align__(16) __half g_KVh[(size_t)ROWS * 256];   // fp16 kv, local heads
__device__ float g_Qf[(size_t)ROWS * 256];                   // fp32 q, linear heads
__device__ float g_KVf[(size_t)ROWS * 256];                  // fp32 kv, linear heads
__device__ float g_ctx[16 * 64 * 64];
__device__ float g_csum[16 * 64];

// ---------------- helpers -----------------------------------------------------
__device__ __forceinline__ uint32_t smem_u32(const void* p) {
    uint32_t a;
    asm("{ .reg .u64 t; cvta.to.shared.u64 t, %1; cvt.u32.u64 %0, t; }"
        : "=r"(a) : "l"(p));
    return a;
}
#define CP_ASYNC16(dst, src) \
    asm volatile("cp.async.cg.shared.global [%0], [%1], 16;" \
                 :: "r"(dst), "l"(src))
#define CP_COMMIT() asm volatile("cp.async.commit_group;" ::: "memory")
#define CP_WAIT2()  asm volatile("cp.async.wait_group 2;" ::: "memory")

__device__ __forceinline__ void ldsm_x4(uint32_t& r0, uint32_t& r1,
                                        uint32_t& r2, uint32_t& r3, uint32_t addr) {
    asm volatile("ldmatrix.sync.aligned.m8n8.x4.shared.b16 {%0,%1,%2,%3}, [%4];"
                 : "=r"(r0), "=r"(r1), "=r"(r2), "=r"(r3) : "r"(addr));
}
__device__ __forceinline__ void ldsm_x4_trans(uint32_t& r0, uint32_t& r1,
                                              uint32_t& r2, uint32_t& r3,
                                              uint32_t addr) {
    asm volatile("ldmatrix.sync.aligned.m8n8.x4.trans.shared.b16 {%0,%1,%2,%3}, [%4];"
                 : "=r"(r0), "=r"(r1), "=r"(r2), "=r"(r3) : "r"(addr));
}
__device__ __forceinline__ void mma_f16(float* c, uint32_t a0, uint32_t a1,
                                        uint32_t a2, uint32_t a3,
                                        uint32_t b0, uint32_t b1) {
    asm volatile(
        "mma.sync.aligned.m16n8k16.row.col.f32.f16.f16.f32 "
        "{%0,%1,%2,%3}, {%4,%5,%6,%7}, {%8,%9}, {%0,%1,%2,%3};"
        : "+f"(c[0]), "+f"(c[1]), "+f"(c[2]), "+f"(c[3])
        : "r"(a0), "r"(a1), "r"(a2), "r"(a3), "r"(b0), "r"(b1));
}
__device__ __forceinline__ uint32_t pack_h2(float lo, float hi) {
    __half2 h = __floats2half2_rn(lo, hi);
    return *reinterpret_cast<uint32_t*>(&h);
}

// ---------------- conversions --------------------------------------------------
__global__ __launch_bounds__(256) void round_h_kernel(
    const float* __restrict__ src, __half* __restrict__ dst, int nrows)
{
    int total = nrows * (C_ / 4);
    for (int i = blockIdx.x * blockDim.x + threadIdx.x; i < total;
         i += gridDim.x * blockDim.x) {
        int r = i >> 7;
        int c = (i & 127) * 4;
        float4 v = *(const float4*)(src + (size_t)r * C_ + c);
        __half* base = dst + (size_t)r * C_ + c;
        *(__half2*)(base + 0) = __floats2half2_rn(v.x, v.y);
        *(__half2*)(base + 2) = __floats2half2_rn(v.z, v.w);
    }
}

// weights (3 matrices, 512x512 each = 65536 quads) + ctx/csum zeroing
__global__ __launch_bounds__(256) void prep_kernel(
    const float* __restrict__ Wq, const float* __restrict__ Wkv,
    const float* __restrict__ Wproj)
{
    const int wtotal = 3 * 65536;
    const int total = wtotal + 16 * 4096 + 16 * 64;
    for (int i = blockIdx.x * blockDim.x + threadIdx.x; i < total;
         i += gridDim.x * blockDim.x) {
        if (i < wtotal) {
            int mat = i >> 16, wi = i & 65535;
            int r = wi >> 7, c = (wi & 127) * 4;
            const float* src = (mat == 0) ? Wq : (mat == 1) ? Wkv : Wproj;
            __half* dst = (mat == 0) ? g_W16
                        : (mat == 1) ? (g_W16 + (size_t)512 * C_) : g_Wp16;
            float4 v = *(const float4*)(src + (size_t)r * C_ + c);
            __half* base = dst + (size_t)r * C_ + c;
            *(__half2*)(base + 0) = __floats2half2_rn(v.x, v.y);
            *(__half2*)(base + 2) = __floats2half2_rn(v.z, v.w);
        } else if (i < wtotal + 65536) {
            g_ctx[i - wtotal] = 0.f;
        } else {
            g_csum[i - wtotal - 65536] = 0.f;
        }
    }
}

// ---------------- fp16 mma GEMM, K=512, 128x256 tile --------------------------
#define GST     4
#define GA_ST   (128 * 40)
#define GB_ST   (256 * 40)
#define GB_BASE (GST * GA_ST)
#define GEMM_SMEM ((GB_BASE + GST * GB_ST) * 2)
#define KITS    (C_ / 32)             // 16

__global__ __launch_bounds__(512, 1) void gemm_f16(
    const __half* __restrict__ Ah, const __half* __restrict__ Bh,
    float* __restrict__ f0, float* __restrict__ f1,
    __half* __restrict__ h0p, __half* __restrict__ h1p,
    const float* __restrict__ bias, int mode)
{
    extern __shared__ __half smh[];
    const int tid = threadIdx.x;
    const int warp = tid >> 5, lane = tid & 31;
    const int wm = warp & 3, wn = warp >> 2;
    const int m0 = blockIdx.y * 128;
    const int n0 = blockIdx.x * 256;

    float acc[2][8][4];
#pragma unroll
    for (int i = 0; i < 2; i++)
#pragma unroll
        for (int j = 0; j < 8; j++)
#pragma unroll
            for (int e = 0; e < 4; e++) acc[i][j][e] = 0.f;

    const __half* Ab = Ah + (size_t)m0 * C_;
    const __half* Bb = Bh + (size_t)n0 * C_;

    const int lrow = tid >> 2;
    const int lchk = (tid & 3) * 8;

#define LOADQ(s, j) do { \
    const int ko = (j) * 32; \
    CP_ASYNC16(smem_u32(smh + (s) * GA_ST + lrow * 40 + lchk), \
               Ab + (size_t)lrow * C_ + ko + lchk); \
    CP_ASYNC16(smem_u32(smh + GB_BASE + (size_t)(s) * GB_ST + lrow * 40 + lchk), \
               Bb + (size_t)lrow * C_ + ko + lchk); \
    CP_ASYNC16(smem_u32(smh + GB_BASE + (size_t)(s) * GB_ST + (lrow + 128) * 40 + lchk), \
               Bb + (size_t)(lrow + 128) * C_ + ko + lchk); \
} while (0)

    LOADQ(0, 0); CP_COMMIT();
    LOADQ(1, 1); CP_COMMIT();
    LOADQ(2, 2); CP_COMMIT();

    const int a_row = wm * 32 + (lane & 15);
    const int a_col = (lane >> 4) << 3;
    const int b_row = wn * 64 + ((lane >> 4) << 3) + (lane & 7);
    const int b_col = ((lane >> 3) & 1) << 3;

    for (int j = 0; j < KITS; ++j) {
        const int s = j & 3;
        CP_WAIT2();
        __syncthreads();
        if (j + 3 < KITS) LOADQ((j + 3) & 3, j + 3);
        CP_COMMIT();

        const __half* As = smh + s * GA_ST;
        const __half* Bs = smh + GB_BASE + (size_t)s * GB_ST;
#pragma unroll
        for (int kk = 0; kk < 2; kk++) {
            const int k16 = kk * 16;
            uint32_t a[2][4];
#pragma unroll
            for (int i = 0; i < 2; i++)
                ldsm_x4(a[i][0], a[i][1], a[i][2], a[i][3],
                        smem_u32(As + (a_row + i * 16) * 40 + k16 + a_col));
            uint32_t b[4][4];
#pragma unroll
            for (int jb = 0; jb < 4; jb++)
                ldsm_x4(b[jb][0], b[jb][1], b[jb][2], b[jb][3],
                        smem_u32(Bs + (b_row + jb * 16) * 40 + k16 + b_col));
#pragma unroll
            for (int i = 0; i < 2; i++)
#pragma unroll
                for (int jn = 0; jn < 8; jn++) {
                    const int jb = jn >> 1, hf = (jn & 1) * 2;
                    mma_f16(acc[i][jn], a[i][0], a[i][1], a[i][2], a[i][3],
                            b[jb][hf], b[jb][hf + 1]);
                }
        }
    }

    if (mode == 0) {
        if ((blockIdx.x & 1) == 0) {
            __half* Hd = (blockIdx.x == 0) ? h0p : h1p;
#pragma unroll
            for (int i = 0; i < 2; i++) {
                const int r0 = m0 + wm * 32 + i * 16 + (lane >> 2);
#pragma unroll
                for (int jn = 0; jn < 8; jn++) {
                    const int c0 = wn * 64 + jn * 8 + (lane & 3) * 2;
                    *(__half2*)(Hd + (size_t)r0 * 256 + c0) =
                        __floats2half2_rn(acc[i][jn][0], acc[i][jn][1]);
                    *(__half2*)(Hd + (size_t)(r0 + 8) * 256 + c0) =
                        __floats2half2_rn(acc[i][jn][2], acc[i][jn][3]);
                }
            }
        } else {
            float* Fd = (blockIdx.x == 1) ? f0 : f1;
#pragma unroll
            for (int i = 0; i < 2; i++) {
                const int r0 = m0 + wm * 32 + i * 16 + (lane >> 2);
#pragma unroll
                for (int jn = 0; jn < 8; jn++) {
                    const int c0 = wn * 64 + jn * 8 + (lane & 3) * 2;
                    *(float2*)(Fd + (size_t)r0 * 256 + c0) =
                        make_float2(acc[i][jn][0], acc[i][jn][1]);
                    *(float2*)(Fd + (size_t)(r0 + 8) * 256 + c0) =
                        make_float2(acc[i][jn][2], acc[i][jn][3]);
                }
            }
        }
    } else {
#pragma unroll
        for (int i = 0; i < 2; i++) {
            const int r0 = m0 + wm * 32 + i * 16 + (lane >> 2);
#pragma unroll
            for (int jn = 0; jn < 8; jn++) {
                const int c0 = n0 + wn * 64 + jn * 8 + (lane & 3) * 2;
                float b0 = bias[c0], b1 = bias[c0 + 1];
                *(float2*)(f0 + (size_t)r0 * C_ + c0) =
                    make_float2(acc[i][jn][0] + b0, acc[i][jn][1] + b1);
                *(float2*)(f0 + (size_t)(r0 + 8) * C_ + c0) =
                    make_float2(acc[i][jn][2] + b0, acc[i][jn][3] + b1);
            }
        }
    }
}

// ---------------- local window attention via mma (heads 0..3) ------------------
#define QS2 72          // halfs: 64 + 8
#define KS2 72
#define OA2 36          // floats: 32 + 4
#define OFF_QS 0
#define OFF_KS (OFF_QS + 64 * QS2 * 2)        // 9216
#define OFF_OA (OFF_KS + 192 * KS2 * 2)       // 36864
#define OFF_RED (OFF_OA + 64 * OA2 * 4)       // 46080
#define OFF_SUM (OFF_RED + 512)               // 46592
#define LA_SMEM (OFF_SUM + 512)               // 47104

__global__ __launch_bounds__(256, 2) void local_attn_mma(float* __restrict__ attn_out)
{
    extern __shared__ char smla[];
    __half* qs = (__half*)(smla + OFF_QS);
    __half* ks = (__half*)(smla + OFF_KS);
    float* oacc = (float*)(smla + OFF_OA);
    float* redbuf = (float*)(smla + OFF_RED);
    float* sumbuf = (float*)(smla + OFF_SUM);

    const int w = blockIdx.x;
    const int bh = blockIdx.y;
    const int b = bh >> 2, hh = bh & 3;
    const int t = threadIdx.x;
    const int warp = t >> 5, lane = t & 31;
    const int wm = warp & 3, wn = warp >> 2;
    const size_t rowbase = (size_t)b * N_ + (size_t)w * M_;
    const int col0h = hh * D_;

    {
        const __half2 sc = __floats2half2_rn(0.125f, 0.125f);
        for (int idx = t; idx < 64 * 8; idx += 256) {
            int r = idx >> 3, c8 = (idx & 7) * 8;
            uint4 v = *(const uint4*)(g_Qh + (rowbase + r) * 256 + col0h + c8);
            __half2* hv = (__half2*)&v;
            hv[0] = __hmul2(hv[0], sc); hv[1] = __hmul2(hv[1], sc);
            hv[2] = __hmul2(hv[2], sc); hv[3] = __hmul2(hv[3], sc);
            *(uint4*)(qs + r * QS2 + c8) = v;
        }
    }
    const int nbase = (w - 1) * M_;
    for (int idx = t; idx < 192 * 8; idx += 256) {
        int j = idx >> 3, c8 = (idx & 7) * 8;
        int n = nbase + j;
        uint4 v = make_uint4(0, 0, 0, 0);
        if (n >= 0 && n < N_)
            v = *(const uint4*)(g_KVh + ((size_t)b * N_ + n) * 256 + col0h + c8);
        *(uint4*)(ks + j * KS2 + c8) = v;
    }
    __syncthreads();

    float c[12][4];
#pragma unroll
    for (int jn = 0; jn < 12; jn++)
#pragma unroll
        for (int e = 0; e < 4; e++) c[jn][e] = 0.f;

    const int a_rw = wm * 16 + (lane & 15);
    const int a_cl = (lane >> 4) << 3;
    const int b_rw = wn * 96 + ((lane >> 4) << 3) + (lane & 7);
    const int b_cl = ((lane >> 3) & 1) << 3;

#pragma unroll
    for (int k16 = 0; k16 < 64; k16 += 16) {
        uint32_t a0, a1, a2, a3;
        ldsm_x4(a0, a1, a2, a3, smem_u32(qs + a_rw * QS2 + k16 + a_cl));
        uint32_t bf[6][4];
#pragma unroll
        for (int jb = 0; jb < 6; jb++)
            ldsm_x4(bf[jb][0], bf[jb][1], bf[jb][2], bf[jb][3],
                    smem_u32(ks + (b_rw + jb * 16) * KS2 + k16 + b_cl));
#pragma unroll
        for (int jn = 0; jn < 12; jn++) {
            const int jb = jn >> 1, hf = (jn & 1) * 2;
            mma_f16(c[jn], a0, a1, a2, a3, bf[jb][hf], bf[jb][hf + 1]);
        }
    }

    const bool leftInv = (w == 0), rightInv = (w == NW - 1);
    if (leftInv || rightInv) {
#pragma unroll
        for (int jn = 0; jn < 12; jn++) {
            const int cb = wn * 96 + jn * 8 + (lane & 3) * 2;
#pragma unroll
            for (int e = 0; e < 4; e++) {
                const int jj = cb + (e & 1);
                if ((jj < 64 && leftInv) || (jj >= 128 && rightInv))
                    c[jn][e] = NEG_INF_F;
            }
        }
    }

    const int grA = wm * 16 + (lane >> 2);
    float mA = -1e30f, mB = -1e30f;
#pragma unroll
    for (int jn = 0; jn < 12; jn++) {
        mA = fmaxf(mA, fmaxf(c[jn][0], c[jn][1]));
        mB = fmaxf(mB, fmaxf(c[jn][2], c[jn][3]));
    }
    mA = fmaxf(mA, __shfl_xor_sync(0xffffffffu, mA, 1));
    mA = fmaxf(mA, __shfl_xor_sync(0xffffffffu, mA, 2));
    mB = fmaxf(mB, __shfl_xor_sync(0xffffffffu, mB, 1));
    mB = fmaxf(mB, __shfl_xor_sync(0xffffffffu, mB, 2));
    if ((lane & 3) == 0) {
        redbuf[wn * 64 + grA] = mA;
        redbuf[wn * 64 + grA + 8] = mB;
    }
    __syncthreads();
    mA = fmaxf(redbuf[grA], redbuf[64 + grA]);
    mB = fmaxf(redbuf[grA + 8], redbuf[64 + grA + 8]);

    float sA = 0.f, sB = 0.f;
#pragma unroll
    for (int jn = 0; jn < 12; jn++) {
        c[jn][0] = __expf(c[jn][0] - mA); sA += c[jn][0];
        c[jn][1] = __expf(c[jn][1] - mA); sA += c[jn][1];
        c[jn][2] = __expf(c[jn][2] - mB); sB += c[jn][2];
        c[jn][3] = __expf(c[jn][3] - mB); sB += c[jn][3];
    }
    sA += __shfl_xor_sync(0xffffffffu, sA, 1);
    sA += __shfl_xor_sync(0xffffffffu, sA, 2);
    sB += __shfl_xor_sync(0xffffffffu, sB, 1);
    sB += __shfl_xor_sync(0xffffffffu, sB, 2);
    if ((lane & 3) == 0) {
        sumbuf[wn * 64 + grA] = sA;
        sumbuf[wn * 64 + grA + 8] = sB;
    }
    __syncthreads();
    const float invA = 1.f / (sumbuf[grA] + sumbuf[64 + grA]);
    const float invB = 1.f / (sumbuf[grA + 8] + sumbuf[64 + grA + 8]);

    uint32_t ah[6][4], al[6][4];
#pragma unroll
    for (int kk = 0; kk < 6; kk++) {
        const int jn0 = 2 * kk, jn1 = 2 * kk + 1;
        float p00 = c[jn0][0] * invA, p01 = c[jn0][1] * invA;
        float p02 = c[jn0][2] * invB, p03 = c[jn0][3] * invB;
        float p10 = c[jn1][0] * invA, p11 = c[jn1][1] * invA;
        float p12 = c[jn1][2] * invB, p13 = c[jn1][3] * invB;
        ah[kk][0] = pack_h2(p00, p01);
        ah[kk][1] = pack_h2(p02, p03);
        ah[kk][2] = pack_h2(p10, p11);
        ah[kk][3] = pack_h2(p12, p13);
        __half2 h0 = *reinterpret_cast<__half2*>(&ah[kk][0]);
        __half2 h1 = *reinterpret_cast<__half2*>(&ah[kk][1]);
        __half2 h2 = *reinterpret_cast<__half2*>(&ah[kk][2]);
        __half2 h3 = *reinterpret_cast<__half2*>(&ah[kk][3]);
        al[kk][0] = pack_h2(p00 - __low2float(h0), p01 - __high2float(h0));
        al[kk][1] = pack_h2(p02 - __low2float(h1), p03 - __high2float(h1));
        al[kk][2] = pack_h2(p10 - __low2float(h2), p11 - __high2float(h2));
        al[kk][3] = pack_h2(p12 - __low2float(h3), p13 - __high2float(h3));
    }

    const int t_jofs = (((lane >> 3) & 1) << 3) + (lane & 7);
    const int t_eofs = (lane >> 4) << 3;
#pragma unroll
    for (int eh = 0; eh < 2; eh++) {
        float o[4][4];
#pragma unroll
        for (int jn = 0; jn < 4; jn++)
#pragma unroll
            for (int e = 0; e < 4; e++) o[jn][e] = 0.f;

#pragma unroll
        for (int kk = 0; kk < 6; kk++) {
            const int jcol = wn * 96 + kk * 16;
            uint32_t bf[2][4];
#pragma unroll
            for (int jb = 0; jb < 2; jb++)
                ldsm_x4_trans(bf[jb][0], bf[jb][1], bf[jb][2], bf[jb][3],
                              smem_u32(ks + (jcol + t_jofs) * KS2
                                       + eh * 32 + jb * 16 + t_eofs));
#pragma unroll
            for (int jn = 0; jn < 4; jn++) {
                const int jb = jn >> 1, hf = (jn & 1) * 2;
                mma_f16(o[jn], ah[kk][0], ah[kk][1], ah[kk][2], ah[kk][3],
                        bf[jb][hf], bf[jb][hf + 1]);
                mma_f16(o[jn], al[kk][0], al[kk][1], al[kk][2], al[kk][3],
                        bf[jb][hf], bf[jb][hf + 1]);
            }
        }

        if (wn == 0) {
#pragma unroll
            for (int jn = 0; jn < 4; jn++) {
                const int cb = jn * 8 + (lane & 3) * 2;
                oacc[grA * OA2 + cb] = o[jn][0];
                oacc[grA * OA2 + cb + 1] = o[jn][1];
                oacc[(grA + 8) * OA2 + cb] = o[jn][2];
                oacc[(grA + 8) * OA2 + cb + 1] = o[jn][3];
            }
        }
        __syncthreads();
        if (wn == 1) {
#pragma unroll
            for (int jn = 0; jn < 4; jn++) {
                const int cb = jn * 8 + (lane & 3) * 2;
#pragma unroll
                for (int half = 0; half < 2; half++) {
                    const int row = grA + half * 8;
                    const int n = w * M_ + row;
                    const int ecol = eh * 32 + cb;
                    const float v0 = o[jn][half * 2] + oacc[row * OA2 + cb];
                    const float v1 = o[jn][half * 2 + 1] + oacc[row * OA2 + cb + 1];
                    float* ad = attn_out +
                        ((size_t)(b * H_ + hh) * N_ + n) * D_ + ecol;
                    ad[0] = v0; ad[1] = v1;
                    *(__half2*)(g_attnH + ((size_t)b * N_ + n) * C_
                                + hh * D_ + ecol) = __floats2half2_rn(v0, v1);
                }
            }
        }
        __syncthreads();
    }
}

// ---------------- linear attention via mma (heads 4..7) ------------------------
// ctx = E^T V: per (bh, n-chunk 128). E fp16, V exact hi/lo fp16. fp32 atomics.
#define CXS 72
#define CTX_SMEM (3 * 128 * CXS * 2)     // et | vhs | vls = 55296 B

__global__ __launch_bounds__(128) void ctx_mma_kernel()
{
    extern __shared__ __half smc[];
    __half* et = smc;
    __half* vhs = et + 128 * CXS;
    __half* vls = vhs + 128 * CXS;

    const int bh = blockIdx.y;
    const int b = bh >> 2, hh4 = bh & 3;
    const int n0 = blockIdx.x * 128;
    const int t = threadIdx.x;
    const int warp = t >> 5, lane = t & 31;

    // load + exp + hi/lo; thread covers rows r0+8k, fixed 4 cols
    const float* src = g_KVf + ((size_t)b * N_ + n0) * 256 + hh4 * D_;
    const int c4 = (t & 15) * 4;
    const int r0 = t >> 4;
    float cs0 = 0.f, cs1 = 0.f, cs2 = 0.f, cs3 = 0.f;
#pragma unroll
    for (int k = 0; k < 16; k++) {
        const int r = r0 + k * 8;
        float4 v = *(const float4*)(src + (size_t)r * 256 + c4);
        float e0 = __expf(v.x), e1 = __expf(v.y);
        float e2 = __expf(v.z), e3 = __expf(v.w);
        cs0 += e0; cs1 += e1; cs2 += e2; cs3 += e3;
        __half* ep = et + r * CXS + c4;
        *(__half2*)(ep + 0) = __floats2half2_rn(e0, e1);
        *(__half2*)(ep + 2) = __floats2half2_rn(e2, e3);
        __half h0 = __float2half_rn(v.x), h1 = __float2half_rn(v.y);
        __half h2 = __float2half_rn(v.z), h3 = __float2half_rn(v.w);
        __half2 hA; hA.x = h0; hA.y = h1;
        __half2 hB; hB.x = h2; hB.y = h3;
        __half* vp = vhs + r * CXS + c4;
        *(__half2*)(vp + 0) = hA;
        *(__half2*)(vp + 2) = hB;
        __half* lp = vls + r * CXS + c4;
        *(__half2*)(lp + 0) = __floats2half2_rn(v.x - __half2float(h0),
                                                v.y - __half2float(h1));
        *(__half2*)(lp + 2) = __floats2half2_rn(v.z - __half2float(h2),
                                                v.w - __half2float(h3));
    }
    atomicAdd(&g_csum[bh * 64 + c4 + 0], cs0);
    atomicAdd(&g_csum[bh * 64 + c4 + 1], cs1);
    atomicAdd(&g_csum[bh * 64 + c4 + 2], cs2);
    atomicAdd(&g_csum[bh * 64 + c4 + 3], cs3);
    __syncthreads();

    // mma: warp tile m16 (d) x n64 (e), K=128 n-rows; A trans from et, B trans from vhs/vls
    const int m0 = warp * 16;
    float acc[8][4];
#pragma unroll
    for (int jn = 0; jn < 8; jn++)
#pragma unroll
        for (int e = 0; e < 4; e++) acc[jn][e] = 0.f;

    const int a_r = ((lane >> 4) << 3) + (lane & 7);         // A-trans row ofs
    const int a_c = m0 + (((lane >> 3) & 1) << 3);           // A-trans col
    const int b_r = (((lane >> 3) & 1) << 3) + (lane & 7);   // B-trans row ofs
    const int b_cofs = (lane >> 4) << 3;                     // B-trans col ofs

#pragma unroll
    for (int kc = 0; kc < 8; kc++) {
        const int k0 = kc * 16;
        uint32_t a0, a1, a2, a3;
        ldsm_x4_trans(a0, a1, a2, a3, smem_u32(et + (k0 + a_r) * CXS + a_c));
        uint32_t bfh[4][4], bfl[4][4];
#pragma unroll
        for (int jb = 0; jb < 4; jb++) {
            ldsm_x4_trans(bfh[jb][0], bfh[jb][1], bfh[jb][2], bfh[jb][3],
                          smem_u32(vhs + (k0 + b_r) * CXS + jb * 16 + b_cofs));
            ldsm_x4_trans(bfl[jb][0], bfl[jb][1], bfl[jb][2], bfl[jb][3],
                          smem_u32(vls + (k0 + b_r) * CXS + jb * 16 + b_cofs));
        }
#pragma unroll
        for (int jn = 0; jn < 8; jn++) {
            const int jb = jn >> 1, hf = (jn & 1) * 2;
            mma_f16(acc[jn], a0, a1, a2, a3, bfh[jb][hf], bfh[jb][hf + 1]);
            mma_f16(acc[jn], a0, a1, a2, a3, bfl[jb][hf], bfl[jb][hf + 1]);
        }
    }

    float* cdst = g_ctx + bh * 4096;
    const int d0 = m0 + (lane >> 2);
#pragma unroll
    for (int jn = 0; jn < 8; jn++) {
        const int e0 = jn * 8 + (lane & 3) * 2;
        atomicAdd(&cdst[d0 * 64 + e0], acc[jn][0]);
        atomicAdd(&cdst[d0 * 64 + e0 + 1], acc[jn][1]);
        atomicAdd(&cdst[(d0 + 8) * 64 + e0], acc[jn][2]);
        atomicAdd(&cdst[(d0 + 8) * 64 + e0 + 1], acc[jn][3]);
    }
}

// lin_out: out = softmax(q) @ (ctx * 0.125/csum[d]); softq and ctx as exact hi/lo
#define LO_CTS 72
#define LO_SQS 136
#define LO_OFF_CTH 0
#define LO_OFF_CTL (LO_OFF_CTH + 64 * LO_CTS * 2)    // 9216
#define LO_OFF_SQ  (LO_OFF_CTL + 64 * LO_CTS * 2)    // 18432
#define LO_OFF_CI  (LO_OFF_SQ + 64 * LO_SQS * 2)     // 35840
#define LO_SMEM    (LO_OFF_CI + 256)                 // 36096

__global__ __launch_bounds__(128) void lin_out_mma(float* __restrict__ attn_out)
{
    extern __shared__ char sml[];
    __half* cth = (__half*)(sml + LO_OFF_CTH);
    __half* ctl = (__half*)(sml + LO_OFF_CTL);
    __half* sq = (__half*)(sml + LO_OFF_SQ);
    float* cinv_s = (float*)(sml + LO_OFF_CI);

    const int bh = blockIdx.y;
    const int b = bh >> 2, hh4 = bh & 3, hh = 4 + hh4;
    const int t = threadIdx.x;
    const int warp = t >> 5, lane = t & 31;

    if (t < 64) cinv_s[t] = 0.125f / g_csum[bh * 64 + t];
    __syncthreads();

    // ctx -> scaled hi/lo fp16 tiles
    for (int idx = t; idx < 4096; idx += 128) {
        const int d = idx >> 6, e = idx & 63;
        float v = g_ctx[bh * 4096 + idx] * cinv_s[d];
        __half h = __float2half_rn(v);
        cth[d * LO_CTS + e] = h;
        ctl[d * LO_CTS + e] = __float2half_rn(v - __half2float(h));
    }

    // softq rows (fp32 softmax from Qf), hi/lo into sq[row][0..63 | 64..127]
    for (int r = warp; r < 64; r += 4) {
        const int n = blockIdx.x * 64 + r;
        const float* qrow = g_Qf + ((size_t)b * N_ + n) * 256 + hh4 * D_;
        float q0 = qrow[lane], q1 = qrow[lane + 32];
        float m = fmaxf(q0, q1);
#pragma unroll
        for (int o = 16; o; o >>= 1) m = fmaxf(m, __shfl_xor_sync(0xffffffffu, m, o));
        float e0 = __expf(q0 - m), e1 = __expf(q1 - m);
        float s = e0 + e1;
#pragma unroll
        for (int o = 16; o; o >>= 1) s += __shfl_xor_sync(0xffffffffu, s, o);
        float inv = 1.f / s;
        float p0 = e0 * inv, p1 = e1 * inv;
        __half h0 = __float2half_rn(p0), h1 = __float2half_rn(p1);
        sq[r * LO_SQS + lane] = h0;
        sq[r * LO_SQS + lane + 32] = h1;
        sq[r * LO_SQS + 64 + lane] = __float2half_rn(p0 - __half2float(h0));
        sq[r * LO_SQS + 64 + lane + 32] = __float2half_rn(p1 - __half2float(h1));
    }
    __syncthreads();

    // mma: warp tile m16 x n64, K'=128 (hi: k 0-63 from cth, lo: 64-127 from ctl)
    float o[8][4];
#pragma unroll
    for (int jn = 0; jn < 8; jn++)
#pragma unroll
        for (int e = 0; e < 4; e++) o[jn][e] = 0.f;

    const int a_row = warp * 16 + (lane & 15);
    const int a_cofs = (lane >> 4) << 3;
    const int b_r = (((lane >> 3) & 1) << 3) + (lane & 7);
    const int b_cofs = (lane >> 4) << 3;

#pragma unroll
    for (int kc = 0; kc < 8; kc++) {
        const int k16 = kc * 16;
        uint32_t a0, a1, a2, a3;
        ldsm_x4(a0, a1, a2, a3, smem_u32(sq + a_row * LO_SQS + k16 + a_cofs));
        const __half* Bt = (k16 < 64) ? cth : ctl;
        const int kd = k16 & 63;
        uint32_t bf[4][4];
#pragma unroll
        for (int jb = 0; jb < 4; jb++)
            ldsm_x4_trans(bf[jb][0], bf[jb][1], bf[jb][2], bf[jb][3],
                          smem_u32(Bt + (kd + b_r) * LO_CTS + jb * 16 + b_cofs));
#pragma unroll
        for (int jn = 0; jn < 8; jn++) {
            const int jb = jn >> 1, hf = (jn & 1) * 2;
            mma_f16(o[jn], a0, a1, a2, a3, bf[jb][hf], bf[jb][hf + 1]);
        }
    }

    // epilogue
#pragma unroll
    for (int jn = 0; jn < 8; jn++) {
        const int e0 = jn * 8 + (lane & 3) * 2;
#pragma unroll
        for (int half = 0; half < 2; half++) {
            const int row = warp * 16 + (lane >> 2) + half * 8;
            const int n = blockIdx.x * 64 + row;
            const float v0 = o[jn][half * 2], v1 = o[jn][half * 2 + 1];
            float* ad = attn_out + ((size_t)(b * H_ + hh) * N_ + n) * D_ + e0;
            ad[0] = v0; ad[1] = v1;
            *(__half2*)(g_attnH + ((size_t)b * N_ + n) * C_ + hh * D_ + e0) =
                __floats2half2_rn(v0, v1);
        }
    }
}

// ---------------------------------- launch ------------------------------------
extern "C" void kernel_launch(void* const* d_in, const int* in_sizes, int n_in,
                              void* d_out, int out_size)
{
    (void)in_sizes; (void)n_in; (void)out_size;
    const float* x     = (const float*)d_in[0];
    const float* Wq    = (const float*)d_in[1];
    const float* Wkv   = (const float*)d_in[2];
    const float* Wproj = (const float*)d_in[3];
    const float* bproj = (const float*)d_in[4];

    float* y    = (float*)d_out;
    float* attn = y + (size_t)ROWS * C_;

    float *pQf, *pKVf;
    __half *pxh, *paH, *pW16, *pWp16, *pQh, *pKVh;
    cudaGetSymbolAddress((void**)&pQf, g_Qf);
    cudaGetSymbolAddress((void**)&pKVf, g_KVf);
    cudaGetSymbolAddress((void**)&pQh, g_Qh);
    cudaGetSymbolAddress((void**)&pKVh, g_KVh);
    cudaGetSymbolAddress((void**)&pxh, g_xh);
    cudaGetSymbolAddress((void**)&paH, g_attnH);
    cudaGetSymbolAddress((void**)&pW16, g_W16);
    cudaGetSymbolAddress((void**)&pWp16, g_Wp16);

    cudaFuncSetAttribute(gemm_f16,
                         cudaFuncAttributeMaxDynamicSharedMemorySize, GEMM_SMEM);
    cudaFuncSetAttribute(local_attn_mma,
                         cudaFuncAttributeMaxDynamicSharedMemorySize, LA_SMEM);
    cudaFuncSetAttribute(ctx_mma_kernel,
                         cudaFuncAttributeMaxDynamicSharedMemorySize, CTX_SMEM);
    cudaFuncSetAttribute(lin_out_mma,
                         cudaFuncAttributeMaxDynamicSharedMemorySize, LO_SMEM);

    // conversions + ctx/csum zeroing
    prep_kernel<<<512, 256>>>(Wq, Wkv, Wproj);
    round_h_kernel<<<2048, 256>>>(x, pxh, ROWS);

    // fused Q+KV GEMM: n-tiles -> Qh | Qf | KVh | KVf
    gemm_f16<<<dim3(4, ROWS / 128), 512, GEMM_SMEM>>>(
        pxh, pW16, pQf, pKVf, pQh, pKVh, nullptr, 0);

    local_attn_mma<<<dim3(NW, 16), 256, LA_SMEM>>>(attn);

    ctx_mma_kernel<<<dim3(64, 16), 128, CTX_SMEM>>>();
    lin_out_mma<<<dim3(128, 16), 128, LO_SMEM>>>(attn);

    // proj GEMM: y = attnH @ Wp16^T + bias
    gemm_f16<<<dim3(2, ROWS / 128), 512, GEMM_SMEM>>>(
        paH, pWp16, y, nullptr, nullptr, nullptr, bproj, 1);
}

// round 15
// speedup vs baseline: 3.5712x; 1.0161x over previous
#include <cuda_runtime.h>
#include <cuda_bf16.h>
#include <cuda_fp16.h>
#include <math.h>
#include <stdint.h>

#define B_    4
#define N_    8192
#define C_    512
#define H_    8
#define D_    64
#define M_    64           // window
#define NW    (N_ / M_)    // 128
#define ROWS  (B_ * N_)    // 32768
#define NEG_INF_F (-1000000000.0f)

// ---------------- scratch (static device globals: allocation-free) ------------
__device__ __align__(16) __half g_xh[(size_t)ROWS * C_];     // fp16 x
__device__ __align__(16) __half g_attnH[(size_t)ROWS * C_];  // fp16 attn (B,N,C)
__device__ __align__(16) __half g_W16[1024 * C_];            // fp16 Wq | Wkv
__device__ __align__(16) __half g_Wp16[C_ * C_];             // fp16 Wproj
__device__ __align__(16) __half g_Qh[(size_t)ROWS * 256];    // fp16 q, local heads
__device__ __align__(16) __half g_KVh[(size_t)ROWS * 256];   // fp16 kv, local heads
__device__ float g_Qf[(size_t)ROWS * 256];                   // fp32 q, linear heads
__device__ float g_KVf[(size_t)ROWS * 256];                  // fp32 kv, linear heads
__device__ float g_ctx[16 * 64 * 64];
__device__ float g_csum[16 * 64];

// ---------------- helpers -----------------------------------------------------
__device__ __forceinline__ uint32_t smem_u32(const void* p) {
    uint32_t a;
    asm("{ .reg .u64 t; cvta.to.shared.u64 t, %1; cvt.u32.u64 %0, t; }"
        : "=r"(a) : "l"(p));
    return a;
}
#define CP_ASYNC16(dst, src) \
    asm volatile("cp.async.cg.shared.global [%0], [%1], 16;" \
                 :: "r"(dst), "l"(src))
#define CP_COMMIT() asm volatile("cp.async.commit_group;" ::: "memory")
#define CP_WAIT2()  asm volatile("cp.async.wait_group 2;" ::: "memory")

__device__ __forceinline__ void ldsm_x4(uint32_t& r0, uint32_t& r1,
                                        uint32_t& r2, uint32_t& r3, uint32_t addr) {
    asm volatile("ldmatrix.sync.aligned.m8n8.x4.shared.b16 {%0,%1,%2,%3}, [%4];"
                 : "=r"(r0), "=r"(r1), "=r"(r2), "=r"(r3) : "r"(addr));
}
__device__ __forceinline__ void ldsm_x4_trans(uint32_t& r0, uint32_t& r1,
                                              uint32_t& r2, uint32_t& r3,
                                              uint32_t addr) {
    asm volatile("ldmatrix.sync.aligned.m8n8.x4.trans.shared.b16 {%0,%1,%2,%3}, [%4];"
                 : "=r"(r0), "=r"(r1), "=r"(r2), "=r"(r3) : "r"(addr));
}
__device__ __forceinline__ void mma_f16(float* c, uint32_t a0, uint32_t a1,
                                        uint32_t a2, uint32_t a3,
                                        uint32_t b0, uint32_t b1) {
    asm volatile(
        "mma.sync.aligned.m16n8k16.row.col.f32.f16.f16.f32 "
        "{%0,%1,%2,%3}, {%4,%5,%6,%7}, {%8,%9}, {%0,%1,%2,%3};"
        : "+f"(c[0]), "+f"(c[1]), "+f"(c[2]), "+f"(c[3])
        : "r"(a0), "r"(a1), "r"(a2), "r"(a3), "r"(b0), "r"(b1));
}
__device__ __forceinline__ uint32_t pack_h2(float lo, float hi) {
    __half2 h = __floats2half2_rn(lo, hi);
    return *reinterpret_cast<uint32_t*>(&h);
}

// ---------------- conversions --------------------------------------------------
__global__ __launch_bounds__(256) void round_h_kernel(
    const float* __restrict__ src, __half* __restrict__ dst, int nrows)
{
    int total = nrows * (C_ / 4);
    for (int i = blockIdx.x * blockDim.x + threadIdx.x; i < total;
         i += gridDim.x * blockDim.x) {
        int r = i >> 7;
        int c = (i & 127) * 4;
        float4 v = *(const float4*)(src + (size_t)r * C_ + c);
        __half* base = dst + (size_t)r * C_ + c;
        *(__half2*)(base + 0) = __floats2half2_rn(v.x, v.y);
        *(__half2*)(base + 2) = __floats2half2_rn(v.z, v.w);
    }
}

// weights (3 matrices, 512x512 each = 65536 quads) + ctx/csum zeroing
__global__ __launch_bounds__(256) void prep_kernel(
    const float* __restrict__ Wq, const float* __restrict__ Wkv,
    const float* __restrict__ Wproj)
{
    const int wtotal = 3 * 65536;
    const int total = wtotal + 16 * 4096 + 16 * 64;
    for (int i = blockIdx.x * blockDim.x + threadIdx.x; i < total;
         i += gridDim.x * blockDim.x) {
        if (i < wtotal) {
            int mat = i >> 16, wi = i & 65535;
            int r = wi >> 7, c = (wi & 127) * 4;
            const float* src = (mat == 0) ? Wq : (mat == 1) ? Wkv : Wproj;
            __half* dst = (mat == 0) ? g_W16
                        : (mat == 1) ? (g_W16 + (size_t)512 * C_) : g_Wp16;
            float4 v = *(const float4*)(src + (size_t)r * C_ + c);
            __half* base = dst + (size_t)r * C_ + c;
            *(__half2*)(base + 0) = __floats2half2_rn(v.x, v.y);
            *(__half2*)(base + 2) = __floats2half2_rn(v.z, v.w);
        } else if (i < wtotal + 65536) {
            g_ctx[i - wtotal] = 0.f;
        } else {
            g_csum[i - wtotal - 65536] = 0.f;
        }
    }
}

// ---------------- fp16 mma GEMM, K=512, 128x256 tile --------------------------
#define GST     4
#define GA_ST   (128 * 40)
#define GB_ST   (256 * 40)
#define GB_BASE (GST * GA_ST)
#define GEMM_SMEM ((GB_BASE + GST * GB_ST) * 2)
#define KITS    (C_ / 32)             // 16

__global__ __launch_bounds__(512, 1) void gemm_f16(
    const __half* __restrict__ Ah, const __half* __restrict__ Bh,
    float* __restrict__ f0, float* __restrict__ f1,
    __half* __restrict__ h0p, __half* __restrict__ h1p,
    const float* __restrict__ bias, int mode)
{
    extern __shared__ __half smh[];
    const int tid = threadIdx.x;
    const int warp = tid >> 5, lane = tid & 31;
    const int wm = warp & 3, wn = warp >> 2;
    const int m0 = blockIdx.y * 128;
    const int n0 = blockIdx.x * 256;

    float acc[2][8][4];
#pragma unroll
    for (int i = 0; i < 2; i++)
#pragma unroll
        for (int j = 0; j < 8; j++)
#pragma unroll
            for (int e = 0; e < 4; e++) acc[i][j][e] = 0.f;

    const __half* Ab = Ah + (size_t)m0 * C_;
    const __half* Bb = Bh + (size_t)n0 * C_;

    const int lrow = tid >> 2;
    const int lchk = (tid & 3) * 8;

#define LOADQ(s, j) do { \
    const int ko = (j) * 32; \
    CP_ASYNC16(smem_u32(smh + (s) * GA_ST + lrow * 40 + lchk), \
               Ab + (size_t)lrow * C_ + ko + lchk); \
    CP_ASYNC16(smem_u32(smh + GB_BASE + (size_t)(s) * GB_ST + lrow * 40 + lchk), \
               Bb + (size_t)lrow * C_ + ko + lchk); \
    CP_ASYNC16(smem_u32(smh + GB_BASE + (size_t)(s) * GB_ST + (lrow + 128) * 40 + lchk), \
               Bb + (size_t)(lrow + 128) * C_ + ko + lchk); \
} while (0)

    LOADQ(0, 0); CP_COMMIT();
    LOADQ(1, 1); CP_COMMIT();
    LOADQ(2, 2); CP_COMMIT();

    const int a_row = wm * 32 + (lane & 15);
    const int a_col = (lane >> 4) << 3;
    const int b_row = wn * 64 + ((lane >> 4) << 3) + (lane & 7);
    const int b_col = ((lane >> 3) & 1) << 3;

    for (int j = 0; j < KITS; ++j) {
        const int s = j & 3;
        CP_WAIT2();
        __syncthreads();
        if (j + 3 < KITS) LOADQ((j + 3) & 3, j + 3);
        CP_COMMIT();

        const __half* As = smh + s * GA_ST;
        const __half* Bs = smh + GB_BASE + (size_t)s * GB_ST;
#pragma unroll
        for (int kk = 0; kk < 2; kk++) {
            const int k16 = kk * 16;
            uint32_t a[2][4];
#pragma unroll
            for (int i = 0; i < 2; i++)
                ldsm_x4(a[i][0], a[i][1], a[i][2], a[i][3],
                        smem_u32(As + (a_row + i * 16) * 40 + k16 + a_col));
            uint32_t b[4][4];
#pragma unroll
            for (int jb = 0; jb < 4; jb++)
                ldsm_x4(b[jb][0], b[jb][1], b[jb][2], b[jb][3],
                        smem_u32(Bs + (b_row + jb * 16) * 40 + k16 + b_col));
#pragma unroll
            for (int i = 0; i < 2; i++)
#pragma unroll
                for (int jn = 0; jn < 8; jn++) {
                    const int jb = jn >> 1, hf = (jn & 1) * 2;
                    mma_f16(acc[i][jn], a[i][0], a[i][1], a[i][2], a[i][3],
                            b[jb][hf], b[jb][hf + 1]);
                }
        }
    }

    if (mode == 0) {
        if ((blockIdx.x & 1) == 0) {
            __half* Hd = (blockIdx.x == 0) ? h0p : h1p;
#pragma unroll
            for (int i = 0; i < 2; i++) {
                const int r0 = m0 + wm * 32 + i * 16 + (lane >> 2);
#pragma unroll
                for (int jn = 0; jn < 8; jn++) {
                    const int c0 = wn * 64 + jn * 8 + (lane & 3) * 2;
                    *(__half2*)(Hd + (size_t)r0 * 256 + c0) =
                        __floats2half2_rn(acc[i][jn][0], acc[i][jn][1]);
                    *(__half2*)(Hd + (size_t)(r0 + 8) * 256 + c0) =
                        __floats2half2_rn(acc[i][jn][2], acc[i][jn][3]);
                }
            }
        } else {
            float* Fd = (blockIdx.x == 1) ? f0 : f1;
#pragma unroll
            for (int i = 0; i < 2; i++) {
                const int r0 = m0 + wm * 32 + i * 16 + (lane >> 2);
#pragma unroll
                for (int jn = 0; jn < 8; jn++) {
                    const int c0 = wn * 64 + jn * 8 + (lane & 3) * 2;
                    *(float2*)(Fd + (size_t)r0 * 256 + c0) =
                        make_float2(acc[i][jn][0], acc[i][jn][1]);
                    *(float2*)(Fd + (size_t)(r0 + 8) * 256 + c0) =
                        make_float2(acc[i][jn][2], acc[i][jn][3]);
                }
            }
        }
    } else {
#pragma unroll
        for (int i = 0; i < 2; i++) {
            const int r0 = m0 + wm * 32 + i * 16 + (lane >> 2);
#pragma unroll
            for (int jn = 0; jn < 8; jn++) {
                const int c0 = n0 + wn * 64 + jn * 8 + (lane & 3) * 2;
                float b0 = bias[c0], b1 = bias[c0 + 1];
                *(float2*)(f0 + (size_t)r0 * C_ + c0) =
                    make_float2(acc[i][jn][0] + b0, acc[i][jn][1] + b1);
                *(float2*)(f0 + (size_t)(r0 + 8) * C_ + c0) =
                    make_float2(acc[i][jn][2] + b0, acc[i][jn][3] + b1);
            }
        }
    }
}

// ---------------- local window attention via mma (heads 0..3) ------------------
#define QS2 72          // halfs: 64 + 8
#define KS2 72
#define OA2 36          // floats: 32 + 4
#define OFF_QS 0
#define OFF_KS (OFF_QS + 64 * QS2 * 2)        // 9216
#define OFF_OA (OFF_KS + 192 * KS2 * 2)       // 36864
#define OFF_RED (OFF_OA + 64 * OA2 * 4)       // 46080
#define OFF_SUM (OFF_RED + 512)               // 46592
#define LA_SMEM (OFF_SUM + 512)               // 47104

__global__ __launch_bounds__(256, 2) void local_attn_mma(float* __restrict__ attn_out)
{
    extern __shared__ char smla[];
    __half* qs = (__half*)(smla + OFF_QS);
    __half* ks = (__half*)(smla + OFF_KS);
    float* oacc = (float*)(smla + OFF_OA);
    float* redbuf = (float*)(smla + OFF_RED);
    float* sumbuf = (float*)(smla + OFF_SUM);

    const int w = blockIdx.x;
    const int bh = blockIdx.y;
    const int b = bh >> 2, hh = bh & 3;
    const int t = threadIdx.x;
    const int warp = t >> 5, lane = t & 31;
    const int wm = warp & 3, wn = warp >> 2;
    const size_t rowbase = (size_t)b * N_ + (size_t)w * M_;
    const int col0h = hh * D_;

    {
        const __half2 sc = __floats2half2_rn(0.125f, 0.125f);
        for (int idx = t; idx < 64 * 8; idx += 256) {
            int r = idx >> 3, c8 = (idx & 7) * 8;
            uint4 v = *(const uint4*)(g_Qh + (rowbase + r) * 256 + col0h + c8);
            __half2* hv = (__half2*)&v;
            hv[0] = __hmul2(hv[0], sc); hv[1] = __hmul2(hv[1], sc);
            hv[2] = __hmul2(hv[2], sc); hv[3] = __hmul2(hv[3], sc);
            *(uint4*)(qs + r * QS2 + c8) = v;
        }
    }
    const int nbase = (w - 1) * M_;
    for (int idx = t; idx < 192 * 8; idx += 256) {
        int j = idx >> 3, c8 = (idx & 7) * 8;
        int n = nbase + j;
        uint4 v = make_uint4(0, 0, 0, 0);
        if (n >= 0 && n < N_)
            v = *(const uint4*)(g_KVh + ((size_t)b * N_ + n) * 256 + col0h + c8);
        *(uint4*)(ks + j * KS2 + c8) = v;
    }
    __syncthreads();

    float c[12][4];
#pragma unroll
    for (int jn = 0; jn < 12; jn++)
#pragma unroll
        for (int e = 0; e < 4; e++) c[jn][e] = 0.f;

    const int a_rw = wm * 16 + (lane & 15);
    const int a_cl = (lane >> 4) << 3;
    const int b_rw = wn * 96 + ((lane >> 4) << 3) + (lane & 7);
    const int b_cl = ((lane >> 3) & 1) << 3;

#pragma unroll
    for (int k16 = 0; k16 < 64; k16 += 16) {
        uint32_t a0, a1, a2, a3;
        ldsm_x4(a0, a1, a2, a3, smem_u32(qs + a_rw * QS2 + k16 + a_cl));
        uint32_t bf[6][4];
#pragma unroll
        for (int jb = 0; jb < 6; jb++)
            ldsm_x4(bf[jb][0], bf[jb][1], bf[jb][2], bf[jb][3],
                    smem_u32(ks + (b_rw + jb * 16) * KS2 + k16 + b_cl));
#pragma unroll
        for (int jn = 0; jn < 12; jn++) {
            const int jb = jn >> 1, hf = (jn & 1) * 2;
            mma_f16(c[jn], a0, a1, a2, a3, bf[jb][hf], bf[jb][hf + 1]);
        }
    }

    const bool leftInv = (w == 0), rightInv = (w == NW - 1);
    if (leftInv || rightInv) {
#pragma unroll
        for (int jn = 0; jn < 12; jn++) {
            const int cb = wn * 96 + jn * 8 + (lane & 3) * 2;
#pragma unroll
            for (int e = 0; e < 4; e++) {
                const int jj = cb + (e & 1);
                if ((jj < 64 && leftInv) || (jj >= 128 && rightInv))
                    c[jn][e] = NEG_INF_F;
            }
        }
    }

    const int grA = wm * 16 + (lane >> 2);
    float mA = -1e30f, mB = -1e30f;
#pragma unroll
    for (int jn = 0; jn < 12; jn++) {
        mA = fmaxf(mA, fmaxf(c[jn][0], c[jn][1]));
        mB = fmaxf(mB, fmaxf(c[jn][2], c[jn][3]));
    }
    mA = fmaxf(mA, __shfl_xor_sync(0xffffffffu, mA, 1));
    mA = fmaxf(mA, __shfl_xor_sync(0xffffffffu, mA, 2));
    mB = fmaxf(mB, __shfl_xor_sync(0xffffffffu, mB, 1));
    mB = fmaxf(mB, __shfl_xor_sync(0xffffffffu, mB, 2));
    if ((lane & 3) == 0) {
        redbuf[wn * 64 + grA] = mA;
        redbuf[wn * 64 + grA + 8] = mB;
    }
    __syncthreads();
    mA = fmaxf(redbuf[grA], redbuf[64 + grA]);
    mB = fmaxf(redbuf[grA + 8], redbuf[64 + grA + 8]);

    float sA = 0.f, sB = 0.f;
#pragma unroll
    for (int jn = 0; jn < 12; jn++) {
        c[jn][0] = __expf(c[jn][0] - mA); sA += c[jn][0];
        c[jn][1] = __expf(c[jn][1] - mA); sA += c[jn][1];
        c[jn][2] = __expf(c[jn][2] - mB); sB += c[jn][2];
        c[jn][3] = __expf(c[jn][3] - mB); sB += c[jn][3];
    }
    sA += __shfl_xor_sync(0xffffffffu, sA, 1);
    sA += __shfl_xor_sync(0xffffffffu, sA, 2);
    sB += __shfl_xor_sync(0xffffffffu, sB, 1);
    sB += __shfl_xor_sync(0xffffffffu, sB, 2);
    if ((lane & 3) == 0) {
        sumbuf[wn * 64 + grA] = sA;
        sumbuf[wn * 64 + grA + 8] = sB;
    }
    __syncthreads();
    const float invA = 1.f / (sumbuf[grA] + sumbuf[64 + grA]);
    const float invB = 1.f / (sumbuf[grA + 8] + sumbuf[64 + grA + 8]);

    uint32_t ah[6][4], al[6][4];
#pragma unroll
    for (int kk = 0; kk < 6; kk++) {
        const int jn0 = 2 * kk, jn1 = 2 * kk + 1;
        float p00 = c[jn0][0] * invA, p01 = c[jn0][1] * invA;
        float p02 = c[jn0][2] * invB, p03 = c[jn0][3] * invB;
        float p10 = c[jn1][0] * invA, p11 = c[jn1][1] * invA;
        float p12 = c[jn1][2] * invB, p13 = c[jn1][3] * invB;
        ah[kk][0] = pack_h2(p00, p01);
        ah[kk][1] = pack_h2(p02, p03);
        ah[kk][2] = pack_h2(p10, p11);
        ah[kk][3] = pack_h2(p12, p13);
        __half2 h0 = *reinterpret_cast<__half2*>(&ah[kk][0]);
        __half2 h1 = *reinterpret_cast<__half2*>(&ah[kk][1]);
        __half2 h2 = *reinterpret_cast<__half2*>(&ah[kk][2]);
        __half2 h3 = *reinterpret_cast<__half2*>(&ah[kk][3]);
        al[kk][0] = pack_h2(p00 - __low2float(h0), p01 - __high2float(h0));
        al[kk][1] = pack_h2(p02 - __low2float(h1), p03 - __high2float(h1));
        al[kk][2] = pack_h2(p10 - __low2float(h2), p11 - __high2float(h2));
        al[kk][3] = pack_h2(p12 - __low2float(h3), p13 - __high2float(h3));
    }

    const int t_jofs = (((lane >> 3) & 1) << 3) + (lane & 7);
    const int t_eofs = (lane >> 4) << 3;
#pragma unroll
    for (int eh = 0; eh < 2; eh++) {
        float o[4][4];
#pragma unroll
        for (int jn = 0; jn < 4; jn++)
#pragma unroll
            for (int e = 0; e < 4; e++) o[jn][e] = 0.f;

#pragma unroll
        for (int kk = 0; kk < 6; kk++) {
            const int jcol = wn * 96 + kk * 16;
            uint32_t bf[2][4];
#pragma unroll
            for (int jb = 0; jb < 2; jb++)
                ldsm_x4_trans(bf[jb][0], bf[jb][1], bf[jb][2], bf[jb][3],
                              smem_u32(ks + (jcol + t_jofs) * KS2
                                       + eh * 32 + jb * 16 + t_eofs));
#pragma unroll
            for (int jn = 0; jn < 4; jn++) {
                const int jb = jn >> 1, hf = (jn & 1) * 2;
                mma_f16(o[jn], ah[kk][0], ah[kk][1], ah[kk][2], ah[kk][3],
                        bf[jb][hf], bf[jb][hf + 1]);
                mma_f16(o[jn], al[kk][0], al[kk][1], al[kk][2], al[kk][3],
                        bf[jb][hf], bf[jb][hf + 1]);
            }
        }

        if (wn == 0) {
#pragma unroll
            for (int jn = 0; jn < 4; jn++) {
                const int cb = jn * 8 + (lane & 3) * 2;
                oacc[grA * OA2 + cb] = o[jn][0];
                oacc[grA * OA2 + cb + 1] = o[jn][1];
                oacc[(grA + 8) * OA2 + cb] = o[jn][2];
                oacc[(grA + 8) * OA2 + cb + 1] = o[jn][3];
            }
        }
        __syncthreads();
        if (wn == 1) {
#pragma unroll
            for (int jn = 0; jn < 4; jn++) {
                const int cb = jn * 8 + (lane & 3) * 2;
#pragma unroll
                for (int half = 0; half < 2; half++) {
                    const int row = grA + half * 8;
                    const int n = w * M_ + row;
                    const int ecol = eh * 32 + cb;
                    const float v0 = o[jn][half * 2] + oacc[row * OA2 + cb];
                    const float v1 = o[jn][half * 2 + 1] + oacc[row * OA2 + cb + 1];
                    float* ad = attn_out +
                        ((size_t)(b * H_ + hh) * N_ + n) * D_ + ecol;
                    ad[0] = v0; ad[1] = v1;
                    *(__half2*)(g_attnH + ((size_t)b * N_ + n) * C_
                                + hh * D_ + ecol) = __floats2half2_rn(v0, v1);
                }
            }
        }
        __syncthreads();
    }
}

// ---------------- linear attention via mma (heads 4..7) ------------------------
#define CXS 72
#define CTX_SMEM (3 * 128 * CXS * 2)     // et | vhs | vls = 55296 B

__global__ __launch_bounds__(128) void ctx_mma_kernel()
{
    extern __shared__ __half smc[];
    __half* et = smc;
    __half* vhs = et + 128 * CXS;
    __half* vls = vhs + 128 * CXS;

    const int bh = blockIdx.y;
    const int b = bh >> 2, hh4 = bh & 3;
    const int n0 = blockIdx.x * 128;
    const int t = threadIdx.x;
    const int warp = t >> 5, lane = t & 31;

    const float* src = g_KVf + ((size_t)b * N_ + n0) * 256 + hh4 * D_;
    const int c4 = (t & 15) * 4;
    const int r0 = t >> 4;
    float cs0 = 0.f, cs1 = 0.f, cs2 = 0.f, cs3 = 0.f;
#pragma unroll
    for (int k = 0; k < 16; k++) {
        const int r = r0 + k * 8;
        float4 v = *(const float4*)(src + (size_t)r * 256 + c4);
        float e0 = __expf(v.x), e1 = __expf(v.y);
        float e2 = __expf(v.z), e3 = __expf(v.w);
        cs0 += e0; cs1 += e1; cs2 += e2; cs3 += e3;
        __half* ep = et + r * CXS + c4;
        *(__half2*)(ep + 0) = __floats2half2_rn(e0, e1);
        *(__half2*)(ep + 2) = __floats2half2_rn(e2, e3);
        __half h0 = __float2half_rn(v.x), h1 = __float2half_rn(v.y);
        __half h2 = __float2half_rn(v.z), h3 = __float2half_rn(v.w);
        __half2 hA; hA.x = h0; hA.y = h1;
        __half2 hB; hB.x = h2; hB.y = h3;
        __half* vp = vhs + r * CXS + c4;
        *(__half2*)(vp + 0) = hA;
        *(__half2*)(vp + 2) = hB;
        __half* lp = vls + r * CXS + c4;
        *(__half2*)(lp + 0) = __floats2half2_rn(v.x - __half2float(h0),
                                                v.y - __half2float(h1));
        *(__half2*)(lp + 2) = __floats2half2_rn(v.z - __half2float(h2),
                                                v.w - __half2float(h3));
    }
    atomicAdd(&g_csum[bh * 64 + c4 + 0], cs0);
    atomicAdd(&g_csum[bh * 64 + c4 + 1], cs1);
    atomicAdd(&g_csum[bh * 64 + c4 + 2], cs2);
    atomicAdd(&g_csum[bh * 64 + c4 + 3], cs3);
    __syncthreads();

    const int m0 = warp * 16;
    float acc[8][4];
#pragma unroll
    for (int jn = 0; jn < 8; jn++)
#pragma unroll
        for (int e = 0; e < 4; e++) acc[jn][e] = 0.f;

    const int a_r = ((lane >> 4) << 3) + (lane & 7);
    const int a_c = m0 + (((lane >> 3) & 1) << 3);
    const int b_r = (((lane >> 3) & 1) << 3) + (lane & 7);
    const int b_cofs = (lane >> 4) << 3;

#pragma unroll
    for (int kc = 0; kc < 8; kc++) {
        const int k0 = kc * 16;
        uint32_t a0, a1, a2, a3;
        ldsm_x4_trans(a0, a1, a2, a3, smem_u32(et + (k0 + a_r) * CXS + a_c));
        uint32_t bfh[4][4], bfl[4][4];
#pragma unroll
        for (int jb = 0; jb < 4; jb++) {
            ldsm_x4_trans(bfh[jb][0], bfh[jb][1], bfh[jb][2], bfh[jb][3],
                          smem_u32(vhs + (k0 + b_r) * CXS + jb * 16 + b_cofs));
            ldsm_x4_trans(bfl[jb][0], bfl[jb][1], bfl[jb][2], bfl[jb][3],
                          smem_u32(vls + (k0 + b_r) * CXS + jb * 16 + b_cofs));
        }
#pragma unroll
        for (int jn = 0; jn < 8; jn++) {
            const int jb = jn >> 1, hf = (jn & 1) * 2;
            mma_f16(acc[jn], a0, a1, a2, a3, bfh[jb][hf], bfh[jb][hf + 1]);
            mma_f16(acc[jn], a0, a1, a2, a3, bfl[jb][hf], bfl[jb][hf + 1]);
        }
    }

    float* cdst = g_ctx + bh * 4096;
    const int d0 = m0 + (lane >> 2);
#pragma unroll
    for (int jn = 0; jn < 8; jn++) {
        const int e0 = jn * 8 + (lane & 3) * 2;
        atomicAdd(&cdst[d0 * 64 + e0], acc[jn][0]);
        atomicAdd(&cdst[d0 * 64 + e0 + 1], acc[jn][1]);
        atomicAdd(&cdst[(d0 + 8) * 64 + e0], acc[jn][2]);
        atomicAdd(&cdst[(d0 + 8) * 64 + e0 + 1], acc[jn][3]);
    }
}

// lin_out: out = softmax(q) @ (ctx * 0.125/csum[d]); softq and ctx as exact hi/lo
#define LO_CTS 72
#define LO_SQS 136
#define LO_OFF_CTH 0
#define LO_OFF_CTL (LO_OFF_CTH + 64 * LO_CTS * 2)    // 9216
#define LO_OFF_SQ  (LO_OFF_CTL + 64 * LO_CTS * 2)    // 18432
#define LO_OFF_CI  (LO_OFF_SQ + 64 * LO_SQS * 2)     // 35840
#define LO_SMEM    (LO_OFF_CI + 256)                 // 36096

__global__ __launch_bounds__(128) void lin_out_mma(float* __restrict__ attn_out)
{
    extern __shared__ char sml[];
    __half* cth = (__half*)(sml + LO_OFF_CTH);
    __half* ctl = (__half*)(sml + LO_OFF_CTL);
    __half* sq = (__half*)(sml + LO_OFF_SQ);
    float* cinv_s = (float*)(sml + LO_OFF_CI);

    const int bh = blockIdx.y;
    const int b = bh >> 2, hh4 = bh & 3, hh = 4 + hh4;
    const int t = threadIdx.x;
    const int warp = t >> 5, lane = t & 31;

    if (t < 64) cinv_s[t] = 0.125f / g_csum[bh * 64 + t];
    __syncthreads();

    for (int idx = t; idx < 4096; idx += 128) {
        const int d = idx >> 6, e = idx & 63;
        float v = g_ctx[bh * 4096 + idx] * cinv_s[d];
        __half h = __float2half_rn(v);
        cth[d * LO_CTS + e] = h;
        ctl[d * LO_CTS + e] = __float2half_rn(v - __half2float(h));
    }

    for (int r = warp; r < 64; r += 4) {
        const int n = blockIdx.x * 64 + r;
        const float* qrow = g_Qf + ((size_t)b * N_ + n) * 256 + hh4 * D_;
        float q0 = qrow[lane], q1 = qrow[lane + 32];
        float m = fmaxf(q0, q1);
#pragma unroll
        for (int o = 16; o; o >>= 1) m = fmaxf(m, __shfl_xor_sync(0xffffffffu, m, o));
        float e0 = __expf(q0 - m), e1 = __expf(q1 - m);
        float s = e0 + e1;
#pragma unroll
        for (int o = 16; o; o >>= 1) s += __shfl_xor_sync(0xffffffffu, s, o);
        float inv = 1.f / s;
        float p0 = e0 * inv, p1 = e1 * inv;
        __half h0 = __float2half_rn(p0), h1 = __float2half_rn(p1);
        sq[r * LO_SQS + lane] = h0;
        sq[r * LO_SQS + lane + 32] = h1;
        sq[r * LO_SQS + 64 + lane] = __float2half_rn(p0 - __half2float(h0));
        sq[r * LO_SQS + 64 + lane + 32] = __float2half_rn(p1 - __half2float(h1));
    }
    __syncthreads();

    float o[8][4];
#pragma unroll
    for (int jn = 0; jn < 8; jn++)
#pragma unroll
        for (int e = 0; e < 4; e++) o[jn][e] = 0.f;

    const int a_row = warp * 16 + (lane & 15);
    const int a_cofs = (lane >> 4) << 3;
    const int b_r = (((lane >> 3) & 1) << 3) + (lane & 7);
    const int b_cofs = (lane >> 4) << 3;

#pragma unroll
    for (int kc = 0; kc < 8; kc++) {
        const int k16 = kc * 16;
        uint32_t a0, a1, a2, a3;
        ldsm_x4(a0, a1, a2, a3, smem_u32(sq + a_row * LO_SQS + k16 + a_cofs));
        const __half* Bt = (k16 < 64) ? cth : ctl;
        const int kd = k16 & 63;
        uint32_t bf[4][4];
#pragma unroll
        for (int jb = 0; jb < 4; jb++)
            ldsm_x4_trans(bf[jb][0], bf[jb][1], bf[jb][2], bf[jb][3],
                          smem_u32(Bt + (kd + b_r) * LO_CTS + jb * 16 + b_cofs));
#pragma unroll
        for (int jn = 0; jn < 8; jn++) {
            const int jb = jn >> 1, hf = (jn & 1) * 2;
            mma_f16(o[jn], a0, a1, a2, a3, bf[jb][hf], bf[jb][hf + 1]);
        }
    }

#pragma unroll
    for (int jn = 0; jn < 8; jn++) {
        const int e0 = jn * 8 + (lane & 3) * 2;
#pragma unroll
        for (int half = 0; half < 2; half++) {
            const int row = warp * 16 + (lane >> 2) + half * 8;
            const int n = blockIdx.x * 64 + row;
            const float v0 = o[jn][half * 2], v1 = o[jn][half * 2 + 1];
            float* ad = attn_out + ((size_t)(b * H_ + hh) * N_ + n) * D_ + e0;
            ad[0] = v0; ad[1] = v1;
            *(__half2*)(g_attnH + ((size_t)b * N_ + n) * C_ + hh * D_ + e0) =
                __floats2half2_rn(v0, v1);
        }
    }
}

// ---------------------------------- launch ------------------------------------
extern "C" void kernel_launch(void* const* d_in, const int* in_sizes, int n_in,
                              void* d_out, int out_size)
{
    (void)in_sizes; (void)n_in; (void)out_size;
    const float* x     = (const float*)d_in[0];
    const float* Wq    = (const float*)d_in[1];
    const float* Wkv   = (const float*)d_in[2];
    const float* Wproj = (const float*)d_in[3];
    const float* bproj = (const float*)d_in[4];

    float* y    = (float*)d_out;
    float* attn = y + (size_t)ROWS * C_;

    float *pQf, *pKVf;
    __half *pxh, *paH, *pW16, *pWp16, *pQh, *pKVh;
    cudaGetSymbolAddress((void**)&pQf, g_Qf);
    cudaGetSymbolAddress((void**)&pKVf, g_KVf);
    cudaGetSymbolAddress((void**)&pQh, g_Qh);
    cudaGetSymbolAddress((void**)&pKVh, g_KVh);
    cudaGetSymbolAddress((void**)&pxh, g_xh);
    cudaGetSymbolAddress((void**)&paH, g_attnH);
    cudaGetSymbolAddress((void**)&pW16, g_W16);
    cudaGetSymbolAddress((void**)&pWp16, g_Wp16);

    cudaFuncSetAttribute(gemm_f16,
                         cudaFuncAttributeMaxDynamicSharedMemorySize, GEMM_SMEM);
    cudaFuncSetAttribute(local_attn_mma,
                         cudaFuncAttributeMaxDynamicSharedMemorySize, LA_SMEM);
    cudaFuncSetAttribute(ctx_mma_kernel,
                         cudaFuncAttributeMaxDynamicSharedMemorySize, CTX_SMEM);
    cudaFuncSetAttribute(lin_out_mma,
                         cudaFuncAttributeMaxDynamicSharedMemorySize, LO_SMEM);

    // second stream + fork/join events (created once, outside graph capture)
    static cudaStream_t s2 = nullptr;
    static cudaEvent_t eFork0 = nullptr, eJoin0 = nullptr;
    static cudaEvent_t eFork1 = nullptr, eJoin1 = nullptr;
    if (!s2) {
        cudaStreamCreateWithFlags(&s2, cudaStreamNonBlocking);
        cudaEventCreateWithFlags(&eFork0, cudaEventDisableTiming);
        cudaEventCreateWithFlags(&eJoin0, cudaEventDisableTiming);
        cudaEventCreateWithFlags(&eFork1, cudaEventDisableTiming);
        cudaEventCreateWithFlags(&eJoin1, cudaEventDisableTiming);
    }

    // fork: x conversion on s2, weight prep + ctx zeroing on main
    cudaEventRecord(eFork0, 0);
    cudaStreamWaitEvent(s2, eFork0, 0);
    round_h_kernel<<<2048, 256, 0, s2>>>(x, pxh, ROWS);
    cudaEventRecord(eJoin0, s2);
    prep_kernel<<<512, 256>>>(Wq, Wkv, Wproj);
    cudaStreamWaitEvent(0, eJoin0, 0);

    // fused Q+KV GEMM: n-tiles -> Qh | Qf | KVh | KVf
    gemm_f16<<<dim3(4, ROWS / 128), 512, GEMM_SMEM>>>(
        pxh, pW16, pQf, pKVf, pQh, pKVh, nullptr, 0);

    // fork: local heads on main, linear heads on s2
    cudaEventRecord(eFork1, 0);
    cudaStreamWaitEvent(s2, eFork1, 0);
    ctx_mma_kernel<<<dim3(64, 16), 128, CTX_SMEM, s2>>>();
    lin_out_mma<<<dim3(128, 16), 128, LO_SMEM, s2>>>(attn);
    cudaEventRecord(eJoin1, s2);

    local_attn_mma<<<dim3(NW, 16), 256, LA_SMEM>>>(attn);
    cudaStreamWaitEvent(0, eJoin1, 0);

    // proj GEMM: y = attnH @ Wp16^T + bias
    gemm_f16<<<dim3(2, ROWS / 128), 512, GEMM_SMEM>>>(
        paH, pWp16, y, nullptr, nullptr, nullptr, bproj, 1);
}

// round 16
// speedup vs baseline: 3.6925x; 1.0340x over previous
#include <cuda_runtime.h>
#include <cuda_bf16.h>
#include <cuda_fp16.h>
#include <math.h>
#include <stdint.h>

#define B_    4
#define N_    8192
#define C_    512
#define H_    8
#define D_    64
#define M_    64           // window
#define NW    (N_ / M_)    // 128
#define ROWS  (B_ * N_)    // 32768
#define NEG_INF_F (-1000000000.0f)

// ---------------- scratch (static device globals: allocation-free) ------------
__device__ __align__(16) __half g_xh[(size_t)ROWS * C_];     // fp16 x
__device__ __align__(16) __half g_attnH[(size_t)ROWS * C_];  // fp16 attn (B,N,C)
__device__ __align__(16) __half g_W16[1024 * C_];            // fp16 Wq | Wkv
__device__ __align__(16) __half g_Wp16[C_ * C_];             // fp16 Wproj
__device__ __align__(16) __half g_Qh[(size_t)ROWS * 256];    // fp16 q, local heads
__device__ __align__(16) __half g_KVh[(size_t)ROWS * 256];   // fp16 kv, local heads
__device__ float g_Qf[(size_t)ROWS * 256];                   // fp32 q, linear heads
__device__ float g_KVf[(size_t)ROWS * 256];                  // fp32 kv, linear heads
__device__ float g_ctx[16 * 64 * 64];
__device__ float g_csum[16 * 64];

// ---------------- helpers -----------------------------------------------------
__device__ __forceinline__ uint32_t smem_u32(const void* p) {
    uint32_t a;
    asm("{ .reg .u64 t; cvta.to.shared.u64 t, %1; cvt.u32.u64 %0, t; }"
        : "=r"(a) : "l"(p));
    return a;
}
#define CP_ASYNC16(dst, src) \
    asm volatile("cp.async.cg.shared.global [%0], [%1], 16;" \
                 :: "r"(dst), "l"(src))
#define CP_COMMIT() asm volatile("cp.async.commit_group;" ::: "memory")
#define CP_WAIT2()  asm volatile("cp.async.wait_group 2;" ::: "memory")

__device__ __forceinline__ void ldsm_x4(uint32_t& r0, uint32_t& r1,
                                        uint32_t& r2, uint32_t& r3, uint32_t addr) {
    asm volatile("ldmatrix.sync.aligned.m8n8.x4.shared.b16 {%0,%1,%2,%3}, [%4];"
                 : "=r"(r0), "=r"(r1), "=r"(r2), "=r"(r3) : "r"(addr));
}
__device__ __forceinline__ void ldsm_x4_trans(uint32_t& r0, uint32_t& r1,
                                              uint32_t& r2, uint32_t& r3,
                                              uint32_t addr) {
    asm volatile("ldmatrix.sync.aligned.m8n8.x4.trans.shared.b16 {%0,%1,%2,%3}, [%4];"
                 : "=r"(r0), "=r"(r1), "=r"(r2), "=r"(r3) : "r"(addr));
}
__device__ __forceinline__ void mma_f16(float* c, uint32_t a0, uint32_t a1,
                                        uint32_t a2, uint32_t a3,
                                        uint32_t b0, uint32_t b1) {
    asm volatile(
        "mma.sync.aligned.m16n8k16.row.col.f32.f16.f16.f32 "
        "{%0,%1,%2,%3}, {%4,%5,%6,%7}, {%8,%9}, {%0,%1,%2,%3};"
        : "+f"(c[0]), "+f"(c[1]), "+f"(c[2]), "+f"(c[3])
        : "r"(a0), "r"(a1), "r"(a2), "r"(a3), "r"(b0), "r"(b1));
}
__device__ __forceinline__ uint32_t pack_h2(float lo, float hi) {
    __half2 h = __floats2half2_rn(lo, hi);
    return *reinterpret_cast<uint32_t*>(&h);
}

// ---------------- conversions --------------------------------------------------
__global__ __launch_bounds__(256) void round_h_kernel(
    const float* __restrict__ src, __half* __restrict__ dst, int nrows)
{
    int total = nrows * (C_ / 4);
    for (int i = blockIdx.x * blockDim.x + threadIdx.x; i < total;
         i += gridDim.x * blockDim.x) {
        int r = i >> 7;
        int c = (i & 127) * 4;
        float4 v = *(const float4*)(src + (size_t)r * C_ + c);
        __half* base = dst + (size_t)r * C_ + c;
        *(__half2*)(base + 0) = __floats2half2_rn(v.x, v.y);
        *(__half2*)(base + 2) = __floats2half2_rn(v.z, v.w);
    }
}

// weights (3 matrices, 512x512 each = 65536 quads) + ctx/csum zeroing
__global__ __launch_bounds__(256) void prep_kernel(
    const float* __restrict__ Wq, const float* __restrict__ Wkv,
    const float* __restrict__ Wproj)
{
    const int wtotal = 3 * 65536;
    const int total = wtotal + 16 * 4096 + 16 * 64;
    for (int i = blockIdx.x * blockDim.x + threadIdx.x; i < total;
         i += gridDim.x * blockDim.x) {
        if (i < wtotal) {
            int mat = i >> 16, wi = i & 65535;
            int r = wi >> 7, c = (wi & 127) * 4;
            const float* src = (mat == 0) ? Wq : (mat == 1) ? Wkv : Wproj;
            __half* dst = (mat == 0) ? g_W16
                        : (mat == 1) ? (g_W16 + (size_t)512 * C_) : g_Wp16;
            float4 v = *(const float4*)(src + (size_t)r * C_ + c);
            __half* base = dst + (size_t)r * C_ + c;
            *(__half2*)(base + 0) = __floats2half2_rn(v.x, v.y);
            *(__half2*)(base + 2) = __floats2half2_rn(v.z, v.w);
        } else if (i < wtotal + 65536) {
            g_ctx[i - wtotal] = 0.f;
        } else {
            g_csum[i - wtotal - 65536] = 0.f;
        }
    }
}

// ---------------- fp16 mma GEMM, K=512, 128x256 tile --------------------------
#define GST     4
#define GA_ST   (128 * 40)
#define GB_ST   (256 * 40)
#define GB_BASE (GST * GA_ST)
#define GEMM_SMEM ((GB_BASE + GST * GB_ST) * 2)
#define KITS    (C_ / 32)             // 16

__global__ __launch_bounds__(512, 1) void gemm_f16(
    const __half* __restrict__ Ah, const __half* __restrict__ Bh,
    float* __restrict__ f0, float* __restrict__ f1,
    __half* __restrict__ h0p, __half* __restrict__ h1p,
    const float* __restrict__ bias, int mode)
{
    extern __shared__ __half smh[];
    const int tid = threadIdx.x;
    const int warp = tid >> 5, lane = tid & 31;
    const int wm = warp & 3, wn = warp >> 2;
    const int m0 = blockIdx.y * 128;
    const int n0 = blockIdx.x * 256;

    float acc[2][8][4];
#pragma unroll
    for (int i = 0; i < 2; i++)
#pragma unroll
        for (int j = 0; j < 8; j++)
#pragma unroll
            for (int e = 0; e < 4; e++) acc[i][j][e] = 0.f;

    const __half* Ab = Ah + (size_t)m0 * C_;
    const __half* Bb = Bh + (size_t)n0 * C_;

    const int lrow = tid >> 2;
    const int lchk = (tid & 3) * 8;

#define LOADQ(s, j) do { \
    const int ko = (j) * 32; \
    CP_ASYNC16(smem_u32(smh + (s) * GA_ST + lrow * 40 + lchk), \
               Ab + (size_t)lrow * C_ + ko + lchk); \
    CP_ASYNC16(smem_u32(smh + GB_BASE + (size_t)(s) * GB_ST + lrow * 40 + lchk), \
               Bb + (size_t)lrow * C_ + ko + lchk); \
    CP_ASYNC16(smem_u32(smh + GB_BASE + (size_t)(s) * GB_ST + (lrow + 128) * 40 + lchk), \
               Bb + (size_t)(lrow + 128) * C_ + ko + lchk); \
} while (0)

    LOADQ(0, 0); CP_COMMIT();
    LOADQ(1, 1); CP_COMMIT();
    LOADQ(2, 2); CP_COMMIT();

    const int a_row = wm * 32 + (lane & 15);
    const int a_col = (lane >> 4) << 3;
    const int b_row = wn * 64 + ((lane >> 4) << 3) + (lane & 7);
    const int b_col = ((lane >> 3) & 1) << 3;

    for (int j = 0; j < KITS; ++j) {
        const int s = j & 3;
        CP_WAIT2();
        __syncthreads();
        if (j + 3 < KITS) LOADQ((j + 3) & 3, j + 3);
        CP_COMMIT();

        const __half* As = smh + s * GA_ST;
        const __half* Bs = smh + GB_BASE + (size_t)s * GB_ST;
#pragma unroll
        for (int kk = 0; kk < 2; kk++) {
            const int k16 = kk * 16;
            uint32_t a[2][4];
#pragma unroll
            for (int i = 0; i < 2; i++)
                ldsm_x4(a[i][0], a[i][1], a[i][2], a[i][3],
                        smem_u32(As + (a_row + i * 16) * 40 + k16 + a_col));
            uint32_t b[4][4];
#pragma unroll
            for (int jb = 0; jb < 4; jb++)
                ldsm_x4(b[jb][0], b[jb][1], b[jb][2], b[jb][3],
                        smem_u32(Bs + (b_row + jb * 16) * 40 + k16 + b_col));
#pragma unroll
            for (int i = 0; i < 2; i++)
#pragma unroll
                for (int jn = 0; jn < 8; jn++) {
                    const int jb = jn >> 1, hf = (jn & 1) * 2;
                    mma_f16(acc[i][jn], a[i][0], a[i][1], a[i][2], a[i][3],
                            b[jb][hf], b[jb][hf + 1]);
                }
        }
    }

    if (mode == 0) {
        if ((blockIdx.x & 1) == 0) {
            __half* Hd = (blockIdx.x == 0) ? h0p : h1p;
#pragma unroll
            for (int i = 0; i < 2; i++) {
                const int r0 = m0 + wm * 32 + i * 16 + (lane >> 2);
#pragma unroll
                for (int jn = 0; jn < 8; jn++) {
                    const int c0 = wn * 64 + jn * 8 + (lane & 3) * 2;
                    *(__half2*)(Hd + (size_t)r0 * 256 + c0) =
                        __floats2half2_rn(acc[i][jn][0], acc[i][jn][1]);
                    *(__half2*)(Hd + (size_t)(r0 + 8) * 256 + c0) =
                        __floats2half2_rn(acc[i][jn][2], acc[i][jn][3]);
                }
            }
        } else {
            float* Fd = (blockIdx.x == 1) ? f0 : f1;
#pragma unroll
            for (int i = 0; i < 2; i++) {
                const int r0 = m0 + wm * 32 + i * 16 + (lane >> 2);
#pragma unroll
                for (int jn = 0; jn < 8; jn++) {
                    const int c0 = wn * 64 + jn * 8 + (lane & 3) * 2;
                    *(float2*)(Fd + (size_t)r0 * 256 + c0) =
                        make_float2(acc[i][jn][0], acc[i][jn][1]);
                    *(float2*)(Fd + (size_t)(r0 + 8) * 256 + c0) =
                        make_float2(acc[i][jn][2], acc[i][jn][3]);
                }
            }
        }
    } else {
#pragma unroll
        for (int i = 0; i < 2; i++) {
            const int r0 = m0 + wm * 32 + i * 16 + (lane >> 2);
#pragma unroll
            for (int jn = 0; jn < 8; jn++) {
                const int c0 = n0 + wn * 64 + jn * 8 + (lane & 3) * 2;
                float b0 = bias[c0], b1 = bias[c0 + 1];
                *(float2*)(f0 + (size_t)r0 * C_ + c0) =
                    make_float2(acc[i][jn][0] + b0, acc[i][jn][1] + b1);
                *(float2*)(f0 + (size_t)(r0 + 8) * C_ + c0) =
                    make_float2(acc[i][jn][2] + b0, acc[i][jn][3] + b1);
            }
        }
    }
}

// ---------------- local window attention via mma (heads 0..3) ------------------
#define QS2 72          // halfs: 64 + 8
#define KS2 72
#define OA2 36          // floats: 32 + 4
#define OFF_QS 0
#define OFF_KS (OFF_QS + 64 * QS2 * 2)        // 9216
#define OFF_OA (OFF_KS + 192 * KS2 * 2)       // 36864
#define OFF_RED (OFF_OA + 64 * OA2 * 4)       // 46080
#define OFF_SUM (OFF_RED + 512)               // 46592
#define LA_SMEM (OFF_SUM + 512)               // 47104

__global__ __launch_bounds__(256, 2) void local_attn_mma(float* __restrict__ attn_out)
{
    extern __shared__ char smla[];
    __half* qs = (__half*)(smla + OFF_QS);
    __half* ks = (__half*)(smla + OFF_KS);
    float* oacc = (float*)(smla + OFF_OA);
    float* redbuf = (float*)(smla + OFF_RED);
    float* sumbuf = (float*)(smla + OFF_SUM);

    const int w = blockIdx.x;
    const int bh = blockIdx.y;
    const int b = bh >> 2, hh = bh & 3;
    const int t = threadIdx.x;
    const int warp = t >> 5, lane = t & 31;
    const int wm = warp & 3, wn = warp >> 2;
    const size_t rowbase = (size_t)b * N_ + (size_t)w * M_;
    const int col0h = hh * D_;

    {
        const __half2 sc = __floats2half2_rn(0.125f, 0.125f);
        for (int idx = t; idx < 64 * 8; idx += 256) {
            int r = idx >> 3, c8 = (idx & 7) * 8;
            uint4 v = *(const uint4*)(g_Qh + (rowbase + r) * 256 + col0h + c8);
            __half2* hv = (__half2*)&v;
            hv[0] = __hmul2(hv[0], sc); hv[1] = __hmul2(hv[1], sc);
            hv[2] = __hmul2(hv[2], sc); hv[3] = __hmul2(hv[3], sc);
            *(uint4*)(qs + r * QS2 + c8) = v;
        }
    }
    const int nbase = (w - 1) * M_;
    for (int idx = t; idx < 192 * 8; idx += 256) {
        int j = idx >> 3, c8 = (idx & 7) * 8;
        int n = nbase + j;
        uint4 v = make_uint4(0, 0, 0, 0);
        if (n >= 0 && n < N_)
            v = *(const uint4*)(g_KVh + ((size_t)b * N_ + n) * 256 + col0h + c8);
        *(uint4*)(ks + j * KS2 + c8) = v;
    }
    __syncthreads();

    float c[12][4];
#pragma unroll
    for (int jn = 0; jn < 12; jn++)
#pragma unroll
        for (int e = 0; e < 4; e++) c[jn][e] = 0.f;

    const int a_rw = wm * 16 + (lane & 15);
    const int a_cl = (lane >> 4) << 3;
    const int b_rw = wn * 96 + ((lane >> 4) << 3) + (lane & 7);
    const int b_cl = ((lane >> 3) & 1) << 3;

#pragma unroll
    for (int k16 = 0; k16 < 64; k16 += 16) {
        uint32_t a0, a1, a2, a3;
        ldsm_x4(a0, a1, a2, a3, smem_u32(qs + a_rw * QS2 + k16 + a_cl));
        uint32_t bf[6][4];
#pragma unroll
        for (int jb = 0; jb < 6; jb++)
            ldsm_x4(bf[jb][0], bf[jb][1], bf[jb][2], bf[jb][3],
                    smem_u32(ks + (b_rw + jb * 16) * KS2 + k16 + b_cl));
#pragma unroll
        for (int jn = 0; jn < 12; jn++) {
            const int jb = jn >> 1, hf = (jn & 1) * 2;
            mma_f16(c[jn], a0, a1, a2, a3, bf[jb][hf], bf[jb][hf + 1]);
        }
    }

    const bool leftInv = (w == 0), rightInv = (w == NW - 1);
    if (leftInv || rightInv) {
#pragma unroll
        for (int jn = 0; jn < 12; jn++) {
            const int cb = wn * 96 + jn * 8 + (lane & 3) * 2;
#pragma unroll
            for (int e = 0; e < 4; e++) {
                const int jj = cb + (e & 1);
                if ((jj < 64 && leftInv) || (jj >= 128 && rightInv))
                    c[jn][e] = NEG_INF_F;
            }
        }
    }

    const int grA = wm * 16 + (lane >> 2);
    float mA = -1e30f, mB = -1e30f;
#pragma unroll
    for (int jn = 0; jn < 12; jn++) {
        mA = fmaxf(mA, fmaxf(c[jn][0], c[jn][1]));
        mB = fmaxf(mB, fmaxf(c[jn][2], c[jn][3]));
    }
    mA = fmaxf(mA, __shfl_xor_sync(0xffffffffu, mA, 1));
    mA = fmaxf(mA, __shfl_xor_sync(0xffffffffu, mA, 2));
    mB = fmaxf(mB, __shfl_xor_sync(0xffffffffu, mB, 1));
    mB = fmaxf(mB, __shfl_xor_sync(0xffffffffu, mB, 2));
    if ((lane & 3) == 0) {
        redbuf[wn * 64 + grA] = mA;
        redbuf[wn * 64 + grA + 8] = mB;
    }
    __syncthreads();
    mA = fmaxf(redbuf[grA], redbuf[64 + grA]);
    mB = fmaxf(redbuf[grA + 8], redbuf[64 + grA + 8]);

    float sA = 0.f, sB = 0.f;
#pragma unroll
    for (int jn = 0; jn < 12; jn++) {
        c[jn][0] = __expf(c[jn][0] - mA); sA += c[jn][0];
        c[jn][1] = __expf(c[jn][1] - mA); sA += c[jn][1];
        c[jn][2] = __expf(c[jn][2] - mB); sB += c[jn][2];
        c[jn][3] = __expf(c[jn][3] - mB); sB += c[jn][3];
    }
    sA += __shfl_xor_sync(0xffffffffu, sA, 1);
    sA += __shfl_xor_sync(0xffffffffu, sA, 2);
    sB += __shfl_xor_sync(0xffffffffu, sB, 1);
    sB += __shfl_xor_sync(0xffffffffu, sB, 2);
    if ((lane & 3) == 0) {
        sumbuf[wn * 64 + grA] = sA;
        sumbuf[wn * 64 + grA + 8] = sB;
    }
    __syncthreads();
    const float invA = 1.f / (sumbuf[grA] + sumbuf[64 + grA]);
    const float invB = 1.f / (sumbuf[grA + 8] + sumbuf[64 + grA + 8]);

    uint32_t ah[6][4], al[6][4];
#pragma unroll
    for (int kk = 0; kk < 6; kk++) {
        const int jn0 = 2 * kk, jn1 = 2 * kk + 1;
        float p00 = c[jn0][0] * invA, p01 = c[jn0][1] * invA;
        float p02 = c[jn0][2] * invB, p03 = c[jn0][3] * invB;
        float p10 = c[jn1][0] * invA, p11 = c[jn1][1] * invA;
        float p12 = c[jn1][2] * invB, p13 = c[jn1][3] * invB;
        ah[kk][0] = pack_h2(p00, p01);
        ah[kk][1] = pack_h2(p02, p03);
        ah[kk][2] = pack_h2(p10, p11);
        ah[kk][3] = pack_h2(p12, p13);
        __half2 h0 = *reinterpret_cast<__half2*>(&ah[kk][0]);
        __half2 h1 = *reinterpret_cast<__half2*>(&ah[kk][1]);
        __half2 h2 = *reinterpret_cast<__half2*>(&ah[kk][2]);
        __half2 h3 = *reinterpret_cast<__half2*>(&ah[kk][3]);
        al[kk][0] = pack_h2(p00 - __low2float(h0), p01 - __high2float(h0));
        al[kk][1] = pack_h2(p02 - __low2float(h1), p03 - __high2float(h1));
        al[kk][2] = pack_h2(p10 - __low2float(h2), p11 - __high2float(h2));
        al[kk][3] = pack_h2(p12 - __low2float(h3), p13 - __high2float(h3));
    }

    const int t_jofs = (((lane >> 3) & 1) << 3) + (lane & 7);
    const int t_eofs = (lane >> 4) << 3;
#pragma unroll
    for (int eh = 0; eh < 2; eh++) {
        float o[4][4];
#pragma unroll
        for (int jn = 0; jn < 4; jn++)
#pragma unroll
            for (int e = 0; e < 4; e++) o[jn][e] = 0.f;

#pragma unroll
        for (int kk = 0; kk < 6; kk++) {
            const int jcol = wn * 96 + kk * 16;
            uint32_t bf[2][4];
#pragma unroll
            for (int jb = 0; jb < 2; jb++)
                ldsm_x4_trans(bf[jb][0], bf[jb][1], bf[jb][2], bf[jb][3],
                              smem_u32(ks + (jcol + t_jofs) * KS2
                                       + eh * 32 + jb * 16 + t_eofs));
#pragma unroll
            for (int jn = 0; jn < 4; jn++) {
                const int jb = jn >> 1, hf = (jn & 1) * 2;
                mma_f16(o[jn], ah[kk][0], ah[kk][1], ah[kk][2], ah[kk][3],
                        bf[jb][hf], bf[jb][hf + 1]);
                mma_f16(o[jn], al[kk][0], al[kk][1], al[kk][2], al[kk][3],
                        bf[jb][hf], bf[jb][hf + 1]);
            }
        }

        if (wn == 0) {
#pragma unroll
            for (int jn = 0; jn < 4; jn++) {
                const int cb = jn * 8 + (lane & 3) * 2;
                oacc[grA * OA2 + cb] = o[jn][0];
                oacc[grA * OA2 + cb + 1] = o[jn][1];
                oacc[(grA + 8) * OA2 + cb] = o[jn][2];
                oacc[(grA + 8) * OA2 + cb + 1] = o[jn][3];
            }
        }
        __syncthreads();
        if (wn == 1) {
#pragma unroll
            for (int jn = 0; jn < 4; jn++) {
                const int cb = jn * 8 + (lane & 3) * 2;
#pragma unroll
                for (int half = 0; half < 2; half++) {
                    const int row = grA + half * 8;
                    const int n = w * M_ + row;
                    const int ecol = eh * 32 + cb;
                    const float v0 = o[jn][half * 2] + oacc[row * OA2 + cb];
                    const float v1 = o[jn][half * 2 + 1] + oacc[row * OA2 + cb + 1];
                    float* ad = attn_out +
                        ((size_t)(b * H_ + hh) * N_ + n) * D_ + ecol;
                    ad[0] = v0; ad[1] = v1;
                    *(__half2*)(g_attnH + ((size_t)b * N_ + n) * C_
                                + hh * D_ + ecol) = __floats2half2_rn(v0, v1);
                }
            }
        }
        __syncthreads();
    }
}

// ---------------- linear attention via mma (heads 4..7) ------------------------
// ctx = E^T V: 256 n-rows/block, 256 threads, E fp16, V fp16 (single).
#define CXS 72
#define CTX_SMEM (2 * 256 * CXS * 2)     // et | vh = 73728 B

__global__ __launch_bounds__(256, 2) void ctx_mma_kernel()
{
    extern __shared__ __half smc[];
    __half* et = smc;                 // [256][CXS]
    __half* vh = et + 256 * CXS;

    const int bh = blockIdx.y;
    const int b = bh >> 2, hh4 = bh & 3;
    const int n0 = blockIdx.x * 256;
    const int t = threadIdx.x;
    const int warp = t >> 5, lane = t & 31;

    // load + exp; thread covers rows r0+16k, fixed 4 cols
    const float* src = g_KVf + ((size_t)b * N_ + n0) * 256 + hh4 * D_;
    const int c4 = (t & 15) * 4;
    const int r0 = t >> 4;
    float cs0 = 0.f, cs1 = 0.f, cs2 = 0.f, cs3 = 0.f;
#pragma unroll
    for (int k = 0; k < 16; k++) {
        const int r = r0 + k * 16;
        float4 v = *(const float4*)(src + (size_t)r * 256 + c4);
        float e0 = __expf(v.x), e1 = __expf(v.y);
        float e2 = __expf(v.z), e3 = __expf(v.w);
        cs0 += e0; cs1 += e1; cs2 += e2; cs3 += e3;
        __half* ep = et + r * CXS + c4;
        *(__half2*)(ep + 0) = __floats2half2_rn(e0, e1);
        *(__half2*)(ep + 2) = __floats2half2_rn(e2, e3);
        __half* vp = vh + r * CXS + c4;
        *(__half2*)(vp + 0) = __floats2half2_rn(v.x, v.y);
        *(__half2*)(vp + 2) = __floats2half2_rn(v.z, v.w);
    }
    atomicAdd(&g_csum[bh * 64 + c4 + 0], cs0);
    atomicAdd(&g_csum[bh * 64 + c4 + 1], cs1);
    atomicAdd(&g_csum[bh * 64 + c4 + 2], cs2);
    atomicAdd(&g_csum[bh * 64 + c4 + 3], cs3);
    __syncthreads();

    // warps 0-3: k-rows 0-127; warps 4-7: k-rows 128-255. m-tile (warp&3)*16.
    const int kbase = (warp >> 2) * 128;
    const int m0 = (warp & 3) * 16;
    float acc[8][4];
#pragma unroll
    for (int jn = 0; jn < 8; jn++)
#pragma unroll
        for (int e = 0; e < 4; e++) acc[jn][e] = 0.f;

    const int a_r = ((lane >> 4) << 3) + (lane & 7);
    const int a_c = m0 + (((lane >> 3) & 1) << 3);
    const int b_r = (((lane >> 3) & 1) << 3) + (lane & 7);
    const int b_cofs = (lane >> 4) << 3;

#pragma unroll
    for (int kc = 0; kc < 8; kc++) {
        const int k0 = kbase + kc * 16;
        uint32_t a0, a1, a2, a3;
        ldsm_x4_trans(a0, a1, a2, a3, smem_u32(et + (k0 + a_r) * CXS + a_c));
        uint32_t bf[4][4];
#pragma unroll
        for (int jb = 0; jb < 4; jb++)
            ldsm_x4_trans(bf[jb][0], bf[jb][1], bf[jb][2], bf[jb][3],
                          smem_u32(vh + (k0 + b_r) * CXS + jb * 16 + b_cofs));
#pragma unroll
        for (int jn = 0; jn < 8; jn++) {
            const int jb = jn >> 1, hf = (jn & 1) * 2;
            mma_f16(acc[jn], a0, a1, a2, a3, bf[jb][hf], bf[jb][hf + 1]);
        }
    }

    float* cdst = g_ctx + bh * 4096;
    const int d0 = m0 + (lane >> 2);
#pragma unroll
    for (int jn = 0; jn < 8; jn++) {
        const int e0 = jn * 8 + (lane & 3) * 2;
        atomicAdd(&cdst[d0 * 64 + e0], acc[jn][0]);
        atomicAdd(&cdst[d0 * 64 + e0 + 1], acc[jn][1]);
        atomicAdd(&cdst[(d0 + 8) * 64 + e0], acc[jn][2]);
        atomicAdd(&cdst[(d0 + 8) * 64 + e0 + 1], acc[jn][3]);
    }
}

// lin_out: out = softmax(q) @ (ctx * 0.125/csum[d]); softq and ctx as exact hi/lo
#define LO_CTS 72
#define LO_SQS 136
#define LO_OFF_CTH 0
#define LO_OFF_CTL (LO_OFF_CTH + 64 * LO_CTS * 2)    // 9216
#define LO_OFF_SQ  (LO_OFF_CTL + 64 * LO_CTS * 2)    // 18432
#define LO_OFF_CI  (LO_OFF_SQ + 64 * LO_SQS * 2)     // 35840
#define LO_SMEM    (LO_OFF_CI + 256)                 // 36096

__global__ __launch_bounds__(128) void lin_out_mma(float* __restrict__ attn_out)
{
    extern __shared__ char sml[];
    __half* cth = (__half*)(sml + LO_OFF_CTH);
    __half* ctl = (__half*)(sml + LO_OFF_CTL);
    __half* sq = (__half*)(sml + LO_OFF_SQ);
    float* cinv_s = (float*)(sml + LO_OFF_CI);

    const int bh = blockIdx.y;
    const int b = bh >> 2, hh4 = bh & 3, hh = 4 + hh4;
    const int t = threadIdx.x;
    const int warp = t >> 5, lane = t & 31;

    if (t < 64) cinv_s[t] = 0.125f / g_csum[bh * 64 + t];
    __syncthreads();

    for (int idx = t; idx < 4096; idx += 128) {
        const int d = idx >> 6, e = idx & 63;
        float v = g_ctx[bh * 4096 + idx] * cinv_s[d];
        __half h = __float2half_rn(v);
        cth[d * LO_CTS + e] = h;
        ctl[d * LO_CTS + e] = __float2half_rn(v - __half2float(h));
    }

    for (int r = warp; r < 64; r += 4) {
        const int n = blockIdx.x * 64 + r;
        const float* qrow = g_Qf + ((size_t)b * N_ + n) * 256 + hh4 * D_;
        float q0 = qrow[lane], q1 = qrow[lane + 32];
        float m = fmaxf(q0, q1);
#pragma unroll
        for (int o = 16; o; o >>= 1) m = fmaxf(m, __shfl_xor_sync(0xffffffffu, m, o));
        float e0 = __expf(q0 - m), e1 = __expf(q1 - m);
        float s = e0 + e1;
#pragma unroll
        for (int o = 16; o; o >>= 1) s += __shfl_xor_sync(0xffffffffu, s, o);
        float inv = 1.f / s;
        float p0 = e0 * inv, p1 = e1 * inv;
        __half h0 = __float2half_rn(p0), h1 = __float2half_rn(p1);
        sq[r * LO_SQS + lane] = h0;
        sq[r * LO_SQS + lane + 32] = h1;
        sq[r * LO_SQS + 64 + lane] = __float2half_rn(p0 - __half2float(h0));
        sq[r * LO_SQS + 64 + lane + 32] = __float2half_rn(p1 - __half2float(h1));
    }
    __syncthreads();

    float o[8][4];
#pragma unroll
    for (int jn = 0; jn < 8; jn++)
#pragma unroll
        for (int e = 0; e < 4; e++) o[jn][e] = 0.f;

    const int a_row = warp * 16 + (lane & 15);
    const int a_cofs = (lane >> 4) << 3;
    const int b_r = (((lane >> 3) & 1) << 3) + (lane & 7);
    const int b_cofs = (lane >> 4) << 3;

#pragma unroll
    for (int kc = 0; kc < 8; kc++) {
        const int k16 = kc * 16;
        uint32_t a0, a1, a2, a3;
        ldsm_x4(a0, a1, a2, a3, smem_u32(sq + a_row * LO_SQS + k16 + a_cofs));
        const __half* Bt = (k16 < 64) ? cth : ctl;
        const int kd = k16 & 63;
        uint32_t bf[4][4];
#pragma unroll
        for (int jb = 0; jb < 4; jb++)
            ldsm_x4_trans(bf[jb][0], bf[jb][1], bf[jb][2], bf[jb][3],
                          smem_u32(Bt + (kd + b_r) * LO_CTS + jb * 16 + b_cofs));
#pragma unroll
        for (int jn = 0; jn < 8; jn++) {
            const int jb = jn >> 1, hf = (jn & 1) * 2;
            mma_f16(o[jn], a0, a1, a2, a3, bf[jb][hf], bf[jb][hf + 1]);
        }
    }

#pragma unroll
    for (int jn = 0; jn < 8; jn++) {
        const int e0 = jn * 8 + (lane & 3) * 2;
#pragma unroll
        for (int half = 0; half < 2; half++) {
            const int row = warp * 16 + (lane >> 2) + half * 8;
            const int n = blockIdx.x * 64 + row;
            const float v0 = o[jn][half * 2], v1 = o[jn][half * 2 + 1];
            float* ad = attn_out + ((size_t)(b * H_ + hh) * N_ + n) * D_ + e0;
            ad[0] = v0; ad[1] = v1;
            *(__half2*)(g_attnH + ((size_t)b * N_ + n) * C_ + hh * D_ + e0) =
                __floats2half2_rn(v0, v1);
        }
    }
}

// ---------------------------------- launch ------------------------------------
extern "C" void kernel_launch(void* const* d_in, const int* in_sizes, int n_in,
                              void* d_out, int out_size)
{
    (void)in_sizes; (void)n_in; (void)out_size;
    const float* x     = (const float*)d_in[0];
    const float* Wq    = (const float*)d_in[1];
    const float* Wkv   = (const float*)d_in[2];
    const float* Wproj = (const float*)d_in[3];
    const float* bproj = (const float*)d_in[4];

    float* y    = (float*)d_out;
    float* attn = y + (size_t)ROWS * C_;

    float *pQf, *pKVf;
    __half *pxh, *paH, *pW16, *pWp16, *pQh, *pKVh;
    cudaGetSymbolAddress((void**)&pQf, g_Qf);
    cudaGetSymbolAddress((void**)&pKVf, g_KVf);
    cudaGetSymbolAddress((void**)&pQh, g_Qh);
    cudaGetSymbolAddress((void**)&pKVh, g_KVh);
    cudaGetSymbolAddress((void**)&pxh, g_xh);
    cudaGetSymbolAddress((void**)&paH, g_attnH);
    cudaGetSymbolAddress((void**)&pW16, g_W16);
    cudaGetSymbolAddress((void**)&pWp16, g_Wp16);

    cudaFuncSetAttribute(gemm_f16,
                         cudaFuncAttributeMaxDynamicSharedMemorySize, GEMM_SMEM);
    cudaFuncSetAttribute(local_attn_mma,
                         cudaFuncAttributeMaxDynamicSharedMemorySize, LA_SMEM);
    cudaFuncSetAttribute(ctx_mma_kernel,
                         cudaFuncAttributeMaxDynamicSharedMemorySize, CTX_SMEM);
    cudaFuncSetAttribute(lin_out_mma,
                         cudaFuncAttributeMaxDynamicSharedMemorySize, LO_SMEM);

    static cudaStream_t s2 = nullptr;
    static cudaEvent_t eFork0 = nullptr, eJoin0 = nullptr;
    static cudaEvent_t eFork1 = nullptr, eJoin1 = nullptr;
    if (!s2) {
        cudaStreamCreateWithFlags(&s2, cudaStreamNonBlocking);
        cudaEventCreateWithFlags(&eFork0, cudaEventDisableTiming);
        cudaEventCreateWithFlags(&eJoin0, cudaEventDisableTiming);
        cudaEventCreateWithFlags(&eFork1, cudaEventDisableTiming);
        cudaEventCreateWithFlags(&eJoin1, cudaEventDisableTiming);
    }

    // fork: x conversion on s2, weight prep + ctx zeroing on main
    cudaEventRecord(eFork0, 0);
    cudaStreamWaitEvent(s2, eFork0, 0);
    round_h_kernel<<<2048, 256, 0, s2>>>(x, pxh, ROWS);
    cudaEventRecord(eJoin0, s2);
    prep_kernel<<<512, 256>>>(Wq, Wkv, Wproj);
    cudaStreamWaitEvent(0, eJoin0, 0);

    // fused Q+KV GEMM: n-tiles -> Qh | Qf | KVh | KVf
    gemm_f16<<<dim3(4, ROWS / 128), 512, GEMM_SMEM>>>(
        pxh, pW16, pQf, pKVf, pQh, pKVh, nullptr, 0);

    // fork: local heads on main, linear heads on s2
    cudaEventRecord(eFork1, 0);
    cudaStreamWaitEvent(s2, eFork1, 0);
    ctx_mma_kernel<<<dim3(32, 16), 256, CTX_SMEM, s2>>>();
    lin_out_mma<<<dim3(128, 16), 128, LO_SMEM, s2>>>(attn);
    cudaEventRecord(eJoin1, s2);

    local_attn_mma<<<dim3(NW, 16), 256, LA_SMEM>>>(attn);
    cudaStreamWaitEvent(0, eJoin1, 0);

    // proj GEMM: y = attnH @ Wp16^T + bias
    gemm_f16<<<dim3(2, ROWS / 128), 512, GEMM_SMEM>>>(
        paH, pWp16, y, nullptr, nullptr, nullptr, bproj, 1);
}